// round 7
// baseline (speedup 1.0000x reference)
#include <cuda_runtime.h>
#include <cuda_bf16.h>
#include <cstdint>

#define S_   1024
#define H_   1024
#define B_   4
#define NH_  16
#define D_   64
#define BS_  4096
#define BH_  64

// ---------------- scratch (no allocs allowed) ----------------
__device__ float g_y[BS_ * H_];

__device__ __nv_bfloat16 g_xh[BS_ * H_], g_xl[BS_ * H_];
__device__ __nv_bfloat16 g_wqh[H_ * H_], g_wql[H_ * H_];
__device__ __nv_bfloat16 g_wkh[H_ * H_], g_wkl[H_ * H_];
__device__ __nv_bfloat16 g_wvh[H_ * H_], g_wvl[H_ * H_];
__device__ __nv_bfloat16 g_woh[H_ * H_], g_wol[H_ * H_];
__device__ __nv_bfloat16 g_qh[BS_ * H_], g_ql[BS_ * H_];
__device__ __nv_bfloat16 g_kh[BS_ * H_], g_kl[BS_ * H_];
__device__ __nv_bfloat16 g_vh[BS_ * H_], g_vl[BS_ * H_];
__device__ __nv_bfloat16 g_deh[2047 * 64], g_del[2047 * 64];
__device__ __nv_bfloat16 g_ch[BS_ * H_], g_cl[BS_ * H_];

// ---------------- helpers -------------------------------------------------------
__device__ __forceinline__ uint32_t smem_u32(const void* p)
{
    return (uint32_t)__cvta_generic_to_shared(p);
}
__device__ __forceinline__ void ldm4(uint32_t* r, uint32_t addr)
{
    asm volatile("ldmatrix.sync.aligned.m8n8.x4.shared.b16 {%0,%1,%2,%3}, [%4];"
                 : "=r"(r[0]), "=r"(r[1]), "=r"(r[2]), "=r"(r[3]) : "r"(addr));
}
__device__ __forceinline__ void ldm4t(uint32_t* r, uint32_t addr)
{
    asm volatile("ldmatrix.sync.aligned.m8n8.x4.trans.shared.b16 {%0,%1,%2,%3}, [%4];"
                 : "=r"(r[0]), "=r"(r[1]), "=r"(r[2]), "=r"(r[3]) : "r"(addr));
}
__device__ __forceinline__ void mma16816(float* c, const uint32_t* a, const uint32_t* b)
{
    asm volatile("mma.sync.aligned.m16n8k16.row.col.f32.bf16.bf16.f32 "
                 "{%0,%1,%2,%3}, {%4,%5,%6,%7}, {%8,%9}, {%0,%1,%2,%3};"
                 : "+f"(c[0]), "+f"(c[1]), "+f"(c[2]), "+f"(c[3])
                 : "r"(a[0]), "r"(a[1]), "r"(a[2]), "r"(a[3]), "r"(b[0]), "r"(b[1]));
}
__device__ __forceinline__ void cpa16(uint32_t dst, const void* src)
{
    asm volatile("cp.async.cg.shared.global [%0], [%1], 16;" :: "r"(dst), "l"(src));
}
#define CP_COMMIT() asm volatile("cp.async.commit_group;" ::: "memory")
#define CP_WAIT1()  asm volatile("cp.async.wait_group 1;" ::: "memory")
#define CP_WAIT0()  asm volatile("cp.async.wait_group 0;" ::: "memory")

__device__ __forceinline__ void store_split2(__nv_bfloat16* Hp, __nv_bfloat16* Lp,
                                             size_t off, float f0, float f1)
{
    __nv_bfloat162 hp, lp;
    hp.x = __float2bfloat16(f0); hp.y = __float2bfloat16(f1);
    lp.x = __float2bfloat16(f0 - __bfloat162float(hp.x));
    lp.y = __float2bfloat16(f1 - __bfloat162float(hp.y));
    *(__nv_bfloat162*)(Hp + off) = hp;
    *(__nv_bfloat162*)(Lp + off) = lp;
}

// ---------------- fp32 -> (hi,lo) bf16 split ---------------------------------------
__global__ void __launch_bounds__(256) split_kernel(const float* __restrict__ in,
                                                    __nv_bfloat16* __restrict__ hi,
                                                    __nv_bfloat16* __restrict__ lo,
                                                    int n4)
{
    int i = blockIdx.x * 256 + threadIdx.x;
    if (i >= n4) return;
    float4 a = ((const float4*)in)[i];
    __nv_bfloat16 h0 = __float2bfloat16(a.x);
    __nv_bfloat16 h1 = __float2bfloat16(a.y);
    __nv_bfloat16 h2 = __float2bfloat16(a.z);
    __nv_bfloat16 h3 = __float2bfloat16(a.w);
    __nv_bfloat162 hh0; hh0.x = h0; hh0.y = h1;
    __nv_bfloat162 hh1; hh1.x = h2; hh1.y = h3;
    ((__nv_bfloat162*)hi)[i * 2 + 0] = hh0;
    ((__nv_bfloat162*)hi)[i * 2 + 1] = hh1;
    __nv_bfloat162 ll0, ll1;
    ll0.x = __float2bfloat16(a.x - __bfloat162float(h0));
    ll0.y = __float2bfloat16(a.y - __bfloat162float(h1));
    ll1.x = __float2bfloat16(a.z - __bfloat162float(h2));
    ll1.y = __float2bfloat16(a.w - __bfloat162float(h3));
    ((__nv_bfloat162*)lo)[i * 2 + 0] = ll0;
    ((__nv_bfloat162*)lo)[i * 2 + 1] = ll1;
}

__global__ void __launch_bounds__(256) split4_kernel(
    const float* __restrict__ w0, const float* __restrict__ w1,
    const float* __restrict__ w2, const float* __restrict__ w3,
    __nv_bfloat16* __restrict__ h0, __nv_bfloat16* __restrict__ l0p,
    __nv_bfloat16* __restrict__ h1, __nv_bfloat16* __restrict__ l1p,
    __nv_bfloat16* __restrict__ h2, __nv_bfloat16* __restrict__ l2p,
    __nv_bfloat16* __restrict__ h3, __nv_bfloat16* __restrict__ l3p)
{
    const int z = blockIdx.y;
    const float* in = (z == 0) ? w0 : (z == 1) ? w1 : (z == 2) ? w2 : w3;
    __nv_bfloat16* hi = (z == 0) ? h0 : (z == 1) ? h1 : (z == 2) ? h2 : h3;
    __nv_bfloat16* lo = (z == 0) ? l0p : (z == 1) ? l1p : (z == 2) ? l2p : l3p;
    int i = blockIdx.x * 256 + threadIdx.x;
    float4 a = ((const float4*)in)[i];
    __nv_bfloat16 a0 = __float2bfloat16(a.x);
    __nv_bfloat16 a1 = __float2bfloat16(a.y);
    __nv_bfloat16 a2 = __float2bfloat16(a.z);
    __nv_bfloat16 a3 = __float2bfloat16(a.w);
    __nv_bfloat162 hh0; hh0.x = a0; hh0.y = a1;
    __nv_bfloat162 hh1; hh1.x = a2; hh1.y = a3;
    ((__nv_bfloat162*)hi)[i * 2 + 0] = hh0;
    ((__nv_bfloat162*)hi)[i * 2 + 1] = hh1;
    __nv_bfloat162 ll0, ll1;
    ll0.x = __float2bfloat16(a.x - __bfloat162float(a0));
    ll0.y = __float2bfloat16(a.y - __bfloat162float(a1));
    ll1.x = __float2bfloat16(a.z - __bfloat162float(a2));
    ll1.y = __float2bfloat16(a.w - __bfloat162float(a3));
    ((__nv_bfloat162*)lo)[i * 2 + 0] = ll0;
    ((__nv_bfloat162*)lo)[i * 2 + 1] = ll1;
}

// ---------------- split-bf16 GEMM NT via HMMA, 2-stage cp.async, 2 CTAs/SM ---------
// EPI: 1 = fp32+bias+resid, 2 = split bf16 hi/lo +bias
#define KT    32
#define LDS_  40
#define MAT_B (128 * LDS_ * 2)
#define STG_B (4 * MAT_B)
#define NSTG  2
#define GSM_TOTAL (NSTG * STG_B)   // 81920 B -> 2 CTAs/SM

template <int EPI>
__global__ void __launch_bounds__(256, 2) gemm_mma2(
    const __nv_bfloat16* __restrict__ Ah, const __nv_bfloat16* __restrict__ Al,
    const __nv_bfloat16* __restrict__ Bh0, const __nv_bfloat16* __restrict__ Bl0,
    const __nv_bfloat16* __restrict__ Bh1, const __nv_bfloat16* __restrict__ Bl1,
    const __nv_bfloat16* __restrict__ Bh2, const __nv_bfloat16* __restrict__ Bl2,
    const float* __restrict__ bias0, const float* __restrict__ bias1,
    const float* __restrict__ bias2,
    void* O0, void* O1, void* O2,
    void* L0, void* L1, void* L2,
    const float* __restrict__ resid)
{
    extern __shared__ char smem[];
    const uint32_t sb = smem_u32(smem);

    const int z = blockIdx.z;
    const __nv_bfloat16* Bh = (z == 0) ? Bh0 : (z == 1) ? Bh1 : Bh2;
    const __nv_bfloat16* Bl = (z == 0) ? Bl0 : (z == 1) ? Bl1 : Bl2;
    const float* bias = (z == 0) ? bias0 : (z == 1) ? bias1 : bias2;
    void* Ov = (z == 0) ? O0 : (z == 1) ? O1 : O2;
    void* Lv = (z == 0) ? L0 : (z == 1) ? L1 : L2;

    const int tid = threadIdx.x;
    const int lane = tid & 31, wid = tid >> 5;
    const int wm = wid >> 2, wn = wid & 3;
    const int bM = blockIdx.y * 128, bN = blockIdx.x * 128;

    float acc[4][4][4] = {};

    const int v0row = tid >> 2, v0c = (tid & 3);
    const int v1row = (tid + 256) >> 2, v1c = ((tid + 256) & 3);
    const int NK = H_ / KT;

    const int q8 = lane >> 3, r8 = lane & 7;
    const int arowL = wm * 64 + (q8 & 1) * 8 + r8;
    const int browL = wn * 32 + (q8 >> 1) * 8 + r8;
    const int acolL = (q8 >> 1) * 8;
    const int bcolL = (q8 & 1) * 8;

    auto issue = [&](int kt) {
        const int st = kt % NSTG;
        const uint32_t base = sb + st * STG_B;
        const int k0 = kt * KT;
        const uint32_t d0 = (uint32_t)(v0row * (LDS_ * 2) + v0c * 16);
        const uint32_t d1 = (uint32_t)(v1row * (LDS_ * 2) + v1c * 16);
        const size_t gA0 = (size_t)(bM + v0row) * H_ + k0 + v0c * 8;
        const size_t gA1 = (size_t)(bM + v1row) * H_ + k0 + v1c * 8;
        const size_t gB0 = (size_t)(bN + v0row) * H_ + k0 + v0c * 8;
        const size_t gB1 = (size_t)(bN + v1row) * H_ + k0 + v1c * 8;
        cpa16(base + 0 * MAT_B + d0, Ah + gA0);
        cpa16(base + 0 * MAT_B + d1, Ah + gA1);
        cpa16(base + 1 * MAT_B + d0, Al + gA0);
        cpa16(base + 1 * MAT_B + d1, Al + gA1);
        cpa16(base + 2 * MAT_B + d0, Bh + gB0);
        cpa16(base + 2 * MAT_B + d1, Bh + gB1);
        cpa16(base + 3 * MAT_B + d0, Bl + gB0);
        cpa16(base + 3 * MAT_B + d1, Bl + gB1);
    };

    issue(0); CP_COMMIT();
    issue(1); CP_COMMIT();

    for (int kt = 0; kt < NK; kt++) {
        if (kt + 1 < NK) { CP_WAIT1(); } else { CP_WAIT0(); }
        __syncthreads();

        const int st = kt % NSTG;
        const uint32_t bAh = sb + st * STG_B + 0 * MAT_B;
        const uint32_t bAl = sb + st * STG_B + 1 * MAT_B;
        const uint32_t bBh = sb + st * STG_B + 2 * MAT_B;
        const uint32_t bBl = sb + st * STG_B + 3 * MAT_B;

#pragma unroll
        for (int ks = 0; ks < KT; ks += 16) {
            uint32_t afh[4][4], afl[4][4];
#pragma unroll
            for (int mt = 0; mt < 4; mt++) {
                const uint32_t ro = (uint32_t)(((arowL + mt * 16) * LDS_ + acolL + ks) * 2);
                ldm4(afh[mt], bAh + ro);
                ldm4(afl[mt], bAl + ro);
            }
            uint32_t bfh[2][4], bfl[2][4];
#pragma unroll
            for (int p = 0; p < 2; p++) {
                const uint32_t ro = (uint32_t)(((browL + p * 16) * LDS_ + bcolL + ks) * 2);
                ldm4(bfh[p], bBh + ro);
                ldm4(bfl[p], bBl + ro);
            }
#pragma unroll
            for (int mt = 0; mt < 4; mt++)
#pragma unroll
                for (int nt = 0; nt < 4; nt++) {
                    const uint32_t* bhp = &bfh[nt >> 1][(nt & 1) * 2];
                    const uint32_t* blp = &bfl[nt >> 1][(nt & 1) * 2];
                    mma16816(acc[mt][nt], afh[mt], bhp);
                    mma16816(acc[mt][nt], afh[mt], blp);
                    mma16816(acc[mt][nt], afl[mt], bhp);
                }
        }
        __syncthreads();
        if (kt + 2 < NK) { issue(kt + 2); CP_COMMIT(); }
    }

    const int crow0 = bM + wm * 64 + (lane >> 2);
    const int ccol0 = bN + wn * 32 + (lane & 3) * 2;
#pragma unroll
    for (int mt = 0; mt < 4; mt++) {
        const int r0 = crow0 + mt * 16;
#pragma unroll
        for (int nt = 0; nt < 4; nt++) {
            const int c0 = ccol0 + nt * 8;
            float f0 = acc[mt][nt][0] + bias[c0];
            float f1 = acc[mt][nt][1] + bias[c0 + 1];
            float f2 = acc[mt][nt][2] + bias[c0];
            float f3 = acc[mt][nt][3] + bias[c0 + 1];
            if (EPI == 1) {
                f0 += resid[(size_t)r0 * H_ + c0];
                f1 += resid[(size_t)r0 * H_ + c0 + 1];
                f2 += resid[(size_t)(r0 + 8) * H_ + c0];
                f3 += resid[(size_t)(r0 + 8) * H_ + c0 + 1];
            }
            if (EPI == 2) {
                __nv_bfloat16* OH = (__nv_bfloat16*)Ov;
                __nv_bfloat16* OL = (__nv_bfloat16*)Lv;
                store_split2(OH, OL, (size_t)r0 * H_ + c0, f0, f1);
                store_split2(OH, OL, (size_t)(r0 + 8) * H_ + c0, f2, f3);
            } else {
                float* O = (float*)Ov;
                O[(size_t)r0 * H_ + c0]           = f0;
                O[(size_t)r0 * H_ + c0 + 1]       = f1;
                O[(size_t)(r0 + 8) * H_ + c0]     = f2;
                O[(size_t)(r0 + 8) * H_ + c0 + 1] = f3;
            }
        }
    }
}

// ---------------- fused flash attention with relative_key_query bias ---------------
// P (dist_emb) now single bf16 buffer; S2/S3 single-pass.
#define FQ    0
#define FK    18432
#define FV    36864       // 2 bufs x (h 9216 + l 9216)
#define FP    73728       // hi only, 128 rows x 72 pitch = 18432
#define FS2   92160       // fp32 [64][132]; probs hi/lo overlap here (2x9216)
#define FS3   125952
#define FRED  159744      // redm [2][64] f32, redsum [2][64] f32
#define FMASK 160768      // 1024 f32
#define FSM_TOTAL 164864

__global__ void __launch_bounds__(256) fused_attn(
    const __nv_bfloat16* __restrict__ qh, const __nv_bfloat16* __restrict__ ql,
    const __nv_bfloat16* __restrict__ kh, const __nv_bfloat16* __restrict__ kl,
    const __nv_bfloat16* __restrict__ vh, const __nv_bfloat16* __restrict__ vl,
    const __nv_bfloat16* __restrict__ deh,
    const float* __restrict__ mask,
    __nv_bfloat16* __restrict__ ch, __nv_bfloat16* __restrict__ cl)
{
    extern __shared__ char smem[];
    const uint32_t sb = smem_u32(smem);
    const int tid = threadIdx.x, lane = tid & 31, wid = tid >> 5;
    const int wr = wid >> 1, wc = wid & 1;
    const int l0 = blockIdx.x * 64;
    const int bh = blockIdx.y;
    const int b = bh >> 4, h = bh & 15;
    const int hcol = h * D_;

    const int q8 = lane >> 3, r8 = lane & 7;
    const int aRow = (q8 & 1) * 8 + r8, aCol = (q8 >> 1) * 8;
    const int bRow = (q8 >> 1) * 8 + r8, bCol = (q8 & 1) * 8;

    auto cp_t64 = [&](uint32_t dstbase, const __nv_bfloat16* srcH,
                      const __nv_bfloat16* srcL, int growbase) {
#pragma unroll
        for (int j = 0; j < 2; j++) {
            int v = tid + 256 * j;
            int row = v >> 3, c = v & 7;
            uint32_t d = dstbase + (uint32_t)(row * 72 + c * 8) * 2;
            cpa16(d, srcH + (size_t)(growbase + row) * H_ + hcol + c * 8);
            cpa16(d + 9216, srcL + (size_t)(growbase + row) * H_ + hcol + c * 8);
        }
    };
    auto cp_P = [&](int it) {
        const int prow0 = l0 - it * 64 + 960;
#pragma unroll
        for (int j = 0; j < 4; j++) {
            int v = tid + 256 * j;
            int row = v >> 3, c = v & 7;
            uint32_t off = (uint32_t)(row * 72 + c * 8) * 2;
            if (row < 127) {
                cpa16(sb + FP + off, deh + (size_t)(prow0 + row) * 64 + c * 8);
            } else {
                uint4 zz = {0, 0, 0, 0};
                *(uint4*)(smem + FP + off) = zz;
            }
        }
    };

    // ---- initial loads ----
    cp_t64(sb + FQ, qh, ql, b * S_ + l0);
    cp_t64(sb + FK, kh, kl, b * S_ + 0);
    cp_t64(sb + FV, vh, vl, b * S_ + 0);
    cp_P(0);
    cpa16(sb + FMASK + tid * 16, mask + (size_t)b * S_ + tid * 4);
    CP_COMMIT();

    float O[4][4] = {};
    float mrunA = -1e30f, mrunB = -1e30f;
    float srunA = 0.f, srunB = 0.f;

    const int la = wr * 16 + (lane >> 2);
    float* S2p = (float*)(smem + FS2);
    float* S3p = (float*)(smem + FS3);
    float* redm = (float*)(smem + FRED);
    float* redsum = (float*)(smem + FRED + 512);
    const float* maskS = (const float*)(smem + FMASK);

    CP_WAIT0();
    __syncthreads();

    for (int it = 0; it < 16; it++) {
        if (it > 0) { CP_WAIT0(); __syncthreads(); }
        const uint32_t Vb = sb + FV + (uint32_t)(it & 1) * 18432;

        // ---- S1 = Q @ K^T (3-pass) ----
        float accS[4][4] = {};
#pragma unroll
        for (int ks = 0; ks < 4; ks++) {
            uint32_t ah_[4], al_[4];
            ldm4(ah_, sb + FQ + (uint32_t)(((wr * 16 + aRow) * 72) + ks * 16 + aCol) * 2);
            ldm4(al_, sb + FQ + 9216 + (uint32_t)(((wr * 16 + aRow) * 72) + ks * 16 + aCol) * 2);
            uint32_t kbh[2][4], kbl[2][4];
#pragma unroll
            for (int p = 0; p < 2; p++) {
                uint32_t ro = (uint32_t)(((wc * 32 + p * 16 + bRow) * 72) + ks * 16 + bCol) * 2;
                ldm4(kbh[p], sb + FK + ro);
                ldm4(kbl[p], sb + FK + 9216 + ro);
            }
#pragma unroll
            for (int nf = 0; nf < 4; nf++) {
                const uint32_t* bhp = &kbh[nf >> 1][(nf & 1) * 2];
                const uint32_t* blp = &kbl[nf >> 1][(nf & 1) * 2];
                mma16816(accS[nf], ah_, bhp);
                mma16816(accS[nf], ah_, blp);
                mma16816(accS[nf], al_, bhp);
            }
        }

        // ---- S2 = Qh @ Ph^T (single pass) -> stage ----
        {
            float a2[4][2][4] = {};
#pragma unroll
            for (int ks = 0; ks < 4; ks++) {
                uint32_t pb[4];
                uint32_t ro = (uint32_t)(((wid * 16 + bRow) * 72) + ks * 16 + bCol) * 2;
                ldm4(pb, sb + FP + ro);
#pragma unroll
                for (int mt = 0; mt < 4; mt++) {
                    uint32_t ah_[4];
                    uint32_t ra = (uint32_t)(((mt * 16 + aRow) * 72) + ks * 16 + aCol) * 2;
                    ldm4(ah_, sb + FQ + ra);
#pragma unroll
                    for (int nf = 0; nf < 2; nf++)
                        mma16816(a2[mt][nf], ah_, &pb[nf * 2]);
                }
            }
#pragma unroll
            for (int mt = 0; mt < 4; mt++) {
                const int rr = mt * 16 + (lane >> 2);
#pragma unroll
                for (int nf = 0; nf < 2; nf++) {
                    const int cc = wid * 16 + nf * 8 + (lane & 3) * 2;
                    float2 u0; u0.x = a2[mt][nf][0]; u0.y = a2[mt][nf][1];
                    float2 u1; u1.x = a2[mt][nf][2]; u1.y = a2[mt][nf][3];
                    *(float2*)&S2p[rr * 132 + cc] = u0;
                    *(float2*)&S2p[(rr + 8) * 132 + cc] = u1;
                }
            }
        }
        // ---- S3 = Kh @ Ph^T (single pass) -> stage ----
        {
            float a3[4][2][4] = {};
#pragma unroll
            for (int ks = 0; ks < 4; ks++) {
                uint32_t pb[4];
                uint32_t ro = (uint32_t)(((wid * 16 + bRow) * 72) + ks * 16 + bCol) * 2;
                ldm4(pb, sb + FP + ro);
#pragma unroll
                for (int mt = 0; mt < 4; mt++) {
                    uint32_t ah_[4];
                    uint32_t ra = (uint32_t)(((mt * 16 + aRow) * 72) + ks * 16 + aCol) * 2;
                    ldm4(ah_, sb + FK + ra);
#pragma unroll
                    for (int nf = 0; nf < 2; nf++)
                        mma16816(a3[mt][nf], ah_, &pb[nf * 2]);
                }
            }
#pragma unroll
            for (int mt = 0; mt < 4; mt++) {
                const int rr = mt * 16 + (lane >> 2);
#pragma unroll
                for (int nf = 0; nf < 2; nf++) {
                    const int cc = wid * 16 + nf * 8 + (lane & 3) * 2;
                    float2 u0; u0.x = a3[mt][nf][0]; u0.y = a3[mt][nf][1];
                    float2 u1; u1.x = a3[mt][nf][2]; u1.y = a3[mt][nf][3];
                    *(float2*)&S3p[rr * 132 + cc] = u0;
                    *(float2*)&S3p[(rr + 8) * 132 + cc] = u1;
                }
            }
        }
        __syncthreads();   // staging visible; K,P reads done

        // prefetch next K,P,V
        if (it < 15) {
            cp_t64(sb + FK, kh, kl, b * S_ + (it + 1) * 64);
            cp_P(it + 1);
            cp_t64(sb + FV + (uint32_t)((it + 1) & 1) * 18432, vh, vl, b * S_ + (it + 1) * 64);
            CP_COMMIT();
        }

        // ---- gather + mask + scale ----
        float s[4][4];
#pragma unroll
        for (int nf = 0; nf < 4; nf++) {
            const int c0 = wc * 32 + nf * 8 + (lane & 3) * 2;
            const int t0 = la - c0 + 63;
            const float mk0 = maskS[it * 64 + c0];
            const float mk1 = maskS[it * 64 + c0 + 1];
            s[nf][0] = (accS[nf][0] + S2p[la * 132 + t0]           + S3p[c0 * 132 + t0])           * 0.125f + mk0;
            s[nf][1] = (accS[nf][1] + S2p[la * 132 + t0 - 1]       + S3p[(c0 + 1) * 132 + t0 - 1]) * 0.125f + mk1;
            s[nf][2] = (accS[nf][2] + S2p[(la + 8) * 132 + t0 + 8] + S3p[c0 * 132 + t0 + 8])       * 0.125f + mk0;
            s[nf][3] = (accS[nf][3] + S2p[(la + 8) * 132 + t0 + 7] + S3p[(c0 + 1) * 132 + t0 + 7]) * 0.125f + mk1;
        }

        // ---- online softmax ----
        float mA = -1e30f, mB = -1e30f;
#pragma unroll
        for (int nf = 0; nf < 4; nf++) {
            mA = fmaxf(mA, fmaxf(s[nf][0], s[nf][1]));
            mB = fmaxf(mB, fmaxf(s[nf][2], s[nf][3]));
        }
        mA = fmaxf(mA, __shfl_xor_sync(~0u, mA, 1));
        mA = fmaxf(mA, __shfl_xor_sync(~0u, mA, 2));
        mB = fmaxf(mB, __shfl_xor_sync(~0u, mB, 1));
        mB = fmaxf(mB, __shfl_xor_sync(~0u, mB, 2));
        if ((lane & 3) == 0) {
            redm[wc * 64 + la] = mA;
            redm[wc * 64 + la + 8] = mB;
        }
        __syncthreads();

        mA = fmaxf(mA, redm[(wc ^ 1) * 64 + la]);
        mB = fmaxf(mB, redm[(wc ^ 1) * 64 + la + 8]);
        const float mnA = fmaxf(mrunA, mA), mnB = fmaxf(mrunB, mB);
        const float sclA = __expf(mrunA - mnA), sclB = __expf(mrunB - mnB);
        mrunA = mnA; mrunB = mnB;
#pragma unroll
        for (int nf = 0; nf < 4; nf++) {
            O[nf][0] *= sclA; O[nf][1] *= sclA;
            O[nf][2] *= sclB; O[nf][3] *= sclB;
        }

        __nv_bfloat16* PsH = (__nv_bfloat16*)(smem + FS2);
        __nv_bfloat16* PsL = (__nv_bfloat16*)(smem + FS2 + 9216);
        float suA = 0.f, suB = 0.f;
#pragma unroll
        for (int nf = 0; nf < 4; nf++) {
            const int c0 = wc * 32 + nf * 8 + (lane & 3) * 2;
            float e0 = __expf(s[nf][0] - mnA), e1 = __expf(s[nf][1] - mnA);
            float e2 = __expf(s[nf][2] - mnB), e3 = __expf(s[nf][3] - mnB);
            suA += e0 + e1; suB += e2 + e3;
            store_split2(PsH, PsL, (size_t)la * 72 + c0, e0, e1);
            store_split2(PsH, PsL, (size_t)(la + 8) * 72 + c0, e2, e3);
        }
        suA += __shfl_xor_sync(~0u, suA, 1);
        suA += __shfl_xor_sync(~0u, suA, 2);
        suB += __shfl_xor_sync(~0u, suB, 1);
        suB += __shfl_xor_sync(~0u, suB, 2);
        if ((lane & 3) == 0) {
            redsum[wc * 64 + la] = suA;
            redsum[wc * 64 + la + 8] = suB;
        }
        __syncthreads();

        suA += redsum[(wc ^ 1) * 64 + la];
        suB += redsum[(wc ^ 1) * 64 + la + 8];
        srunA = srunA * sclA + suA;
        srunB = srunB * sclB + suB;

        // ---- O += P @ V (3-pass) ----
#pragma unroll
        for (int ks = 0; ks < 4; ks++) {
            uint32_t pah[4], pal[4];
            uint32_t ra = (uint32_t)(((wr * 16 + aRow) * 72) + ks * 16 + aCol) * 2;
            ldm4(pah, sb + FS2 + ra);
            ldm4(pal, sb + FS2 + 9216 + ra);
            uint32_t vbh[2][4], vbl[2][4];
#pragma unroll
            for (int p = 0; p < 2; p++) {
                uint32_t ro = (uint32_t)(((ks * 16 + aRow) * 72) + wc * 32 + p * 16 + aCol) * 2;
                ldm4t(vbh[p], Vb + ro);
                ldm4t(vbl[p], Vb + 9216 + ro);
            }
#pragma unroll
            for (int nf = 0; nf < 4; nf++) {
                const uint32_t* bhp = &vbh[nf >> 1][(nf & 1) * 2];
                const uint32_t* blp = &vbl[nf >> 1][(nf & 1) * 2];
                mma16816(O[nf], pah, bhp);
                mma16816(O[nf], pah, blp);
                mma16816(O[nf], pal, bhp);
            }
        }
        __syncthreads();
    }

    // ---- epilogue ----
    const float iA = 1.f / srunA, iB = 1.f / srunB;
#pragma unroll
    for (int nf = 0; nf < 4; nf++) {
        const int col = hcol + wc * 32 + nf * 8 + (lane & 3) * 2;
        const size_t rowA = (size_t)(b * S_ + l0 + la) * H_ + col;
        const size_t rowB = (size_t)(b * S_ + l0 + la + 8) * H_ + col;
        store_split2(ch, cl, rowA, O[nf][0] * iA, O[nf][1] * iA);
        store_split2(ch, cl, rowB, O[nf][2] * iB, O[nf][3] * iB);
    }
}

// ---------------- LayerNorm ----------------------------------------------------------
__global__ void __launch_bounds__(256) ln_kernel(const float* __restrict__ y,
                                                 const float* __restrict__ g,
                                                 const float* __restrict__ bb,
                                                 float* __restrict__ out)
{
    __shared__ float sred[8];
    __shared__ float sbc;
    const size_t row = blockIdx.x;
    const int tid = threadIdx.x;
    const int lane = tid & 31, wid = tid >> 5;

    float4 v = ((const float4*)(y + row * H_))[tid];

    float s = v.x + v.y + v.z + v.w;
#pragma unroll
    for (int o = 16; o > 0; o >>= 1) s += __shfl_xor_sync(~0u, s, o);
    if (lane == 0) sred[wid] = s;
    __syncthreads();
    if (tid == 0) {
        float t = 0.f;
#pragma unroll
        for (int i = 0; i < 8; i++) t += sred[i];
        sbc = t;
    }
    __syncthreads();
    const float mu = sbc * (1.f / H_);

    float dx = v.x - mu, dy = v.y - mu, dz = v.z - mu, dw = v.w - mu;
    float qq = dx * dx + dy * dy + dz * dz + dw * dw;
#pragma unroll
    for (int o = 16; o > 0; o >>= 1) qq += __shfl_xor_sync(~0u, qq, o);
    if (lane == 0) sred[wid] = qq;
    __syncthreads();
    if (tid == 0) {
        float t = 0.f;
#pragma unroll
        for (int i = 0; i < 8; i++) t += sred[i];
        sbc = t;
    }
    __syncthreads();
    const float rstd = rsqrtf(sbc * (1.f / H_) + 1e-12f);

    float4 gg = ((const float4*)g)[tid];
    float4 bt = ((const float4*)bb)[tid];
    float4 o;
    o.x = dx * rstd * gg.x + bt.x;
    o.y = dy * rstd * gg.y + bt.y;
    o.z = dz * rstd * gg.z + bt.z;
    o.w = dw * rstd * gg.w + bt.w;
    ((float4*)(out + row * H_))[tid] = o;
}

// ---------------- launch -----------------------------------------------------------
extern "C" void kernel_launch(void* const* d_in, const int* in_sizes, int n_in,
                              void* d_out, int out_size)
{
    (void)in_sizes; (void)n_in; (void)out_size;
    const float* x    = (const float*)d_in[0];
    const float* mask = (const float*)d_in[1];
    const float* Wq   = (const float*)d_in[2];
    const float* bq   = (const float*)d_in[3];
    const float* Wk   = (const float*)d_in[4];
    const float* bk   = (const float*)d_in[5];
    const float* Wv   = (const float*)d_in[6];
    const float* bv   = (const float*)d_in[7];
    const float* de   = (const float*)d_in[8];
    const float* Wo   = (const float*)d_in[9];
    const float* bo   = (const float*)d_in[10];
    const float* lng  = (const float*)d_in[11];
    const float* lnb  = (const float*)d_in[12];
    float* out = (float*)d_out;

    float* y;
    cudaGetSymbolAddress((void**)&y, g_y);

    __nv_bfloat16 *xh, *xl, *wqh, *wql, *wkh, *wkl, *wvh, *wvl, *woh, *wol;
    __nv_bfloat16 *qh, *ql, *kh, *kl, *vh, *vl, *deh, *del, *ch, *cl;
    cudaGetSymbolAddress((void**)&xh, g_xh);   cudaGetSymbolAddress((void**)&xl, g_xl);
    cudaGetSymbolAddress((void**)&wqh, g_wqh); cudaGetSymbolAddress((void**)&wql, g_wql);
    cudaGetSymbolAddress((void**)&wkh, g_wkh); cudaGetSymbolAddress((void**)&wkl, g_wkl);
    cudaGetSymbolAddress((void**)&wvh, g_wvh); cudaGetSymbolAddress((void**)&wvl, g_wvl);
    cudaGetSymbolAddress((void**)&woh, g_woh); cudaGetSymbolAddress((void**)&wol, g_wol);
    cudaGetSymbolAddress((void**)&qh, g_qh);   cudaGetSymbolAddress((void**)&ql, g_ql);
    cudaGetSymbolAddress((void**)&kh, g_kh);   cudaGetSymbolAddress((void**)&kl, g_kl);
    cudaGetSymbolAddress((void**)&vh, g_vh);   cudaGetSymbolAddress((void**)&vl, g_vl);
    cudaGetSymbolAddress((void**)&deh, g_deh); cudaGetSymbolAddress((void**)&del, g_del);
    cudaGetSymbolAddress((void**)&ch, g_ch);   cudaGetSymbolAddress((void**)&cl, g_cl);

    cudaFuncSetAttribute(gemm_mma2<1>, cudaFuncAttributeMaxDynamicSharedMemorySize, GSM_TOTAL);
    cudaFuncSetAttribute(gemm_mma2<2>, cudaFuncAttributeMaxDynamicSharedMemorySize, GSM_TOTAL);
    cudaFuncSetAttribute(fused_attn, cudaFuncAttributeMaxDynamicSharedMemorySize, FSM_TOTAL);

    const int NX4 = BS_ * H_ / 4;
    const int NW4 = H_ * H_ / 4;
    split_kernel<<<NX4 / 256, 256>>>(x, xh, xl, NX4);
    split4_kernel<<<dim3(NW4 / 256, 4), 256>>>(Wq, Wk, Wv, Wo,
                                               wqh, wql, wkh, wkl,
                                               wvh, wvl, woh, wol);
    const int ND4 = 2047 * 64 / 4;
    split_kernel<<<(ND4 + 255) / 256, 256>>>(de, deh, del, ND4);

    gemm_mma2<2><<<dim3(H_ / 128, BS_ / 128, 3), 256, GSM_TOTAL>>>(
        xh, xl, wqh, wql, wkh, wkl, wvh, wvl, bq, bk, bv,
        qh, kh, vh, ql, kl, vl, nullptr);

    fused_attn<<<dim3(S_ / 64, BH_), 256, FSM_TOTAL>>>(
        qh, ql, kh, kl, vh, vl, deh, mask, ch, cl);

    gemm_mma2<1><<<dim3(H_ / 128, BS_ / 128, 1), 256, GSM_TOTAL>>>(
        ch, cl, woh, wol, woh, wol, woh, wol, bo, bo, bo,
        y, y, y, nullptr, nullptr, nullptr, x);

    ln_kernel<<<BS_, 256>>>(y, lng, lnb, out);
}

// round 8
// speedup vs baseline: 1.3574x; 1.3574x over previous
#include <cuda_runtime.h>
#include <cuda_bf16.h>
#include <cstdint>

#define S_   1024
#define H_   1024
#define B_   4
#define NH_  16
#define D_   64
#define BS_  4096
#define BH_  64

// ---------------- scratch (no allocs allowed) ----------------
__device__ float g_y[BS_ * H_];

__device__ __nv_bfloat16 g_xh[BS_ * H_], g_xl[BS_ * H_];
__device__ __nv_bfloat16 g_wqh[H_ * H_], g_wql[H_ * H_];
__device__ __nv_bfloat16 g_wkh[H_ * H_], g_wkl[H_ * H_];
__device__ __nv_bfloat16 g_wvh[H_ * H_], g_wvl[H_ * H_];
__device__ __nv_bfloat16 g_woh[H_ * H_], g_wol[H_ * H_];
__device__ __nv_bfloat16 g_qh[BS_ * H_], g_ql[BS_ * H_];
__device__ __nv_bfloat16 g_kh[BS_ * H_], g_kl[BS_ * H_];
__device__ __nv_bfloat16 g_vh[BS_ * H_], g_vl[BS_ * H_];
__device__ __nv_bfloat16 g_deh[2047 * 64], g_del[2047 * 64];
__device__ __nv_bfloat16 g_ch[BS_ * H_], g_cl[BS_ * H_];

// ---------------- helpers -------------------------------------------------------
__device__ __forceinline__ uint32_t smem_u32(const void* p)
{
    return (uint32_t)__cvta_generic_to_shared(p);
}
__device__ __forceinline__ void ldm4(uint32_t* r, uint32_t addr)
{
    asm volatile("ldmatrix.sync.aligned.m8n8.x4.shared.b16 {%0,%1,%2,%3}, [%4];"
                 : "=r"(r[0]), "=r"(r[1]), "=r"(r[2]), "=r"(r[3]) : "r"(addr));
}
__device__ __forceinline__ void ldm4t(uint32_t* r, uint32_t addr)
{
    asm volatile("ldmatrix.sync.aligned.m8n8.x4.trans.shared.b16 {%0,%1,%2,%3}, [%4];"
                 : "=r"(r[0]), "=r"(r[1]), "=r"(r[2]), "=r"(r[3]) : "r"(addr));
}
__device__ __forceinline__ void mma16816(float* c, const uint32_t* a, const uint32_t* b)
{
    asm volatile("mma.sync.aligned.m16n8k16.row.col.f32.bf16.bf16.f32 "
                 "{%0,%1,%2,%3}, {%4,%5,%6,%7}, {%8,%9}, {%0,%1,%2,%3};"
                 : "+f"(c[0]), "+f"(c[1]), "+f"(c[2]), "+f"(c[3])
                 : "r"(a[0]), "r"(a[1]), "r"(a[2]), "r"(a[3]), "r"(b[0]), "r"(b[1]));
}
__device__ __forceinline__ void cpa16(uint32_t dst, const void* src)
{
    asm volatile("cp.async.cg.shared.global [%0], [%1], 16;" :: "r"(dst), "l"(src));
}
#define CP_COMMIT() asm volatile("cp.async.commit_group;" ::: "memory")
#define CP_WAIT2()  asm volatile("cp.async.wait_group 2;" ::: "memory")
#define CP_WAIT1()  asm volatile("cp.async.wait_group 1;" ::: "memory")
#define CP_WAIT0()  asm volatile("cp.async.wait_group 0;" ::: "memory")

__device__ __forceinline__ void store_split2(__nv_bfloat16* Hp, __nv_bfloat16* Lp,
                                             size_t off, float f0, float f1)
{
    __nv_bfloat162 hp, lp;
    hp.x = __float2bfloat16(f0); hp.y = __float2bfloat16(f1);
    lp.x = __float2bfloat16(f0 - __bfloat162float(hp.x));
    lp.y = __float2bfloat16(f1 - __bfloat162float(hp.y));
    *(__nv_bfloat162*)(Hp + off) = hp;
    *(__nv_bfloat162*)(Lp + off) = lp;
}

// ---------------- fp32 -> (hi,lo) bf16 split ---------------------------------------
__global__ void __launch_bounds__(256) split_kernel(const float* __restrict__ in,
                                                    __nv_bfloat16* __restrict__ hi,
                                                    __nv_bfloat16* __restrict__ lo,
                                                    int n4)
{
    int i = blockIdx.x * 256 + threadIdx.x;
    if (i >= n4) return;
    float4 a = ((const float4*)in)[i];
    __nv_bfloat16 h0 = __float2bfloat16(a.x);
    __nv_bfloat16 h1 = __float2bfloat16(a.y);
    __nv_bfloat16 h2 = __float2bfloat16(a.z);
    __nv_bfloat16 h3 = __float2bfloat16(a.w);
    __nv_bfloat162 hh0; hh0.x = h0; hh0.y = h1;
    __nv_bfloat162 hh1; hh1.x = h2; hh1.y = h3;
    ((__nv_bfloat162*)hi)[i * 2 + 0] = hh0;
    ((__nv_bfloat162*)hi)[i * 2 + 1] = hh1;
    __nv_bfloat162 ll0, ll1;
    ll0.x = __float2bfloat16(a.x - __bfloat162float(h0));
    ll0.y = __float2bfloat16(a.y - __bfloat162float(h1));
    ll1.x = __float2bfloat16(a.z - __bfloat162float(h2));
    ll1.y = __float2bfloat16(a.w - __bfloat162float(h3));
    ((__nv_bfloat162*)lo)[i * 2 + 0] = ll0;
    ((__nv_bfloat162*)lo)[i * 2 + 1] = ll1;
}

__global__ void __launch_bounds__(256) split4_kernel(
    const float* __restrict__ w0, const float* __restrict__ w1,
    const float* __restrict__ w2, const float* __restrict__ w3,
    __nv_bfloat16* __restrict__ h0, __nv_bfloat16* __restrict__ l0p,
    __nv_bfloat16* __restrict__ h1, __nv_bfloat16* __restrict__ l1p,
    __nv_bfloat16* __restrict__ h2, __nv_bfloat16* __restrict__ l2p,
    __nv_bfloat16* __restrict__ h3, __nv_bfloat16* __restrict__ l3p)
{
    const int z = blockIdx.y;
    const float* in = (z == 0) ? w0 : (z == 1) ? w1 : (z == 2) ? w2 : w3;
    __nv_bfloat16* hi = (z == 0) ? h0 : (z == 1) ? h1 : (z == 2) ? h2 : h3;
    __nv_bfloat16* lo = (z == 0) ? l0p : (z == 1) ? l1p : (z == 2) ? l2p : l3p;
    int i = blockIdx.x * 256 + threadIdx.x;
    float4 a = ((const float4*)in)[i];
    __nv_bfloat16 a0 = __float2bfloat16(a.x);
    __nv_bfloat16 a1 = __float2bfloat16(a.y);
    __nv_bfloat16 a2 = __float2bfloat16(a.z);
    __nv_bfloat16 a3 = __float2bfloat16(a.w);
    __nv_bfloat162 hh0; hh0.x = a0; hh0.y = a1;
    __nv_bfloat162 hh1; hh1.x = a2; hh1.y = a3;
    ((__nv_bfloat162*)hi)[i * 2 + 0] = hh0;
    ((__nv_bfloat162*)hi)[i * 2 + 1] = hh1;
    __nv_bfloat162 ll0, ll1;
    ll0.x = __float2bfloat16(a.x - __bfloat162float(a0));
    ll0.y = __float2bfloat16(a.y - __bfloat162float(a1));
    ll1.x = __float2bfloat16(a.z - __bfloat162float(a2));
    ll1.y = __float2bfloat16(a.w - __bfloat162float(a3));
    ((__nv_bfloat162*)lo)[i * 2 + 0] = ll0;
    ((__nv_bfloat162*)lo)[i * 2 + 1] = ll1;
}

// ---------------- split-bf16 GEMM NT via HMMA, 3-stage cp.async (R6 config) --------
#define KT    32
#define LDS_  40
#define MAT_B (128 * LDS_ * 2)
#define STG_B (4 * MAT_B)
#define NSTG  3
#define GSM_TOTAL (NSTG * STG_B)

template <int EPI>
__global__ void __launch_bounds__(256) gemm_mma2(
    const __nv_bfloat16* __restrict__ Ah, const __nv_bfloat16* __restrict__ Al,
    const __nv_bfloat16* __restrict__ Bh0, const __nv_bfloat16* __restrict__ Bl0,
    const __nv_bfloat16* __restrict__ Bh1, const __nv_bfloat16* __restrict__ Bl1,
    const __nv_bfloat16* __restrict__ Bh2, const __nv_bfloat16* __restrict__ Bl2,
    const float* __restrict__ bias0, const float* __restrict__ bias1,
    const float* __restrict__ bias2,
    void* O0, void* O1, void* O2,
    void* L0, void* L1, void* L2,
    const float* __restrict__ resid)
{
    extern __shared__ char smem[];
    const uint32_t sb = smem_u32(smem);

    const int z = blockIdx.z;
    const __nv_bfloat16* Bh = (z == 0) ? Bh0 : (z == 1) ? Bh1 : Bh2;
    const __nv_bfloat16* Bl = (z == 0) ? Bl0 : (z == 1) ? Bl1 : Bl2;
    const float* bias = (z == 0) ? bias0 : (z == 1) ? bias1 : bias2;
    void* Ov = (z == 0) ? O0 : (z == 1) ? O1 : O2;
    void* Lv = (z == 0) ? L0 : (z == 1) ? L1 : L2;

    const int tid = threadIdx.x;
    const int lane = tid & 31, wid = tid >> 5;
    const int wm = wid >> 2, wn = wid & 3;
    const int bM = blockIdx.y * 128, bN = blockIdx.x * 128;

    float acc[4][4][4] = {};

    const int v0row = tid >> 2, v0c = (tid & 3);
    const int v1row = (tid + 256) >> 2, v1c = ((tid + 256) & 3);
    const int NK = H_ / KT;

    const int q8 = lane >> 3, r8 = lane & 7;
    const int arowL = wm * 64 + (q8 & 1) * 8 + r8;
    const int browL = wn * 32 + (q8 >> 1) * 8 + r8;
    const int acolL = (q8 >> 1) * 8;
    const int bcolL = (q8 & 1) * 8;

    auto issue = [&](int kt) {
        const int st = kt % NSTG;
        const uint32_t base = sb + st * STG_B;
        const int k0 = kt * KT;
        const uint32_t d0 = (uint32_t)(v0row * (LDS_ * 2) + v0c * 16);
        const uint32_t d1 = (uint32_t)(v1row * (LDS_ * 2) + v1c * 16);
        const size_t gA0 = (size_t)(bM + v0row) * H_ + k0 + v0c * 8;
        const size_t gA1 = (size_t)(bM + v1row) * H_ + k0 + v1c * 8;
        const size_t gB0 = (size_t)(bN + v0row) * H_ + k0 + v0c * 8;
        const size_t gB1 = (size_t)(bN + v1row) * H_ + k0 + v1c * 8;
        cpa16(base + 0 * MAT_B + d0, Ah + gA0);
        cpa16(base + 0 * MAT_B + d1, Ah + gA1);
        cpa16(base + 1 * MAT_B + d0, Al + gA0);
        cpa16(base + 1 * MAT_B + d1, Al + gA1);
        cpa16(base + 2 * MAT_B + d0, Bh + gB0);
        cpa16(base + 2 * MAT_B + d1, Bh + gB1);
        cpa16(base + 3 * MAT_B + d0, Bl + gB0);
        cpa16(base + 3 * MAT_B + d1, Bl + gB1);
    };

    issue(0); CP_COMMIT();
    issue(1); CP_COMMIT();

    for (int kt = 0; kt < NK; kt++) {
        if (kt + 2 < NK) { issue(kt + 2); CP_COMMIT(); CP_WAIT2(); }
        else if (kt + 1 < NK) { CP_WAIT1(); }
        else { CP_WAIT0(); }
        __syncthreads();

        const int st = kt % NSTG;
        const uint32_t bAh = sb + st * STG_B + 0 * MAT_B;
        const uint32_t bAl = sb + st * STG_B + 1 * MAT_B;
        const uint32_t bBh = sb + st * STG_B + 2 * MAT_B;
        const uint32_t bBl = sb + st * STG_B + 3 * MAT_B;

#pragma unroll
        for (int ks = 0; ks < KT; ks += 16) {
            uint32_t afh[4][4], afl[4][4];
#pragma unroll
            for (int mt = 0; mt < 4; mt++) {
                const uint32_t ro = (uint32_t)(((arowL + mt * 16) * LDS_ + acolL + ks) * 2);
                ldm4(afh[mt], bAh + ro);
                ldm4(afl[mt], bAl + ro);
            }
            uint32_t bfh[2][4], bfl[2][4];
#pragma unroll
            for (int p = 0; p < 2; p++) {
                const uint32_t ro = (uint32_t)(((browL + p * 16) * LDS_ + bcolL + ks) * 2);
                ldm4(bfh[p], bBh + ro);
                ldm4(bfl[p], bBl + ro);
            }
#pragma unroll
            for (int mt = 0; mt < 4; mt++)
#pragma unroll
                for (int nt = 0; nt < 4; nt++) {
                    const uint32_t* bhp = &bfh[nt >> 1][(nt & 1) * 2];
                    const uint32_t* blp = &bfl[nt >> 1][(nt & 1) * 2];
                    mma16816(acc[mt][nt], afh[mt], bhp);
                    mma16816(acc[mt][nt], afh[mt], blp);
                    mma16816(acc[mt][nt], afl[mt], bhp);
                }
        }
        __syncthreads();
    }

    const int crow0 = bM + wm * 64 + (lane >> 2);
    const int ccol0 = bN + wn * 32 + (lane & 3) * 2;
#pragma unroll
    for (int mt = 0; mt < 4; mt++) {
        const int r0 = crow0 + mt * 16;
#pragma unroll
        for (int nt = 0; nt < 4; nt++) {
            const int c0 = ccol0 + nt * 8;
            float f0 = acc[mt][nt][0] + bias[c0];
            float f1 = acc[mt][nt][1] + bias[c0 + 1];
            float f2 = acc[mt][nt][2] + bias[c0];
            float f3 = acc[mt][nt][3] + bias[c0 + 1];
            if (EPI == 1) {
                f0 += resid[(size_t)r0 * H_ + c0];
                f1 += resid[(size_t)r0 * H_ + c0 + 1];
                f2 += resid[(size_t)(r0 + 8) * H_ + c0];
                f3 += resid[(size_t)(r0 + 8) * H_ + c0 + 1];
            }
            if (EPI == 2) {
                __nv_bfloat16* OH = (__nv_bfloat16*)Ov;
                __nv_bfloat16* OL = (__nv_bfloat16*)Lv;
                store_split2(OH, OL, (size_t)r0 * H_ + c0, f0, f1);
                store_split2(OH, OL, (size_t)(r0 + 8) * H_ + c0, f2, f3);
            } else {
                float* O = (float*)Ov;
                O[(size_t)r0 * H_ + c0]           = f0;
                O[(size_t)r0 * H_ + c0 + 1]       = f1;
                O[(size_t)(r0 + 8) * H_ + c0]     = f2;
                O[(size_t)(r0 + 8) * H_ + c0 + 1] = f3;
            }
        }
    }
}

// ---------------- fused flash attention, 111KB smem -> 2 CTAs/SM -------------------
// bf16 S2/S3 staging (pitch 136), single V buffer with deferred prefetch.
#define FQ    0
#define FK    18432
#define FV    36864
#define FP    55296
#define FS2B  73728               // bf16 [64][136] = 17408
#define FS3B  91136               // bf16 [64][136] = 17408
#define FPS   73728               // probs hi @73728, lo @+9216 (overlap, post-gather)
#define FRED  108544              // redm [2][64] f32, redsum [2][64] f32
#define FMASK 109568              // 1024 f32
#define FSM_TOTAL 113664

__global__ void __launch_bounds__(256, 2) fused_attn(
    const __nv_bfloat16* __restrict__ qh, const __nv_bfloat16* __restrict__ ql,
    const __nv_bfloat16* __restrict__ kh, const __nv_bfloat16* __restrict__ kl,
    const __nv_bfloat16* __restrict__ vh, const __nv_bfloat16* __restrict__ vl,
    const __nv_bfloat16* __restrict__ deh,
    const float* __restrict__ mask,
    __nv_bfloat16* __restrict__ ch, __nv_bfloat16* __restrict__ cl)
{
    extern __shared__ char smem[];
    const uint32_t sb = smem_u32(smem);
    const int tid = threadIdx.x, lane = tid & 31, wid = tid >> 5;
    const int wr = wid >> 1, wc = wid & 1;
    const int l0 = blockIdx.x * 64;
    const int bh = blockIdx.y;
    const int b = bh >> 4, h = bh & 15;
    const int hcol = h * D_;

    const int q8 = lane >> 3, r8 = lane & 7;
    const int aRow = (q8 & 1) * 8 + r8, aCol = (q8 >> 1) * 8;
    const int bRow = (q8 >> 1) * 8 + r8, bCol = (q8 & 1) * 8;

    auto cp_t64 = [&](uint32_t dstbase, const __nv_bfloat16* srcH,
                      const __nv_bfloat16* srcL, int growbase) {
#pragma unroll
        for (int j = 0; j < 2; j++) {
            int v = tid + 256 * j;
            int row = v >> 3, c = v & 7;
            uint32_t d = dstbase + (uint32_t)(row * 72 + c * 8) * 2;
            cpa16(d, srcH + (size_t)(growbase + row) * H_ + hcol + c * 8);
            cpa16(d + 9216, srcL + (size_t)(growbase + row) * H_ + hcol + c * 8);
        }
    };
    auto cp_P = [&](int it) {
        const int prow0 = l0 - it * 64 + 960;
#pragma unroll
        for (int j = 0; j < 4; j++) {
            int v = tid + 256 * j;
            int row = v >> 3, c = v & 7;
            uint32_t off = (uint32_t)(row * 72 + c * 8) * 2;
            if (row < 127) {
                cpa16(sb + FP + off, deh + (size_t)(prow0 + row) * 64 + c * 8);
            } else {
                uint4 zz = {0, 0, 0, 0};
                *(uint4*)(smem + FP + off) = zz;
            }
        }
    };

    // ---- prologue: group1 = {Q, K0, P0, mask}, group2 = {V0} ----
    cp_t64(sb + FQ, qh, ql, b * S_ + l0);
    cp_t64(sb + FK, kh, kl, b * S_ + 0);
    cp_P(0);
    cpa16(sb + FMASK + tid * 16, mask + (size_t)b * S_ + tid * 4);
    CP_COMMIT();
    cp_t64(sb + FV, vh, vl, b * S_ + 0);
    CP_COMMIT();

    float O[4][4] = {};
    float mrunA = -1e30f, mrunB = -1e30f;
    float srunA = 0.f, srunB = 0.f;

    const int la = wr * 16 + (lane >> 2);
    __nv_bfloat16* S2b = (__nv_bfloat16*)(smem + FS2B);
    __nv_bfloat16* S3b = (__nv_bfloat16*)(smem + FS3B);
    float* redm = (float*)(smem + FRED);
    float* redsum = (float*)(smem + FRED + 512);
    const float* maskS = (const float*)(smem + FMASK);

    for (int it = 0; it < 16; it++) {
        CP_WAIT1();          // KP(it) ready (V may still be in flight)
        __syncthreads();

        // ---- S1 = Q @ K^T (3-pass) ----
        float accS[4][4] = {};
#pragma unroll
        for (int ks = 0; ks < 4; ks++) {
            uint32_t ah_[4], al_[4];
            ldm4(ah_, sb + FQ + (uint32_t)(((wr * 16 + aRow) * 72) + ks * 16 + aCol) * 2);
            ldm4(al_, sb + FQ + 9216 + (uint32_t)(((wr * 16 + aRow) * 72) + ks * 16 + aCol) * 2);
            uint32_t kbh[2][4], kbl[2][4];
#pragma unroll
            for (int p = 0; p < 2; p++) {
                uint32_t ro = (uint32_t)(((wc * 32 + p * 16 + bRow) * 72) + ks * 16 + bCol) * 2;
                ldm4(kbh[p], sb + FK + ro);
                ldm4(kbl[p], sb + FK + 9216 + ro);
            }
#pragma unroll
            for (int nf = 0; nf < 4; nf++) {
                const uint32_t* bhp = &kbh[nf >> 1][(nf & 1) * 2];
                const uint32_t* blp = &kbl[nf >> 1][(nf & 1) * 2];
                mma16816(accS[nf], ah_, bhp);
                mma16816(accS[nf], ah_, blp);
                mma16816(accS[nf], al_, bhp);
            }
        }

        // ---- S2 = Qh @ Ph^T (single pass) -> bf16 stage ----
        {
            float a2[4][2][4] = {};
#pragma unroll
            for (int ks = 0; ks < 4; ks++) {
                uint32_t pb[4];
                uint32_t ro = (uint32_t)(((wid * 16 + bRow) * 72) + ks * 16 + bCol) * 2;
                ldm4(pb, sb + FP + ro);
#pragma unroll
                for (int mt = 0; mt < 4; mt++) {
                    uint32_t ah_[4];
                    uint32_t ra = (uint32_t)(((mt * 16 + aRow) * 72) + ks * 16 + aCol) * 2;
                    ldm4(ah_, sb + FQ + ra);
#pragma unroll
                    for (int nf = 0; nf < 2; nf++)
                        mma16816(a2[mt][nf], ah_, &pb[nf * 2]);
                }
            }
#pragma unroll
            for (int mt = 0; mt < 4; mt++) {
                const int rr = mt * 16 + (lane >> 2);
#pragma unroll
                for (int nf = 0; nf < 2; nf++) {
                    const int cc = wid * 16 + nf * 8 + (lane & 3) * 2;
                    float2 u0; u0.x = a2[mt][nf][0]; u0.y = a2[mt][nf][1];
                    float2 u1; u1.x = a2[mt][nf][2]; u1.y = a2[mt][nf][3];
                    *(__nv_bfloat162*)&S2b[rr * 136 + cc] = __float22bfloat162_rn(u0);
                    *(__nv_bfloat162*)&S2b[(rr + 8) * 136 + cc] = __float22bfloat162_rn(u1);
                }
            }
        }
        // ---- S3 = Kh @ Ph^T (single pass) -> bf16 stage ----
        {
            float a3[4][2][4] = {};
#pragma unroll
            for (int ks = 0; ks < 4; ks++) {
                uint32_t pb[4];
                uint32_t ro = (uint32_t)(((wid * 16 + bRow) * 72) + ks * 16 + bCol) * 2;
                ldm4(pb, sb + FP + ro);
#pragma unroll
                for (int mt = 0; mt < 4; mt++) {
                    uint32_t ah_[4];
                    uint32_t ra = (uint32_t)(((mt * 16 + aRow) * 72) + ks * 16 + aCol) * 2;
                    ldm4(ah_, sb + FK + ra);
#pragma unroll
                    for (int nf = 0; nf < 2; nf++)
                        mma16816(a3[mt][nf], ah_, &pb[nf * 2]);
                }
            }
#pragma unroll
            for (int mt = 0; mt < 4; mt++) {
                const int rr = mt * 16 + (lane >> 2);
#pragma unroll
                for (int nf = 0; nf < 2; nf++) {
                    const int cc = wid * 16 + nf * 8 + (lane & 3) * 2;
                    float2 u0; u0.x = a3[mt][nf][0]; u0.y = a3[mt][nf][1];
                    float2 u1; u1.x = a3[mt][nf][2]; u1.y = a3[mt][nf][3];
                    *(__nv_bfloat162*)&S3b[rr * 136 + cc] = __float22bfloat162_rn(u0);
                    *(__nv_bfloat162*)&S3b[(rr + 8) * 136 + cc] = __float22bfloat162_rn(u1);
                }
            }
        }
        __syncthreads();   // staging visible; K,P reads done

        // prefetch next K,P (group: KP(it+1))
        if (it < 15) {
            cp_t64(sb + FK, kh, kl, b * S_ + (it + 1) * 64);
            cp_P(it + 1);
            CP_COMMIT();
        }

        // ---- gather + mask + scale ----
        float s[4][4];
#pragma unroll
        for (int nf = 0; nf < 4; nf++) {
            const int c0 = wc * 32 + nf * 8 + (lane & 3) * 2;
            const int t0 = la - c0 + 63;
            const float mk0 = maskS[it * 64 + c0];
            const float mk1 = maskS[it * 64 + c0 + 1];
            float s2a = __bfloat162float(S2b[la * 136 + t0]);
            float s2b_ = __bfloat162float(S2b[la * 136 + t0 - 1]);
            float s2c = __bfloat162float(S2b[(la + 8) * 136 + t0 + 8]);
            float s2d = __bfloat162float(S2b[(la + 8) * 136 + t0 + 7]);
            float s3a = __bfloat162float(S3b[c0 * 136 + t0]);
            float s3b_ = __bfloat162float(S3b[(c0 + 1) * 136 + t0 - 1]);
            float s3c = __bfloat162float(S3b[c0 * 136 + t0 + 8]);
            float s3d = __bfloat162float(S3b[(c0 + 1) * 136 + t0 + 7]);
            s[nf][0] = (accS[nf][0] + s2a + s3a) * 0.125f + mk0;
            s[nf][1] = (accS[nf][1] + s2b_ + s3b_) * 0.125f + mk1;
            s[nf][2] = (accS[nf][2] + s2c + s3c) * 0.125f + mk0;
            s[nf][3] = (accS[nf][3] + s2d + s3d) * 0.125f + mk1;
        }

        // ---- online softmax ----
        float mA = -1e30f, mB = -1e30f;
#pragma unroll
        for (int nf = 0; nf < 4; nf++) {
            mA = fmaxf(mA, fmaxf(s[nf][0], s[nf][1]));
            mB = fmaxf(mB, fmaxf(s[nf][2], s[nf][3]));
        }
        mA = fmaxf(mA, __shfl_xor_sync(~0u, mA, 1));
        mA = fmaxf(mA, __shfl_xor_sync(~0u, mA, 2));
        mB = fmaxf(mB, __shfl_xor_sync(~0u, mB, 1));
        mB = fmaxf(mB, __shfl_xor_sync(~0u, mB, 2));
        if ((lane & 3) == 0) {
            redm[wc * 64 + la] = mA;
            redm[wc * 64 + la + 8] = mB;
        }
        __syncthreads();   // redm ready; all S2/S3 gathers done -> probs may overwrite

        mA = fmaxf(mA, redm[(wc ^ 1) * 64 + la]);
        mB = fmaxf(mB, redm[(wc ^ 1) * 64 + la + 8]);
        const float mnA = fmaxf(mrunA, mA), mnB = fmaxf(mrunB, mB);
        const float sclA = __expf(mrunA - mnA), sclB = __expf(mrunB - mnB);
        mrunA = mnA; mrunB = mnB;
#pragma unroll
        for (int nf = 0; nf < 4; nf++) {
            O[nf][0] *= sclA; O[nf][1] *= sclA;
            O[nf][2] *= sclB; O[nf][3] *= sclB;
        }

        __nv_bfloat16* PsH = (__nv_bfloat16*)(smem + FPS);
        __nv_bfloat16* PsL = (__nv_bfloat16*)(smem + FPS + 9216);
        float suA = 0.f, suB = 0.f;
#pragma unroll
        for (int nf = 0; nf < 4; nf++) {
            const int c0 = wc * 32 + nf * 8 + (lane & 3) * 2;
            float e0 = __expf(s[nf][0] - mnA), e1 = __expf(s[nf][1] - mnA);
            float e2 = __expf(s[nf][2] - mnB), e3 = __expf(s[nf][3] - mnB);
            suA += e0 + e1; suB += e2 + e3;
            store_split2(PsH, PsL, (size_t)la * 72 + c0, e0, e1);
            store_split2(PsH, PsL, (size_t)(la + 8) * 72 + c0, e2, e3);
        }
        suA += __shfl_xor_sync(~0u, suA, 1);
        suA += __shfl_xor_sync(~0u, suA, 2);
        suB += __shfl_xor_sync(~0u, suB, 1);
        suB += __shfl_xor_sync(~0u, suB, 2);
        if ((lane & 3) == 0) {
            redsum[wc * 64 + la] = suA;
            redsum[wc * 64 + la + 8] = suB;
        }
        // ensure V(it) has arrived (in flight after this: KP(it+1) only)
        if (it < 15) { CP_WAIT1(); } else { CP_WAIT0(); }
        __syncthreads();   // probs + redsum + V visible

        suA += redsum[(wc ^ 1) * 64 + la];
        suB += redsum[(wc ^ 1) * 64 + la + 8];
        srunA = srunA * sclA + suA;
        srunB = srunB * sclB + suB;

        // ---- O += P @ V (3-pass) ----
#pragma unroll
        for (int ks = 0; ks < 4; ks++) {
            uint32_t pah[4], pal[4];
            uint32_t ra = (uint32_t)(((wr * 16 + aRow) * 72) + ks * 16 + aCol) * 2;
            ldm4(pah, sb + FPS + ra);
            ldm4(pal, sb + FPS + 9216 + ra);
            uint32_t vbh[2][4], vbl[2][4];
#pragma unroll
            for (int p = 0; p < 2; p++) {
                uint32_t ro = (uint32_t)(((ks * 16 + aRow) * 72) + wc * 32 + p * 16 + aCol) * 2;
                ldm4t(vbh[p], sb + FV + ro);
                ldm4t(vbl[p], sb + FV + 9216 + ro);
            }
#pragma unroll
            for (int nf = 0; nf < 4; nf++) {
                const uint32_t* bhp = &vbh[nf >> 1][(nf & 1) * 2];
                const uint32_t* blp = &vbl[nf >> 1][(nf & 1) * 2];
                mma16816(O[nf], pah, bhp);
                mma16816(O[nf], pah, blp);
                mma16816(O[nf], pal, bhp);
            }
        }
        __syncthreads();   // PV reads of V done before overwrite

        // deferred V prefetch (group: V(it+1))
        if (it < 15) {
            cp_t64(sb + FV, vh, vl, b * S_ + (it + 1) * 64);
            CP_COMMIT();
        }
    }

    // ---- epilogue ----
    const float iA = 1.f / srunA, iB = 1.f / srunB;
#pragma unroll
    for (int nf = 0; nf < 4; nf++) {
        const int col = hcol + wc * 32 + nf * 8 + (lane & 3) * 2;
        const size_t rowA = (size_t)(b * S_ + l0 + la) * H_ + col;
        const size_t rowB = (size_t)(b * S_ + l0 + la + 8) * H_ + col;
        store_split2(ch, cl, rowA, O[nf][0] * iA, O[nf][1] * iA);
        store_split2(ch, cl, rowB, O[nf][2] * iB, O[nf][3] * iB);
    }
}

// ---------------- LayerNorm ----------------------------------------------------------
__global__ void __launch_bounds__(256) ln_kernel(const float* __restrict__ y,
                                                 const float* __restrict__ g,
                                                 const float* __restrict__ bb,
                                                 float* __restrict__ out)
{
    __shared__ float sred[8];
    __shared__ float sbc;
    const size_t row = blockIdx.x;
    const int tid = threadIdx.x;
    const int lane = tid & 31, wid = tid >> 5;

    float4 v = ((const float4*)(y + row * H_))[tid];

    float s = v.x + v.y + v.z + v.w;
#pragma unroll
    for (int o = 16; o > 0; o >>= 1) s += __shfl_xor_sync(~0u, s, o);
    if (lane == 0) sred[wid] = s;
    __syncthreads();
    if (tid == 0) {
        float t = 0.f;
#pragma unroll
        for (int i = 0; i < 8; i++) t += sred[i];
        sbc = t;
    }
    __syncthreads();
    const float mu = sbc * (1.f / H_);

    float dx = v.x - mu, dy = v.y - mu, dz = v.z - mu, dw = v.w - mu;
    float qq = dx * dx + dy * dy + dz * dz + dw * dw;
#pragma unroll
    for (int o = 16; o > 0; o >>= 1) qq += __shfl_xor_sync(~0u, qq, o);
    if (lane == 0) sred[wid] = qq;
    __syncthreads();
    if (tid == 0) {
        float t = 0.f;
#pragma unroll
        for (int i = 0; i < 8; i++) t += sred[i];
        sbc = t;
    }
    __syncthreads();
    const float rstd = rsqrtf(sbc * (1.f / H_) + 1e-12f);

    float4 gg = ((const float4*)g)[tid];
    float4 bt = ((const float4*)bb)[tid];
    float4 o;
    o.x = dx * rstd * gg.x + bt.x;
    o.y = dy * rstd * gg.y + bt.y;
    o.z = dz * rstd * gg.z + bt.z;
    o.w = dw * rstd * gg.w + bt.w;
    ((float4*)(out + row * H_))[tid] = o;
}

// ---------------- launch -----------------------------------------------------------
extern "C" void kernel_launch(void* const* d_in, const int* in_sizes, int n_in,
                              void* d_out, int out_size)
{
    (void)in_sizes; (void)n_in; (void)out_size;
    const float* x    = (const float*)d_in[0];
    const float* mask = (const float*)d_in[1];
    const float* Wq   = (const float*)d_in[2];
    const float* bq   = (const float*)d_in[3];
    const float* Wk   = (const float*)d_in[4];
    const float* bk   = (const float*)d_in[5];
    const float* Wv   = (const float*)d_in[6];
    const float* bv   = (const float*)d_in[7];
    const float* de   = (const float*)d_in[8];
    const float* Wo   = (const float*)d_in[9];
    const float* bo   = (const float*)d_in[10];
    const float* lng  = (const float*)d_in[11];
    const float* lnb  = (const float*)d_in[12];
    float* out = (float*)d_out;

    float* y;
    cudaGetSymbolAddress((void**)&y, g_y);

    __nv_bfloat16 *xh, *xl, *wqh, *wql, *wkh, *wkl, *wvh, *wvl, *woh, *wol;
    __nv_bfloat16 *qh, *ql, *kh, *kl, *vh, *vl, *deh, *del, *ch, *cl;
    cudaGetSymbolAddress((void**)&xh, g_xh);   cudaGetSymbolAddress((void**)&xl, g_xl);
    cudaGetSymbolAddress((void**)&wqh, g_wqh); cudaGetSymbolAddress((void**)&wql, g_wql);
    cudaGetSymbolAddress((void**)&wkh, g_wkh); cudaGetSymbolAddress((void**)&wkl, g_wkl);
    cudaGetSymbolAddress((void**)&wvh, g_wvh); cudaGetSymbolAddress((void**)&wvl, g_wvl);
    cudaGetSymbolAddress((void**)&woh, g_woh); cudaGetSymbolAddress((void**)&wol, g_wol);
    cudaGetSymbolAddress((void**)&qh, g_qh);   cudaGetSymbolAddress((void**)&ql, g_ql);
    cudaGetSymbolAddress((void**)&kh, g_kh);   cudaGetSymbolAddress((void**)&kl, g_kl);
    cudaGetSymbolAddress((void**)&vh, g_vh);   cudaGetSymbolAddress((void**)&vl, g_vl);
    cudaGetSymbolAddress((void**)&deh, g_deh); cudaGetSymbolAddress((void**)&del, g_del);
    cudaGetSymbolAddress((void**)&ch, g_ch);   cudaGetSymbolAddress((void**)&cl, g_cl);

    cudaFuncSetAttribute(gemm_mma2<1>, cudaFuncAttributeMaxDynamicSharedMemorySize, GSM_TOTAL);
    cudaFuncSetAttribute(gemm_mma2<2>, cudaFuncAttributeMaxDynamicSharedMemorySize, GSM_TOTAL);
    cudaFuncSetAttribute(fused_attn, cudaFuncAttributeMaxDynamicSharedMemorySize, FSM_TOTAL);

    const int NX4 = BS_ * H_ / 4;
    const int NW4 = H_ * H_ / 4;
    split_kernel<<<NX4 / 256, 256>>>(x, xh, xl, NX4);
    split4_kernel<<<dim3(NW4 / 256, 4), 256>>>(Wq, Wk, Wv, Wo,
                                               wqh, wql, wkh, wkl,
                                               wvh, wvl, woh, wol);
    const int ND4 = 2047 * 64 / 4;
    split_kernel<<<(ND4 + 255) / 256, 256>>>(de, deh, del, ND4);

    gemm_mma2<2><<<dim3(H_ / 128, BS_ / 128, 3), 256, GSM_TOTAL>>>(
        xh, xl, wqh, wql, wkh, wkl, wvh, wvl, bq, bk, bv,
        qh, kh, vh, ql, kl, vl, nullptr);

    fused_attn<<<dim3(S_ / 64, BH_), 256, FSM_TOTAL>>>(
        qh, ql, kh, kl, vh, vl, deh, mask, ch, cl);

    gemm_mma2<1><<<dim3(H_ / 128, BS_ / 128, 1), 256, GSM_TOTAL>>>(
        ch, cl, woh, wol, woh, wol, woh, wol, bo, bo, bo,
        y, y, y, nullptr, nullptr, nullptr, x);

    ln_kernel<<<BS_, 256>>>(y, lng, lnb, out);
}

// round 9
// speedup vs baseline: 1.3721x; 1.0108x over previous
#include <cuda_runtime.h>
#include <cuda_bf16.h>
#include <cstdint>

#define S_   1024
#define H_   1024
#define B_   4
#define NH_  16
#define D_   64
#define BS_  4096
#define BH_  64

// ---------------- scratch (no allocs allowed) ----------------
__device__ float g_y[BS_ * H_];

__device__ __nv_bfloat16 g_xh[BS_ * H_], g_xl[BS_ * H_];
__device__ __nv_bfloat16 g_wqh[H_ * H_], g_wql[H_ * H_];
__device__ __nv_bfloat16 g_wkh[H_ * H_], g_wkl[H_ * H_];
__device__ __nv_bfloat16 g_wvh[H_ * H_], g_wvl[H_ * H_];
__device__ __nv_bfloat16 g_woh[H_ * H_], g_wol[H_ * H_];
__device__ __nv_bfloat16 g_qh[BS_ * H_], g_ql[BS_ * H_];
__device__ __nv_bfloat16 g_kh[BS_ * H_], g_kl[BS_ * H_];
__device__ __nv_bfloat16 g_vh[BS_ * H_], g_vl[BS_ * H_];
__device__ __nv_bfloat16 g_deh[2047 * 64], g_del[2047 * 64];
__device__ __nv_bfloat16 g_ch[BS_ * H_], g_cl[BS_ * H_];

// ---------------- helpers -------------------------------------------------------
__device__ __forceinline__ uint32_t smem_u32(const void* p)
{
    return (uint32_t)__cvta_generic_to_shared(p);
}
__device__ __forceinline__ void ldm4(uint32_t* r, uint32_t addr)
{
    asm volatile("ldmatrix.sync.aligned.m8n8.x4.shared.b16 {%0,%1,%2,%3}, [%4];"
                 : "=r"(r[0]), "=r"(r[1]), "=r"(r[2]), "=r"(r[3]) : "r"(addr));
}
__device__ __forceinline__ void ldm4t(uint32_t* r, uint32_t addr)
{
    asm volatile("ldmatrix.sync.aligned.m8n8.x4.trans.shared.b16 {%0,%1,%2,%3}, [%4];"
                 : "=r"(r[0]), "=r"(r[1]), "=r"(r[2]), "=r"(r[3]) : "r"(addr));
}
__device__ __forceinline__ void mma16816(float* c, const uint32_t* a, const uint32_t* b)
{
    asm volatile("mma.sync.aligned.m16n8k16.row.col.f32.bf16.bf16.f32 "
                 "{%0,%1,%2,%3}, {%4,%5,%6,%7}, {%8,%9}, {%0,%1,%2,%3};"
                 : "+f"(c[0]), "+f"(c[1]), "+f"(c[2]), "+f"(c[3])
                 : "r"(a[0]), "r"(a[1]), "r"(a[2]), "r"(a[3]), "r"(b[0]), "r"(b[1]));
}
__device__ __forceinline__ void cpa16(uint32_t dst, const void* src)
{
    asm volatile("cp.async.cg.shared.global [%0], [%1], 16;" :: "r"(dst), "l"(src));
}
#define CP_COMMIT() asm volatile("cp.async.commit_group;" ::: "memory")
#define CP_WAIT2()  asm volatile("cp.async.wait_group 2;" ::: "memory")
#define CP_WAIT1()  asm volatile("cp.async.wait_group 1;" ::: "memory")
#define CP_WAIT0()  asm volatile("cp.async.wait_group 0;" ::: "memory")

__device__ __forceinline__ void store_split2(__nv_bfloat16* Hp, __nv_bfloat16* Lp,
                                             size_t off, float f0, float f1)
{
    __nv_bfloat162 hp, lp;
    hp.x = __float2bfloat16(f0); hp.y = __float2bfloat16(f1);
    lp.x = __float2bfloat16(f0 - __bfloat162float(hp.x));
    lp.y = __float2bfloat16(f1 - __bfloat162float(hp.y));
    *(__nv_bfloat162*)(Hp + off) = hp;
    *(__nv_bfloat162*)(Lp + off) = lp;
}

// ---------------- fp32 -> (hi,lo) bf16 split ---------------------------------------
__global__ void __launch_bounds__(256) split_kernel(const float* __restrict__ in,
                                                    __nv_bfloat16* __restrict__ hi,
                                                    __nv_bfloat16* __restrict__ lo,
                                                    int n4)
{
    int i = blockIdx.x * 256 + threadIdx.x;
    if (i >= n4) return;
    float4 a = ((const float4*)in)[i];
    __nv_bfloat16 h0 = __float2bfloat16(a.x);
    __nv_bfloat16 h1 = __float2bfloat16(a.y);
    __nv_bfloat16 h2 = __float2bfloat16(a.z);
    __nv_bfloat16 h3 = __float2bfloat16(a.w);
    __nv_bfloat162 hh0; hh0.x = h0; hh0.y = h1;
    __nv_bfloat162 hh1; hh1.x = h2; hh1.y = h3;
    ((__nv_bfloat162*)hi)[i * 2 + 0] = hh0;
    ((__nv_bfloat162*)hi)[i * 2 + 1] = hh1;
    __nv_bfloat162 ll0, ll1;
    ll0.x = __float2bfloat16(a.x - __bfloat162float(h0));
    ll0.y = __float2bfloat16(a.y - __bfloat162float(h1));
    ll1.x = __float2bfloat16(a.z - __bfloat162float(h2));
    ll1.y = __float2bfloat16(a.w - __bfloat162float(h3));
    ((__nv_bfloat162*)lo)[i * 2 + 0] = ll0;
    ((__nv_bfloat162*)lo)[i * 2 + 1] = ll1;
}

__global__ void __launch_bounds__(256) split4_kernel(
    const float* __restrict__ w0, const float* __restrict__ w1,
    const float* __restrict__ w2, const float* __restrict__ w3,
    __nv_bfloat16* __restrict__ h0, __nv_bfloat16* __restrict__ l0p,
    __nv_bfloat16* __restrict__ h1, __nv_bfloat16* __restrict__ l1p,
    __nv_bfloat16* __restrict__ h2, __nv_bfloat16* __restrict__ l2p,
    __nv_bfloat16* __restrict__ h3, __nv_bfloat16* __restrict__ l3p)
{
    const int z = blockIdx.y;
    const float* in = (z == 0) ? w0 : (z == 1) ? w1 : (z == 2) ? w2 : w3;
    __nv_bfloat16* hi = (z == 0) ? h0 : (z == 1) ? h1 : (z == 2) ? h2 : h3;
    __nv_bfloat16* lo = (z == 0) ? l0p : (z == 1) ? l1p : (z == 2) ? l2p : l3p;
    int i = blockIdx.x * 256 + threadIdx.x;
    float4 a = ((const float4*)in)[i];
    __nv_bfloat16 a0 = __float2bfloat16(a.x);
    __nv_bfloat16 a1 = __float2bfloat16(a.y);
    __nv_bfloat16 a2 = __float2bfloat16(a.z);
    __nv_bfloat16 a3 = __float2bfloat16(a.w);
    __nv_bfloat162 hh0; hh0.x = a0; hh0.y = a1;
    __nv_bfloat162 hh1; hh1.x = a2; hh1.y = a3;
    ((__nv_bfloat162*)hi)[i * 2 + 0] = hh0;
    ((__nv_bfloat162*)hi)[i * 2 + 1] = hh1;
    __nv_bfloat162 ll0, ll1;
    ll0.x = __float2bfloat16(a.x - __bfloat162float(a0));
    ll0.y = __float2bfloat16(a.y - __bfloat162float(a1));
    ll1.x = __float2bfloat16(a.z - __bfloat162float(a2));
    ll1.y = __float2bfloat16(a.w - __bfloat162float(a3));
    ((__nv_bfloat162*)lo)[i * 2 + 0] = ll0;
    ((__nv_bfloat162*)lo)[i * 2 + 1] = ll1;
}

// ---------------- split-bf16 GEMM NT via HMMA, 3-stage KT=16, 2 CTAs/SM ------------
#define KT    16
#define LDS_  24                    // 16 + 8 pad halves; 48B row stride (conflict-free)
#define MAT_B (128 * LDS_ * 2)      // 6144 B
#define STG_B (4 * MAT_B)           // 24576 B
#define NSTG  3
#define GSM_TOTAL (NSTG * STG_B)    // 73728 B -> 2 CTAs/SM

template <int EPI>
__global__ void __launch_bounds__(256, 2) gemm_mma2(
    const __nv_bfloat16* __restrict__ Ah, const __nv_bfloat16* __restrict__ Al,
    const __nv_bfloat16* __restrict__ Bh0, const __nv_bfloat16* __restrict__ Bl0,
    const __nv_bfloat16* __restrict__ Bh1, const __nv_bfloat16* __restrict__ Bl1,
    const __nv_bfloat16* __restrict__ Bh2, const __nv_bfloat16* __restrict__ Bl2,
    const float* __restrict__ bias0, const float* __restrict__ bias1,
    const float* __restrict__ bias2,
    void* O0, void* O1, void* O2,
    void* L0, void* L1, void* L2,
    const float* __restrict__ resid)
{
    extern __shared__ char smem[];
    const uint32_t sb = smem_u32(smem);

    const int z = blockIdx.z;
    const __nv_bfloat16* Bh = (z == 0) ? Bh0 : (z == 1) ? Bh1 : Bh2;
    const __nv_bfloat16* Bl = (z == 0) ? Bl0 : (z == 1) ? Bl1 : Bl2;
    const float* bias = (z == 0) ? bias0 : (z == 1) ? bias1 : bias2;
    void* Ov = (z == 0) ? O0 : (z == 1) ? O1 : O2;
    void* Lv = (z == 0) ? L0 : (z == 1) ? L1 : L2;

    const int tid = threadIdx.x;
    const int lane = tid & 31, wid = tid >> 5;
    const int wm = wid >> 2, wn = wid & 3;
    const int bM = blockIdx.y * 128, bN = blockIdx.x * 128;

    float acc[4][4][4] = {};

    // cp.async mapping: 1 vec16 per thread per matrix per stage
    const int vrow = tid >> 1;
    const int vc   = tid & 1;
    const int NK = H_ / KT;   // 64

    const int q8 = lane >> 3, r8 = lane & 7;
    const int arowL = wm * 64 + (q8 & 1) * 8 + r8;
    const int browL = wn * 32 + (q8 >> 1) * 8 + r8;
    const int acolL = (q8 >> 1) * 8;
    const int bcolL = (q8 & 1) * 8;

    auto issue = [&](int kt) {
        const int st = kt % NSTG;
        const uint32_t base = sb + st * STG_B;
        const int k0 = kt * KT;
        const uint32_t d0 = (uint32_t)(vrow * (LDS_ * 2) + vc * 16);
        const size_t gA = (size_t)(bM + vrow) * H_ + k0 + vc * 8;
        const size_t gB = (size_t)(bN + vrow) * H_ + k0 + vc * 8;
        cpa16(base + 0 * MAT_B + d0, Ah + gA);
        cpa16(base + 1 * MAT_B + d0, Al + gA);
        cpa16(base + 2 * MAT_B + d0, Bh + gB);
        cpa16(base + 3 * MAT_B + d0, Bl + gB);
    };

    issue(0); CP_COMMIT();
    issue(1); CP_COMMIT();

    for (int kt = 0; kt < NK; kt++) {
        if (kt + 2 < NK) { issue(kt + 2); CP_COMMIT(); CP_WAIT2(); }
        else if (kt + 1 < NK) { CP_WAIT1(); }
        else { CP_WAIT0(); }
        __syncthreads();

        const int st = kt % NSTG;
        const uint32_t bAh = sb + st * STG_B + 0 * MAT_B;
        const uint32_t bAl = sb + st * STG_B + 1 * MAT_B;
        const uint32_t bBh = sb + st * STG_B + 2 * MAT_B;
        const uint32_t bBl = sb + st * STG_B + 3 * MAT_B;

        uint32_t afh[4][4], afl[4][4];
#pragma unroll
        for (int mt = 0; mt < 4; mt++) {
            const uint32_t ro = (uint32_t)(((arowL + mt * 16) * LDS_ + acolL) * 2);
            ldm4(afh[mt], bAh + ro);
            ldm4(afl[mt], bAl + ro);
        }
        uint32_t bfh[2][4], bfl[2][4];
#pragma unroll
        for (int p = 0; p < 2; p++) {
            const uint32_t ro = (uint32_t)(((browL + p * 16) * LDS_ + bcolL) * 2);
            ldm4(bfh[p], bBh + ro);
            ldm4(bfl[p], bBl + ro);
        }
#pragma unroll
        for (int mt = 0; mt < 4; mt++)
#pragma unroll
            for (int nt = 0; nt < 4; nt++) {
                const uint32_t* bhp = &bfh[nt >> 1][(nt & 1) * 2];
                const uint32_t* blp = &bfl[nt >> 1][(nt & 1) * 2];
                mma16816(acc[mt][nt], afh[mt], bhp);
                mma16816(acc[mt][nt], afh[mt], blp);
                mma16816(acc[mt][nt], afl[mt], bhp);
            }
        __syncthreads();
    }

    const int crow0 = bM + wm * 64 + (lane >> 2);
    const int ccol0 = bN + wn * 32 + (lane & 3) * 2;
#pragma unroll
    for (int mt = 0; mt < 4; mt++) {
        const int r0 = crow0 + mt * 16;
#pragma unroll
        for (int nt = 0; nt < 4; nt++) {
            const int c0 = ccol0 + nt * 8;
            float f0 = acc[mt][nt][0] + bias[c0];
            float f1 = acc[mt][nt][1] + bias[c0 + 1];
            float f2 = acc[mt][nt][2] + bias[c0];
            float f3 = acc[mt][nt][3] + bias[c0 + 1];
            if (EPI == 1) {
                f0 += resid[(size_t)r0 * H_ + c0];
                f1 += resid[(size_t)r0 * H_ + c0 + 1];
                f2 += resid[(size_t)(r0 + 8) * H_ + c0];
                f3 += resid[(size_t)(r0 + 8) * H_ + c0 + 1];
            }
            if (EPI == 2) {
                __nv_bfloat16* OH = (__nv_bfloat16*)Ov;
                __nv_bfloat16* OL = (__nv_bfloat16*)Lv;
                store_split2(OH, OL, (size_t)r0 * H_ + c0, f0, f1);
                store_split2(OH, OL, (size_t)(r0 + 8) * H_ + c0, f2, f3);
            } else {
                float* O = (float*)Ov;
                O[(size_t)r0 * H_ + c0]           = f0;
                O[(size_t)r0 * H_ + c0 + 1]       = f1;
                O[(size_t)(r0 + 8) * H_ + c0]     = f2;
                O[(size_t)(r0 + 8) * H_ + c0 + 1] = f3;
            }
        }
    }
}

// ---------------- fused flash attention, 111KB smem -> 2 CTAs/SM (R8 config) -------
#define FQ    0
#define FK    18432
#define FV    36864
#define FP    55296
#define FS2B  73728               // bf16 [64][136] = 17408
#define FS3B  91136               // bf16 [64][136] = 17408
#define FPS   73728               // probs hi @73728, lo @+9216 (overlap, post-gather)
#define FRED  108544
#define FMASK 109568
#define FSM_TOTAL 113664

__global__ void __launch_bounds__(256, 2) fused_attn(
    const __nv_bfloat16* __restrict__ qh, const __nv_bfloat16* __restrict__ ql,
    const __nv_bfloat16* __restrict__ kh, const __nv_bfloat16* __restrict__ kl,
    const __nv_bfloat16* __restrict__ vh, const __nv_bfloat16* __restrict__ vl,
    const __nv_bfloat16* __restrict__ deh,
    const float* __restrict__ mask,
    __nv_bfloat16* __restrict__ ch, __nv_bfloat16* __restrict__ cl)
{
    extern __shared__ char smem[];
    const uint32_t sb = smem_u32(smem);
    const int tid = threadIdx.x, lane = tid & 31, wid = tid >> 5;
    const int wr = wid >> 1, wc = wid & 1;
    const int l0 = blockIdx.x * 64;
    const int bh = blockIdx.y;
    const int b = bh >> 4, h = bh & 15;
    const int hcol = h * D_;

    const int q8 = lane >> 3, r8 = lane & 7;
    const int aRow = (q8 & 1) * 8 + r8, aCol = (q8 >> 1) * 8;
    const int bRow = (q8 >> 1) * 8 + r8, bCol = (q8 & 1) * 8;

    auto cp_t64 = [&](uint32_t dstbase, const __nv_bfloat16* srcH,
                      const __nv_bfloat16* srcL, int growbase) {
#pragma unroll
        for (int j = 0; j < 2; j++) {
            int v = tid + 256 * j;
            int row = v >> 3, c = v & 7;
            uint32_t d = dstbase + (uint32_t)(row * 72 + c * 8) * 2;
            cpa16(d, srcH + (size_t)(growbase + row) * H_ + hcol + c * 8);
            cpa16(d + 9216, srcL + (size_t)(growbase + row) * H_ + hcol + c * 8);
        }
    };
    auto cp_P = [&](int it) {
        const int prow0 = l0 - it * 64 + 960;
#pragma unroll
        for (int j = 0; j < 4; j++) {
            int v = tid + 256 * j;
            int row = v >> 3, c = v & 7;
            uint32_t off = (uint32_t)(row * 72 + c * 8) * 2;
            if (row < 127) {
                cpa16(sb + FP + off, deh + (size_t)(prow0 + row) * 64 + c * 8);
            } else {
                uint4 zz = {0, 0, 0, 0};
                *(uint4*)(smem + FP + off) = zz;
            }
        }
    };

    cp_t64(sb + FQ, qh, ql, b * S_ + l0);
    cp_t64(sb + FK, kh, kl, b * S_ + 0);
    cp_P(0);
    cpa16(sb + FMASK + tid * 16, mask + (size_t)b * S_ + tid * 4);
    CP_COMMIT();
    cp_t64(sb + FV, vh, vl, b * S_ + 0);
    CP_COMMIT();

    float O[4][4] = {};
    float mrunA = -1e30f, mrunB = -1e30f;
    float srunA = 0.f, srunB = 0.f;

    const int la = wr * 16 + (lane >> 2);
    __nv_bfloat16* S2b = (__nv_bfloat16*)(smem + FS2B);
    __nv_bfloat16* S3b = (__nv_bfloat16*)(smem + FS3B);
    float* redm = (float*)(smem + FRED);
    float* redsum = (float*)(smem + FRED + 512);
    const float* maskS = (const float*)(smem + FMASK);

    for (int it = 0; it < 16; it++) {
        CP_WAIT1();
        __syncthreads();

        // ---- S1 = Q @ K^T (3-pass) ----
        float accS[4][4] = {};
#pragma unroll
        for (int ks = 0; ks < 4; ks++) {
            uint32_t ah_[4], al_[4];
            ldm4(ah_, sb + FQ + (uint32_t)(((wr * 16 + aRow) * 72) + ks * 16 + aCol) * 2);
            ldm4(al_, sb + FQ + 9216 + (uint32_t)(((wr * 16 + aRow) * 72) + ks * 16 + aCol) * 2);
            uint32_t kbh[2][4], kbl[2][4];
#pragma unroll
            for (int p = 0; p < 2; p++) {
                uint32_t ro = (uint32_t)(((wc * 32 + p * 16 + bRow) * 72) + ks * 16 + bCol) * 2;
                ldm4(kbh[p], sb + FK + ro);
                ldm4(kbl[p], sb + FK + 9216 + ro);
            }
#pragma unroll
            for (int nf = 0; nf < 4; nf++) {
                const uint32_t* bhp = &kbh[nf >> 1][(nf & 1) * 2];
                const uint32_t* blp = &kbl[nf >> 1][(nf & 1) * 2];
                mma16816(accS[nf], ah_, bhp);
                mma16816(accS[nf], ah_, blp);
                mma16816(accS[nf], al_, bhp);
            }
        }

        // ---- S2 = Qh @ Ph^T (single pass) -> bf16 stage ----
        {
            float a2[4][2][4] = {};
#pragma unroll
            for (int ks = 0; ks < 4; ks++) {
                uint32_t pb[4];
                uint32_t ro = (uint32_t)(((wid * 16 + bRow) * 72) + ks * 16 + bCol) * 2;
                ldm4(pb, sb + FP + ro);
#pragma unroll
                for (int mt = 0; mt < 4; mt++) {
                    uint32_t ah_[4];
                    uint32_t ra = (uint32_t)(((mt * 16 + aRow) * 72) + ks * 16 + aCol) * 2;
                    ldm4(ah_, sb + FQ + ra);
#pragma unroll
                    for (int nf = 0; nf < 2; nf++)
                        mma16816(a2[mt][nf], ah_, &pb[nf * 2]);
                }
            }
#pragma unroll
            for (int mt = 0; mt < 4; mt++) {
                const int rr = mt * 16 + (lane >> 2);
#pragma unroll
                for (int nf = 0; nf < 2; nf++) {
                    const int cc = wid * 16 + nf * 8 + (lane & 3) * 2;
                    float2 u0; u0.x = a2[mt][nf][0]; u0.y = a2[mt][nf][1];
                    float2 u1; u1.x = a2[mt][nf][2]; u1.y = a2[mt][nf][3];
                    *(__nv_bfloat162*)&S2b[rr * 136 + cc] = __float22bfloat162_rn(u0);
                    *(__nv_bfloat162*)&S2b[(rr + 8) * 136 + cc] = __float22bfloat162_rn(u1);
                }
            }
        }
        // ---- S3 = Kh @ Ph^T (single pass) -> bf16 stage ----
        {
            float a3[4][2][4] = {};
#pragma unroll
            for (int ks = 0; ks < 4; ks++) {
                uint32_t pb[4];
                uint32_t ro = (uint32_t)(((wid * 16 + bRow) * 72) + ks * 16 + bCol) * 2;
                ldm4(pb, sb + FP + ro);
#pragma unroll
                for (int mt = 0; mt < 4; mt++) {
                    uint32_t ah_[4];
                    uint32_t ra = (uint32_t)(((mt * 16 + aRow) * 72) + ks * 16 + aCol) * 2;
                    ldm4(ah_, sb + FK + ra);
#pragma unroll
                    for (int nf = 0; nf < 2; nf++)
                        mma16816(a3[mt][nf], ah_, &pb[nf * 2]);
                }
            }
#pragma unroll
            for (int mt = 0; mt < 4; mt++) {
                const int rr = mt * 16 + (lane >> 2);
#pragma unroll
                for (int nf = 0; nf < 2; nf++) {
                    const int cc = wid * 16 + nf * 8 + (lane & 3) * 2;
                    float2 u0; u0.x = a3[mt][nf][0]; u0.y = a3[mt][nf][1];
                    float2 u1; u1.x = a3[mt][nf][2]; u1.y = a3[mt][nf][3];
                    *(__nv_bfloat162*)&S3b[rr * 136 + cc] = __float22bfloat162_rn(u0);
                    *(__nv_bfloat162*)&S3b[(rr + 8) * 136 + cc] = __float22bfloat162_rn(u1);
                }
            }
        }
        __syncthreads();

        if (it < 15) {
            cp_t64(sb + FK, kh, kl, b * S_ + (it + 1) * 64);
            cp_P(it + 1);
            CP_COMMIT();
        }

        // ---- gather + mask + scale ----
        float s[4][4];
#pragma unroll
        for (int nf = 0; nf < 4; nf++) {
            const int c0 = wc * 32 + nf * 8 + (lane & 3) * 2;
            const int t0 = la - c0 + 63;
            const float mk0 = maskS[it * 64 + c0];
            const float mk1 = maskS[it * 64 + c0 + 1];
            float s2a = __bfloat162float(S2b[la * 136 + t0]);
            float s2b_ = __bfloat162float(S2b[la * 136 + t0 - 1]);
            float s2c = __bfloat162float(S2b[(la + 8) * 136 + t0 + 8]);
            float s2d = __bfloat162float(S2b[(la + 8) * 136 + t0 + 7]);
            float s3a = __bfloat162float(S3b[c0 * 136 + t0]);
            float s3b_ = __bfloat162float(S3b[(c0 + 1) * 136 + t0 - 1]);
            float s3c = __bfloat162float(S3b[c0 * 136 + t0 + 8]);
            float s3d = __bfloat162float(S3b[(c0 + 1) * 136 + t0 + 7]);
            s[nf][0] = (accS[nf][0] + s2a + s3a) * 0.125f + mk0;
            s[nf][1] = (accS[nf][1] + s2b_ + s3b_) * 0.125f + mk1;
            s[nf][2] = (accS[nf][2] + s2c + s3c) * 0.125f + mk0;
            s[nf][3] = (accS[nf][3] + s2d + s3d) * 0.125f + mk1;
        }

        // ---- online softmax ----
        float mA = -1e30f, mB = -1e30f;
#pragma unroll
        for (int nf = 0; nf < 4; nf++) {
            mA = fmaxf(mA, fmaxf(s[nf][0], s[nf][1]));
            mB = fmaxf(mB, fmaxf(s[nf][2], s[nf][3]));
        }
        mA = fmaxf(mA, __shfl_xor_sync(~0u, mA, 1));
        mA = fmaxf(mA, __shfl_xor_sync(~0u, mA, 2));
        mB = fmaxf(mB, __shfl_xor_sync(~0u, mB, 1));
        mB = fmaxf(mB, __shfl_xor_sync(~0u, mB, 2));
        if ((lane & 3) == 0) {
            redm[wc * 64 + la] = mA;
            redm[wc * 64 + la + 8] = mB;
        }
        __syncthreads();

        mA = fmaxf(mA, redm[(wc ^ 1) * 64 + la]);
        mB = fmaxf(mB, redm[(wc ^ 1) * 64 + la + 8]);
        const float mnA = fmaxf(mrunA, mA), mnB = fmaxf(mrunB, mB);
        const float sclA = __expf(mrunA - mnA), sclB = __expf(mrunB - mnB);
        mrunA = mnA; mrunB = mnB;
#pragma unroll
        for (int nf = 0; nf < 4; nf++) {
            O[nf][0] *= sclA; O[nf][1] *= sclA;
            O[nf][2] *= sclB; O[nf][3] *= sclB;
        }

        __nv_bfloat16* PsH = (__nv_bfloat16*)(smem + FPS);
        __nv_bfloat16* PsL = (__nv_bfloat16*)(smem + FPS + 9216);
        float suA = 0.f, suB = 0.f;
#pragma unroll
        for (int nf = 0; nf < 4; nf++) {
            const int c0 = wc * 32 + nf * 8 + (lane & 3) * 2;
            float e0 = __expf(s[nf][0] - mnA), e1 = __expf(s[nf][1] - mnA);
            float e2 = __expf(s[nf][2] - mnB), e3 = __expf(s[nf][3] - mnB);
            suA += e0 + e1; suB += e2 + e3;
            store_split2(PsH, PsL, (size_t)la * 72 + c0, e0, e1);
            store_split2(PsH, PsL, (size_t)(la + 8) * 72 + c0, e2, e3);
        }
        suA += __shfl_xor_sync(~0u, suA, 1);
        suA += __shfl_xor_sync(~0u, suA, 2);
        suB += __shfl_xor_sync(~0u, suB, 1);
        suB += __shfl_xor_sync(~0u, suB, 2);
        if ((lane & 3) == 0) {
            redsum[wc * 64 + la] = suA;
            redsum[wc * 64 + la + 8] = suB;
        }
        if (it < 15) { CP_WAIT1(); } else { CP_WAIT0(); }
        __syncthreads();

        suA += redsum[(wc ^ 1) * 64 + la];
        suB += redsum[(wc ^ 1) * 64 + la + 8];
        srunA = srunA * sclA + suA;
        srunB = srunB * sclB + suB;

        // ---- O += P @ V (3-pass) ----
#pragma unroll
        for (int ks = 0; ks < 4; ks++) {
            uint32_t pah[4], pal[4];
            uint32_t ra = (uint32_t)(((wr * 16 + aRow) * 72) + ks * 16 + aCol) * 2;
            ldm4(pah, sb + FPS + ra);
            ldm4(pal, sb + FPS + 9216 + ra);
            uint32_t vbh[2][4], vbl[2][4];
#pragma unroll
            for (int p = 0; p < 2; p++) {
                uint32_t ro = (uint32_t)(((ks * 16 + aRow) * 72) + wc * 32 + p * 16 + aCol) * 2;
                ldm4t(vbh[p], sb + FV + ro);
                ldm4t(vbl[p], sb + FV + 9216 + ro);
            }
#pragma unroll
            for (int nf = 0; nf < 4; nf++) {
                const uint32_t* bhp = &vbh[nf >> 1][(nf & 1) * 2];
                const uint32_t* blp = &vbl[nf >> 1][(nf & 1) * 2];
                mma16816(O[nf], pah, bhp);
                mma16816(O[nf], pah, blp);
                mma16816(O[nf], pal, bhp);
            }
        }
        __syncthreads();

        if (it < 15) {
            cp_t64(sb + FV, vh, vl, b * S_ + (it + 1) * 64);
            CP_COMMIT();
        }
    }

    const float iA = 1.f / srunA, iB = 1.f / srunB;
#pragma unroll
    for (int nf = 0; nf < 4; nf++) {
        const int col = hcol + wc * 32 + nf * 8 + (lane & 3) * 2;
        const size_t rowA = (size_t)(b * S_ + l0 + la) * H_ + col;
        const size_t rowB = (size_t)(b * S_ + l0 + la + 8) * H_ + col;
        store_split2(ch, cl, rowA, O[nf][0] * iA, O[nf][1] * iA);
        store_split2(ch, cl, rowB, O[nf][2] * iB, O[nf][3] * iB);
    }
}

// ---------------- LayerNorm ----------------------------------------------------------
__global__ void __launch_bounds__(256) ln_kernel(const float* __restrict__ y,
                                                 const float* __restrict__ g,
                                                 const float* __restrict__ bb,
                                                 float* __restrict__ out)
{
    __shared__ float sred[8];
    __shared__ float sbc;
    const size_t row = blockIdx.x;
    const int tid = threadIdx.x;
    const int lane = tid & 31, wid = tid >> 5;

    float4 v = ((const float4*)(y + row * H_))[tid];

    float s = v.x + v.y + v.z + v.w;
#pragma unroll
    for (int o = 16; o > 0; o >>= 1) s += __shfl_xor_sync(~0u, s, o);
    if (lane == 0) sred[wid] = s;
    __syncthreads();
    if (tid == 0) {
        float t = 0.f;
#pragma unroll
        for (int i = 0; i < 8; i++) t += sred[i];
        sbc = t;
    }
    __syncthreads();
    const float mu = sbc * (1.f / H_);

    float dx = v.x - mu, dy = v.y - mu, dz = v.z - mu, dw = v.w - mu;
    float qq = dx * dx + dy * dy + dz * dz + dw * dw;
#pragma unroll
    for (int o = 16; o > 0; o >>= 1) qq += __shfl_xor_sync(~0u, qq, o);
    if (lane == 0) sred[wid] = qq;
    __syncthreads();
    if (tid == 0) {
        float t = 0.f;
#pragma unroll
        for (int i = 0; i < 8; i++) t += sred[i];
        sbc = t;
    }
    __syncthreads();
    const float rstd = rsqrtf(sbc * (1.f / H_) + 1e-12f);

    float4 gg = ((const float4*)g)[tid];
    float4 bt = ((const float4*)bb)[tid];
    float4 o;
    o.x = dx * rstd * gg.x + bt.x;
    o.y = dy * rstd * gg.y + bt.y;
    o.z = dz * rstd * gg.z + bt.z;
    o.w = dw * rstd * gg.w + bt.w;
    ((float4*)(out + row * H_))[tid] = o;
}

// ---------------- launch -----------------------------------------------------------
extern "C" void kernel_launch(void* const* d_in, const int* in_sizes, int n_in,
                              void* d_out, int out_size)
{
    (void)in_sizes; (void)n_in; (void)out_size;
    const float* x    = (const float*)d_in[0];
    const float* mask = (const float*)d_in[1];
    const float* Wq   = (const float*)d_in[2];
    const float* bq   = (const float*)d_in[3];
    const float* Wk   = (const float*)d_in[4];
    const float* bk   = (const float*)d_in[5];
    const float* Wv   = (const float*)d_in[6];
    const float* bv   = (const float*)d_in[7];
    const float* de   = (const float*)d_in[8];
    const float* Wo   = (const float*)d_in[9];
    const float* bo   = (const float*)d_in[10];
    const float* lng  = (const float*)d_in[11];
    const float* lnb  = (const float*)d_in[12];
    float* out = (float*)d_out;

    float* y;
    cudaGetSymbolAddress((void**)&y, g_y);

    __nv_bfloat16 *xh, *xl, *wqh, *wql, *wkh, *wkl, *wvh, *wvl, *woh, *wol;
    __nv_bfloat16 *qh, *ql, *kh, *kl, *vh, *vl, *deh, *del, *ch, *cl;
    cudaGetSymbolAddress((void**)&xh, g_xh);   cudaGetSymbolAddress((void**)&xl, g_xl);
    cudaGetSymbolAddress((void**)&wqh, g_wqh); cudaGetSymbolAddress((void**)&wql, g_wql);
    cudaGetSymbolAddress((void**)&wkh, g_wkh); cudaGetSymbolAddress((void**)&wkl, g_wkl);
    cudaGetSymbolAddress((void**)&wvh, g_wvh); cudaGetSymbolAddress((void**)&wvl, g_wvl);
    cudaGetSymbolAddress((void**)&woh, g_woh); cudaGetSymbolAddress((void**)&wol, g_wol);
    cudaGetSymbolAddress((void**)&qh, g_qh);   cudaGetSymbolAddress((void**)&ql, g_ql);
    cudaGetSymbolAddress((void**)&kh, g_kh);   cudaGetSymbolAddress((void**)&kl, g_kl);
    cudaGetSymbolAddress((void**)&vh, g_vh);   cudaGetSymbolAddress((void**)&vl, g_vl);
    cudaGetSymbolAddress((void**)&deh, g_deh); cudaGetSymbolAddress((void**)&del, g_del);
    cudaGetSymbolAddress((void**)&ch, g_ch);   cudaGetSymbolAddress((void**)&cl, g_cl);

    cudaFuncSetAttribute(gemm_mma2<1>, cudaFuncAttributeMaxDynamicSharedMemorySize, GSM_TOTAL);
    cudaFuncSetAttribute(gemm_mma2<2>, cudaFuncAttributeMaxDynamicSharedMemorySize, GSM_TOTAL);
    cudaFuncSetAttribute(fused_attn, cudaFuncAttributeMaxDynamicSharedMemorySize, FSM_TOTAL);

    const int NX4 = BS_ * H_ / 4;
    const int NW4 = H_ * H_ / 4;
    split_kernel<<<NX4 / 256, 256>>>(x, xh, xl, NX4);
    split4_kernel<<<dim3(NW4 / 256, 4), 256>>>(Wq, Wk, Wv, Wo,
                                               wqh, wql, wkh, wkl,
                                               wvh, wvl, woh, wol);
    const int ND4 = 2047 * 64 / 4;
    split_kernel<<<(ND4 + 255) / 256, 256>>>(de, deh, del, ND4);

    gemm_mma2<2><<<dim3(H_ / 128, BS_ / 128, 3), 256, GSM_TOTAL>>>(
        xh, xl, wqh, wql, wkh, wkl, wvh, wvl, bq, bk, bv,
        qh, kh, vh, ql, kl, vl, nullptr);

    fused_attn<<<dim3(S_ / 64, BH_), 256, FSM_TOTAL>>>(
        qh, ql, kh, kl, vh, vl, deh, mask, ch, cl);

    gemm_mma2<1><<<dim3(H_ / 128, BS_ / 128, 1), 256, GSM_TOTAL>>>(
        ch, cl, woh, wol, woh, wol, woh, wol, bo, bo, bo,
        y, y, y, nullptr, nullptr, nullptr, x);

    ln_kernel<<<BS_, 256>>>(y, lng, lnb, out);
}

// round 10
// speedup vs baseline: 1.6344x; 1.1911x over previous
#include <cuda_runtime.h>
#include <cuda_bf16.h>
#include <cstdint>

#define S_   1024
#define H_   1024
#define B_   4
#define NH_  16
#define D_   64
#define BS_  4096
#define BH_  64

// ---------------- scratch (no allocs allowed) ----------------
__device__ float g_y[BS_ * H_];

__device__ __nv_bfloat16 g_xh[BS_ * H_];
__device__ __nv_bfloat16 g_wqh[H_ * H_], g_wql[H_ * H_];
__device__ __nv_bfloat16 g_wkh[H_ * H_], g_wkl[H_ * H_];
__device__ __nv_bfloat16 g_wvh[H_ * H_], g_wvl[H_ * H_];
__device__ __nv_bfloat16 g_woh[H_ * H_], g_wol[H_ * H_];
__device__ __nv_bfloat16 g_qh[BS_ * H_], g_ql[BS_ * H_];
__device__ __nv_bfloat16 g_kh[BS_ * H_], g_kl[BS_ * H_];
__device__ __nv_bfloat16 g_vh[BS_ * H_], g_vl[BS_ * H_];
__device__ __nv_bfloat16 g_deh[2047 * 64], g_del[2047 * 64];
__device__ __nv_bfloat16 g_ch[BS_ * H_];

// ---------------- helpers -------------------------------------------------------
__device__ __forceinline__ uint32_t smem_u32(const void* p)
{
    return (uint32_t)__cvta_generic_to_shared(p);
}
__device__ __forceinline__ void ldm4(uint32_t* r, uint32_t addr)
{
    asm volatile("ldmatrix.sync.aligned.m8n8.x4.shared.b16 {%0,%1,%2,%3}, [%4];"
                 : "=r"(r[0]), "=r"(r[1]), "=r"(r[2]), "=r"(r[3]) : "r"(addr));
}
__device__ __forceinline__ void ldm4t(uint32_t* r, uint32_t addr)
{
    asm volatile("ldmatrix.sync.aligned.m8n8.x4.trans.shared.b16 {%0,%1,%2,%3}, [%4];"
                 : "=r"(r[0]), "=r"(r[1]), "=r"(r[2]), "=r"(r[3]) : "r"(addr));
}
__device__ __forceinline__ void mma16816(float* c, const uint32_t* a, const uint32_t* b)
{
    asm volatile("mma.sync.aligned.m16n8k16.row.col.f32.bf16.bf16.f32 "
                 "{%0,%1,%2,%3}, {%4,%5,%6,%7}, {%8,%9}, {%0,%1,%2,%3};"
                 : "+f"(c[0]), "+f"(c[1]), "+f"(c[2]), "+f"(c[3])
                 : "r"(a[0]), "r"(a[1]), "r"(a[2]), "r"(a[3]), "r"(b[0]), "r"(b[1]));
}
__device__ __forceinline__ void cpa16(uint32_t dst, const void* src)
{
    asm volatile("cp.async.cg.shared.global [%0], [%1], 16;" :: "r"(dst), "l"(src));
}
#define CP_COMMIT() asm volatile("cp.async.commit_group;" ::: "memory")
#define CP_WAIT2()  asm volatile("cp.async.wait_group 2;" ::: "memory")
#define CP_WAIT1()  asm volatile("cp.async.wait_group 1;" ::: "memory")
#define CP_WAIT0()  asm volatile("cp.async.wait_group 0;" ::: "memory")

__device__ __forceinline__ void store_split2(__nv_bfloat16* Hp, __nv_bfloat16* Lp,
                                             size_t off, float f0, float f1)
{
    __nv_bfloat162 hp, lp;
    hp.x = __float2bfloat16(f0); hp.y = __float2bfloat16(f1);
    lp.x = __float2bfloat16(f0 - __bfloat162float(hp.x));
    lp.y = __float2bfloat16(f1 - __bfloat162float(hp.y));
    *(__nv_bfloat162*)(Hp + off) = hp;
    *(__nv_bfloat162*)(Lp + off) = lp;
}

// ---------------- fp32 -> bf16 (hi only) --------------------------------------------
__global__ void __launch_bounds__(256) conv_hi_kernel(const float* __restrict__ in,
                                                      __nv_bfloat16* __restrict__ hi,
                                                      int n4)
{
    int i = blockIdx.x * 256 + threadIdx.x;
    if (i >= n4) return;
    float4 a = ((const float4*)in)[i];
    __nv_bfloat162 h0, h1;
    h0.x = __float2bfloat16(a.x); h0.y = __float2bfloat16(a.y);
    h1.x = __float2bfloat16(a.z); h1.y = __float2bfloat16(a.w);
    ((__nv_bfloat162*)hi)[i * 2 + 0] = h0;
    ((__nv_bfloat162*)hi)[i * 2 + 1] = h1;
}

// ---------------- fp32 -> (hi,lo) bf16 split ---------------------------------------
__global__ void __launch_bounds__(256) split_kernel(const float* __restrict__ in,
                                                    __nv_bfloat16* __restrict__ hi,
                                                    __nv_bfloat16* __restrict__ lo,
                                                    int n4)
{
    int i = blockIdx.x * 256 + threadIdx.x;
    if (i >= n4) return;
    float4 a = ((const float4*)in)[i];
    __nv_bfloat16 h0 = __float2bfloat16(a.x);
    __nv_bfloat16 h1 = __float2bfloat16(a.y);
    __nv_bfloat16 h2 = __float2bfloat16(a.z);
    __nv_bfloat16 h3 = __float2bfloat16(a.w);
    __nv_bfloat162 hh0; hh0.x = h0; hh0.y = h1;
    __nv_bfloat162 hh1; hh1.x = h2; hh1.y = h3;
    ((__nv_bfloat162*)hi)[i * 2 + 0] = hh0;
    ((__nv_bfloat162*)hi)[i * 2 + 1] = hh1;
    __nv_bfloat162 ll0, ll1;
    ll0.x = __float2bfloat16(a.x - __bfloat162float(h0));
    ll0.y = __float2bfloat16(a.y - __bfloat162float(h1));
    ll1.x = __float2bfloat16(a.z - __bfloat162float(h2));
    ll1.y = __float2bfloat16(a.w - __bfloat162float(h3));
    ((__nv_bfloat162*)lo)[i * 2 + 0] = ll0;
    ((__nv_bfloat162*)lo)[i * 2 + 1] = ll1;
}

__global__ void __launch_bounds__(256) split4_kernel(
    const float* __restrict__ w0, const float* __restrict__ w1,
    const float* __restrict__ w2, const float* __restrict__ w3,
    __nv_bfloat16* __restrict__ h0, __nv_bfloat16* __restrict__ l0p,
    __nv_bfloat16* __restrict__ h1, __nv_bfloat16* __restrict__ l1p,
    __nv_bfloat16* __restrict__ h2, __nv_bfloat16* __restrict__ l2p,
    __nv_bfloat16* __restrict__ h3, __nv_bfloat16* __restrict__ l3p)
{
    const int z = blockIdx.y;
    const float* in = (z == 0) ? w0 : (z == 1) ? w1 : (z == 2) ? w2 : w3;
    __nv_bfloat16* hi = (z == 0) ? h0 : (z == 1) ? h1 : (z == 2) ? h2 : h3;
    __nv_bfloat16* lo = (z == 0) ? l0p : (z == 1) ? l1p : (z == 2) ? l2p : l3p;
    int i = blockIdx.x * 256 + threadIdx.x;
    float4 a = ((const float4*)in)[i];
    __nv_bfloat16 a0 = __float2bfloat16(a.x);
    __nv_bfloat16 a1 = __float2bfloat16(a.y);
    __nv_bfloat16 a2 = __float2bfloat16(a.z);
    __nv_bfloat16 a3 = __float2bfloat16(a.w);
    __nv_bfloat162 hh0; hh0.x = a0; hh0.y = a1;
    __nv_bfloat162 hh1; hh1.x = a2; hh1.y = a3;
    ((__nv_bfloat162*)hi)[i * 2 + 0] = hh0;
    ((__nv_bfloat162*)hi)[i * 2 + 1] = hh1;
    __nv_bfloat162 ll0, ll1;
    ll0.x = __float2bfloat16(a.x - __bfloat162float(a0));
    ll0.y = __float2bfloat16(a.y - __bfloat162float(a1));
    ll1.x = __float2bfloat16(a.z - __bfloat162float(a2));
    ll1.y = __float2bfloat16(a.w - __bfloat162float(a3));
    ((__nv_bfloat162*)lo)[i * 2 + 0] = ll0;
    ((__nv_bfloat162*)lo)[i * 2 + 1] = ll1;
}

// ---------------- 2-pass split GEMM NT via HMMA: C = Ah·(Bh+Bl) --------------------
// A hi-only; B split hi/lo. 3-stage cp.async, KT=16.
#define KT    16
#define LDS_  24                    // 48B row stride, conflict-free
#define MAT_B (128 * LDS_ * 2)      // 6144 B
#define STG_B (3 * MAT_B)           // 18432 B (Ah, Bh, Bl)
#define NSTG  3
#define GSM_TOTAL (NSTG * STG_B)    // 55296 B -> 2 CTAs/SM

template <int EPI>
__global__ void __launch_bounds__(256, 2) gemm_mma2(
    const __nv_bfloat16* __restrict__ Ah,
    const __nv_bfloat16* __restrict__ Bh0, const __nv_bfloat16* __restrict__ Bl0,
    const __nv_bfloat16* __restrict__ Bh1, const __nv_bfloat16* __restrict__ Bl1,
    const __nv_bfloat16* __restrict__ Bh2, const __nv_bfloat16* __restrict__ Bl2,
    const float* __restrict__ bias0, const float* __restrict__ bias1,
    const float* __restrict__ bias2,
    void* O0, void* O1, void* O2,
    void* L0, void* L1, void* L2,
    const float* __restrict__ resid)
{
    extern __shared__ char smem[];
    const uint32_t sb = smem_u32(smem);

    const int z = blockIdx.z;
    const __nv_bfloat16* Bh = (z == 0) ? Bh0 : (z == 1) ? Bh1 : Bh2;
    const __nv_bfloat16* Bl = (z == 0) ? Bl0 : (z == 1) ? Bl1 : Bl2;
    const float* bias = (z == 0) ? bias0 : (z == 1) ? bias1 : bias2;
    void* Ov = (z == 0) ? O0 : (z == 1) ? O1 : O2;
    void* Lv = (z == 0) ? L0 : (z == 1) ? L1 : L2;

    const int tid = threadIdx.x;
    const int lane = tid & 31, wid = tid >> 5;
    const int wm = wid >> 2, wn = wid & 3;
    const int bM = blockIdx.y * 128, bN = blockIdx.x * 128;

    float acc[4][4][4] = {};

    const int vrow = tid >> 1;
    const int vc   = tid & 1;
    const int NK = H_ / KT;   // 64

    const int q8 = lane >> 3, r8 = lane & 7;
    const int arowL = wm * 64 + (q8 & 1) * 8 + r8;
    const int browL = wn * 32 + (q8 >> 1) * 8 + r8;
    const int acolL = (q8 >> 1) * 8;
    const int bcolL = (q8 & 1) * 8;

    auto issue = [&](int kt) {
        const int st = kt % NSTG;
        const uint32_t base = sb + st * STG_B;
        const int k0 = kt * KT;
        const uint32_t d0 = (uint32_t)(vrow * (LDS_ * 2) + vc * 16);
        const size_t gA = (size_t)(bM + vrow) * H_ + k0 + vc * 8;
        const size_t gB = (size_t)(bN + vrow) * H_ + k0 + vc * 8;
        cpa16(base + 0 * MAT_B + d0, Ah + gA);
        cpa16(base + 1 * MAT_B + d0, Bh + gB);
        cpa16(base + 2 * MAT_B + d0, Bl + gB);
    };

    issue(0); CP_COMMIT();
    issue(1); CP_COMMIT();

    for (int kt = 0; kt < NK; kt++) {
        if (kt + 2 < NK) { issue(kt + 2); CP_COMMIT(); CP_WAIT2(); }
        else if (kt + 1 < NK) { CP_WAIT1(); }
        else { CP_WAIT0(); }
        __syncthreads();

        const int st = kt % NSTG;
        const uint32_t bAh = sb + st * STG_B + 0 * MAT_B;
        const uint32_t bBh = sb + st * STG_B + 1 * MAT_B;
        const uint32_t bBl = sb + st * STG_B + 2 * MAT_B;

        uint32_t afh[4][4];
#pragma unroll
        for (int mt = 0; mt < 4; mt++) {
            const uint32_t ro = (uint32_t)(((arowL + mt * 16) * LDS_ + acolL) * 2);
            ldm4(afh[mt], bAh + ro);
        }
        uint32_t bfh[2][4], bfl[2][4];
#pragma unroll
        for (int p = 0; p < 2; p++) {
            const uint32_t ro = (uint32_t)(((browL + p * 16) * LDS_ + bcolL) * 2);
            ldm4(bfh[p], bBh + ro);
            ldm4(bfl[p], bBl + ro);
        }
#pragma unroll
        for (int mt = 0; mt < 4; mt++)
#pragma unroll
            for (int nt = 0; nt < 4; nt++) {
                const uint32_t* bhp = &bfh[nt >> 1][(nt & 1) * 2];
                const uint32_t* blp = &bfl[nt >> 1][(nt & 1) * 2];
                mma16816(acc[mt][nt], afh[mt], bhp);
                mma16816(acc[mt][nt], afh[mt], blp);
            }
        __syncthreads();
    }

    const int crow0 = bM + wm * 64 + (lane >> 2);
    const int ccol0 = bN + wn * 32 + (lane & 3) * 2;
#pragma unroll
    for (int mt = 0; mt < 4; mt++) {
        const int r0 = crow0 + mt * 16;
#pragma unroll
        for (int nt = 0; nt < 4; nt++) {
            const int c0 = ccol0 + nt * 8;
            float f0 = acc[mt][nt][0] + bias[c0];
            float f1 = acc[mt][nt][1] + bias[c0 + 1];
            float f2 = acc[mt][nt][2] + bias[c0];
            float f3 = acc[mt][nt][3] + bias[c0 + 1];
            if (EPI == 1) {
                f0 += resid[(size_t)r0 * H_ + c0];
                f1 += resid[(size_t)r0 * H_ + c0 + 1];
                f2 += resid[(size_t)(r0 + 8) * H_ + c0];
                f3 += resid[(size_t)(r0 + 8) * H_ + c0 + 1];
            }
            if (EPI == 2) {
                __nv_bfloat16* OH = (__nv_bfloat16*)Ov;
                __nv_bfloat16* OL = (__nv_bfloat16*)Lv;
                store_split2(OH, OL, (size_t)r0 * H_ + c0, f0, f1);
                store_split2(OH, OL, (size_t)(r0 + 8) * H_ + c0, f2, f3);
            } else {
                float* O = (float*)Ov;
                O[(size_t)r0 * H_ + c0]           = f0;
                O[(size_t)r0 * H_ + c0 + 1]       = f1;
                O[(size_t)(r0 + 8) * H_ + c0]     = f2;
                O[(size_t)(r0 + 8) * H_ + c0 + 1] = f3;
            }
        }
    }
}

// ---------------- fused flash attention (R9 config, ctx hi-only epilogue) ----------
#define FQ    0
#define FK    18432
#define FV    36864
#define FP    55296
#define FS2B  73728               // bf16 [64][136] = 17408
#define FS3B  91136
#define FPS   73728               // probs hi @73728, lo @+9216 (overlap)
#define FRED  108544
#define FMASK 109568
#define FSM_TOTAL 113664

__global__ void __launch_bounds__(256, 2) fused_attn(
    const __nv_bfloat16* __restrict__ qh, const __nv_bfloat16* __restrict__ ql,
    const __nv_bfloat16* __restrict__ kh, const __nv_bfloat16* __restrict__ kl,
    const __nv_bfloat16* __restrict__ vh, const __nv_bfloat16* __restrict__ vl,
    const __nv_bfloat16* __restrict__ deh,
    const float* __restrict__ mask,
    __nv_bfloat16* __restrict__ ch)
{
    extern __shared__ char smem[];
    const uint32_t sb = smem_u32(smem);
    const int tid = threadIdx.x, lane = tid & 31, wid = tid >> 5;
    const int wr = wid >> 1, wc = wid & 1;
    const int l0 = blockIdx.x * 64;
    const int bh = blockIdx.y;
    const int b = bh >> 4, h = bh & 15;
    const int hcol = h * D_;

    const int q8 = lane >> 3, r8 = lane & 7;
    const int aRow = (q8 & 1) * 8 + r8, aCol = (q8 >> 1) * 8;
    const int bRow = (q8 >> 1) * 8 + r8, bCol = (q8 & 1) * 8;

    auto cp_t64 = [&](uint32_t dstbase, const __nv_bfloat16* srcH,
                      const __nv_bfloat16* srcL, int growbase) {
#pragma unroll
        for (int j = 0; j < 2; j++) {
            int v = tid + 256 * j;
            int row = v >> 3, c = v & 7;
            uint32_t d = dstbase + (uint32_t)(row * 72 + c * 8) * 2;
            cpa16(d, srcH + (size_t)(growbase + row) * H_ + hcol + c * 8);
            cpa16(d + 9216, srcL + (size_t)(growbase + row) * H_ + hcol + c * 8);
        }
    };
    auto cp_P = [&](int it) {
        const int prow0 = l0 - it * 64 + 960;
#pragma unroll
        for (int j = 0; j < 4; j++) {
            int v = tid + 256 * j;
            int row = v >> 3, c = v & 7;
            uint32_t off = (uint32_t)(row * 72 + c * 8) * 2;
            if (row < 127) {
                cpa16(sb + FP + off, deh + (size_t)(prow0 + row) * 64 + c * 8);
            } else {
                uint4 zz = {0, 0, 0, 0};
                *(uint4*)(smem + FP + off) = zz;
            }
        }
    };

    cp_t64(sb + FQ, qh, ql, b * S_ + l0);
    cp_t64(sb + FK, kh, kl, b * S_ + 0);
    cp_P(0);
    cpa16(sb + FMASK + tid * 16, mask + (size_t)b * S_ + tid * 4);
    CP_COMMIT();
    cp_t64(sb + FV, vh, vl, b * S_ + 0);
    CP_COMMIT();

    float O[4][4] = {};
    float mrunA = -1e30f, mrunB = -1e30f;
    float srunA = 0.f, srunB = 0.f;

    const int la = wr * 16 + (lane >> 2);
    __nv_bfloat16* S2b = (__nv_bfloat16*)(smem + FS2B);
    __nv_bfloat16* S3b = (__nv_bfloat16*)(smem + FS3B);
    float* redm = (float*)(smem + FRED);
    float* redsum = (float*)(smem + FRED + 512);
    const float* maskS = (const float*)(smem + FMASK);

    for (int it = 0; it < 16; it++) {
        CP_WAIT1();
        __syncthreads();

        // ---- S1 = Q @ K^T (3-pass) ----
        float accS[4][4] = {};
#pragma unroll
        for (int ks = 0; ks < 4; ks++) {
            uint32_t ah_[4], al_[4];
            ldm4(ah_, sb + FQ + (uint32_t)(((wr * 16 + aRow) * 72) + ks * 16 + aCol) * 2);
            ldm4(al_, sb + FQ + 9216 + (uint32_t)(((wr * 16 + aRow) * 72) + ks * 16 + aCol) * 2);
            uint32_t kbh[2][4], kbl[2][4];
#pragma unroll
            for (int p = 0; p < 2; p++) {
                uint32_t ro = (uint32_t)(((wc * 32 + p * 16 + bRow) * 72) + ks * 16 + bCol) * 2;
                ldm4(kbh[p], sb + FK + ro);
                ldm4(kbl[p], sb + FK + 9216 + ro);
            }
#pragma unroll
            for (int nf = 0; nf < 4; nf++) {
                const uint32_t* bhp = &kbh[nf >> 1][(nf & 1) * 2];
                const uint32_t* blp = &kbl[nf >> 1][(nf & 1) * 2];
                mma16816(accS[nf], ah_, bhp);
                mma16816(accS[nf], ah_, blp);
                mma16816(accS[nf], al_, bhp);
            }
        }

        // ---- S2 = Qh @ Ph^T (single pass) -> bf16 stage ----
        {
            float a2[4][2][4] = {};
#pragma unroll
            for (int ks = 0; ks < 4; ks++) {
                uint32_t pb[4];
                uint32_t ro = (uint32_t)(((wid * 16 + bRow) * 72) + ks * 16 + bCol) * 2;
                ldm4(pb, sb + FP + ro);
#pragma unroll
                for (int mt = 0; mt < 4; mt++) {
                    uint32_t ah_[4];
                    uint32_t ra = (uint32_t)(((mt * 16 + aRow) * 72) + ks * 16 + aCol) * 2;
                    ldm4(ah_, sb + FQ + ra);
#pragma unroll
                    for (int nf = 0; nf < 2; nf++)
                        mma16816(a2[mt][nf], ah_, &pb[nf * 2]);
                }
            }
#pragma unroll
            for (int mt = 0; mt < 4; mt++) {
                const int rr = mt * 16 + (lane >> 2);
#pragma unroll
                for (int nf = 0; nf < 2; nf++) {
                    const int cc = wid * 16 + nf * 8 + (lane & 3) * 2;
                    float2 u0; u0.x = a2[mt][nf][0]; u0.y = a2[mt][nf][1];
                    float2 u1; u1.x = a2[mt][nf][2]; u1.y = a2[mt][nf][3];
                    *(__nv_bfloat162*)&S2b[rr * 136 + cc] = __float22bfloat162_rn(u0);
                    *(__nv_bfloat162*)&S2b[(rr + 8) * 136 + cc] = __float22bfloat162_rn(u1);
                }
            }
        }
        // ---- S3 = Kh @ Ph^T (single pass) -> bf16 stage ----
        {
            float a3[4][2][4] = {};
#pragma unroll
            for (int ks = 0; ks < 4; ks++) {
                uint32_t pb[4];
                uint32_t ro = (uint32_t)(((wid * 16 + bRow) * 72) + ks * 16 + bCol) * 2;
                ldm4(pb, sb + FP + ro);
#pragma unroll
                for (int mt = 0; mt < 4; mt++) {
                    uint32_t ah_[4];
                    uint32_t ra = (uint32_t)(((mt * 16 + aRow) * 72) + ks * 16 + aCol) * 2;
                    ldm4(ah_, sb + FK + ra);
#pragma unroll
                    for (int nf = 0; nf < 2; nf++)
                        mma16816(a3[mt][nf], ah_, &pb[nf * 2]);
                }
            }
#pragma unroll
            for (int mt = 0; mt < 4; mt++) {
                const int rr = mt * 16 + (lane >> 2);
#pragma unroll
                for (int nf = 0; nf < 2; nf++) {
                    const int cc = wid * 16 + nf * 8 + (lane & 3) * 2;
                    float2 u0; u0.x = a3[mt][nf][0]; u0.y = a3[mt][nf][1];
                    float2 u1; u1.x = a3[mt][nf][2]; u1.y = a3[mt][nf][3];
                    *(__nv_bfloat162*)&S3b[rr * 136 + cc] = __float22bfloat162_rn(u0);
                    *(__nv_bfloat162*)&S3b[(rr + 8) * 136 + cc] = __float22bfloat162_rn(u1);
                }
            }
        }
        __syncthreads();

        if (it < 15) {
            cp_t64(sb + FK, kh, kl, b * S_ + (it + 1) * 64);
            cp_P(it + 1);
            CP_COMMIT();
        }

        // ---- gather + mask + scale ----
        float s[4][4];
#pragma unroll
        for (int nf = 0; nf < 4; nf++) {
            const int c0 = wc * 32 + nf * 8 + (lane & 3) * 2;
            const int t0 = la - c0 + 63;
            const float mk0 = maskS[it * 64 + c0];
            const float mk1 = maskS[it * 64 + c0 + 1];
            float s2a = __bfloat162float(S2b[la * 136 + t0]);
            float s2b_ = __bfloat162float(S2b[la * 136 + t0 - 1]);
            float s2c = __bfloat162float(S2b[(la + 8) * 136 + t0 + 8]);
            float s2d = __bfloat162float(S2b[(la + 8) * 136 + t0 + 7]);
            float s3a = __bfloat162float(S3b[c0 * 136 + t0]);
            float s3b_ = __bfloat162float(S3b[(c0 + 1) * 136 + t0 - 1]);
            float s3c = __bfloat162float(S3b[c0 * 136 + t0 + 8]);
            float s3d = __bfloat162float(S3b[(c0 + 1) * 136 + t0 + 7]);
            s[nf][0] = (accS[nf][0] + s2a + s3a) * 0.125f + mk0;
            s[nf][1] = (accS[nf][1] + s2b_ + s3b_) * 0.125f + mk1;
            s[nf][2] = (accS[nf][2] + s2c + s3c) * 0.125f + mk0;
            s[nf][3] = (accS[nf][3] + s2d + s3d) * 0.125f + mk1;
        }

        // ---- online softmax ----
        float mA = -1e30f, mB = -1e30f;
#pragma unroll
        for (int nf = 0; nf < 4; nf++) {
            mA = fmaxf(mA, fmaxf(s[nf][0], s[nf][1]));
            mB = fmaxf(mB, fmaxf(s[nf][2], s[nf][3]));
        }
        mA = fmaxf(mA, __shfl_xor_sync(~0u, mA, 1));
        mA = fmaxf(mA, __shfl_xor_sync(~0u, mA, 2));
        mB = fmaxf(mB, __shfl_xor_sync(~0u, mB, 1));
        mB = fmaxf(mB, __shfl_xor_sync(~0u, mB, 2));
        if ((lane & 3) == 0) {
            redm[wc * 64 + la] = mA;
            redm[wc * 64 + la + 8] = mB;
        }
        __syncthreads();

        mA = fmaxf(mA, redm[(wc ^ 1) * 64 + la]);
        mB = fmaxf(mB, redm[(wc ^ 1) * 64 + la + 8]);
        const float mnA = fmaxf(mrunA, mA), mnB = fmaxf(mrunB, mB);
        const float sclA = __expf(mrunA - mnA), sclB = __expf(mrunB - mnB);
        mrunA = mnA; mrunB = mnB;
#pragma unroll
        for (int nf = 0; nf < 4; nf++) {
            O[nf][0] *= sclA; O[nf][1] *= sclA;
            O[nf][2] *= sclB; O[nf][3] *= sclB;
        }

        __nv_bfloat16* PsH = (__nv_bfloat16*)(smem + FPS);
        __nv_bfloat16* PsL = (__nv_bfloat16*)(smem + FPS + 9216);
        float suA = 0.f, suB = 0.f;
#pragma unroll
        for (int nf = 0; nf < 4; nf++) {
            const int c0 = wc * 32 + nf * 8 + (lane & 3) * 2;
            float e0 = __expf(s[nf][0] - mnA), e1 = __expf(s[nf][1] - mnA);
            float e2 = __expf(s[nf][2] - mnB), e3 = __expf(s[nf][3] - mnB);
            suA += e0 + e1; suB += e2 + e3;
            store_split2(PsH, PsL, (size_t)la * 72 + c0, e0, e1);
            store_split2(PsH, PsL, (size_t)(la + 8) * 72 + c0, e2, e3);
        }
        suA += __shfl_xor_sync(~0u, suA, 1);
        suA += __shfl_xor_sync(~0u, suA, 2);
        suB += __shfl_xor_sync(~0u, suB, 1);
        suB += __shfl_xor_sync(~0u, suB, 2);
        if ((lane & 3) == 0) {
            redsum[wc * 64 + la] = suA;
            redsum[wc * 64 + la + 8] = suB;
        }
        if (it < 15) { CP_WAIT1(); } else { CP_WAIT0(); }
        __syncthreads();

        suA += redsum[(wc ^ 1) * 64 + la];
        suB += redsum[(wc ^ 1) * 64 + la + 8];
        srunA = srunA * sclA + suA;
        srunB = srunB * sclB + suB;

        // ---- O += P @ V (3-pass) ----
#pragma unroll
        for (int ks = 0; ks < 4; ks++) {
            uint32_t pah[4], pal[4];
            uint32_t ra = (uint32_t)(((wr * 16 + aRow) * 72) + ks * 16 + aCol) * 2;
            ldm4(pah, sb + FPS + ra);
            ldm4(pal, sb + FPS + 9216 + ra);
            uint32_t vbh[2][4], vbl[2][4];
#pragma unroll
            for (int p = 0; p < 2; p++) {
                uint32_t ro = (uint32_t)(((ks * 16 + aRow) * 72) + wc * 32 + p * 16 + aCol) * 2;
                ldm4t(vbh[p], sb + FV + ro);
                ldm4t(vbl[p], sb + FV + 9216 + ro);
            }
#pragma unroll
            for (int nf = 0; nf < 4; nf++) {
                const uint32_t* bhp = &vbh[nf >> 1][(nf & 1) * 2];
                const uint32_t* blp = &vbl[nf >> 1][(nf & 1) * 2];
                mma16816(O[nf], pah, bhp);
                mma16816(O[nf], pah, blp);
                mma16816(O[nf], pal, bhp);
            }
        }
        __syncthreads();

        if (it < 15) {
            cp_t64(sb + FV, vh, vl, b * S_ + (it + 1) * 64);
            CP_COMMIT();
        }
    }

    // ---- epilogue: ctx hi-only ----
    const float iA = 1.f / srunA, iB = 1.f / srunB;
#pragma unroll
    for (int nf = 0; nf < 4; nf++) {
        const int col = hcol + wc * 32 + nf * 8 + (lane & 3) * 2;
        const size_t rowA = (size_t)(b * S_ + l0 + la) * H_ + col;
        const size_t rowB = (size_t)(b * S_ + l0 + la + 8) * H_ + col;
        __nv_bfloat162 cA, cB;
        cA.x = __float2bfloat16(O[nf][0] * iA); cA.y = __float2bfloat16(O[nf][1] * iA);
        cB.x = __float2bfloat16(O[nf][2] * iB); cB.y = __float2bfloat16(O[nf][3] * iB);
        *(__nv_bfloat162*)(ch + rowA) = cA;
        *(__nv_bfloat162*)(ch + rowB) = cB;
    }
}

// ---------------- LayerNorm ----------------------------------------------------------
__global__ void __launch_bounds__(256) ln_kernel(const float* __restrict__ y,
                                                 const float* __restrict__ g,
                                                 const float* __restrict__ bb,
                                                 float* __restrict__ out)
{
    __shared__ float sred[8];
    __shared__ float sbc;
    const size_t row = blockIdx.x;
    const int tid = threadIdx.x;
    const int lane = tid & 31, wid = tid >> 5;

    float4 v = ((const float4*)(y + row * H_))[tid];

    float s = v.x + v.y + v.z + v.w;
#pragma unroll
    for (int o = 16; o > 0; o >>= 1) s += __shfl_xor_sync(~0u, s, o);
    if (lane == 0) sred[wid] = s;
    __syncthreads();
    if (tid == 0) {
        float t = 0.f;
#pragma unroll
        for (int i = 0; i < 8; i++) t += sred[i];
        sbc = t;
    }
    __syncthreads();
    const float mu = sbc * (1.f / H_);

    float dx = v.x - mu, dy = v.y - mu, dz = v.z - mu, dw = v.w - mu;
    float qq = dx * dx + dy * dy + dz * dz + dw * dw;
#pragma unroll
    for (int o = 16; o > 0; o >>= 1) qq += __shfl_xor_sync(~0u, qq, o);
    if (lane == 0) sred[wid] = qq;
    __syncthreads();
    if (tid == 0) {
        float t = 0.f;
#pragma unroll
        for (int i = 0; i < 8; i++) t += sred[i];
        sbc = t;
    }
    __syncthreads();
    const float rstd = rsqrtf(sbc * (1.f / H_) + 1e-12f);

    float4 gg = ((const float4*)g)[tid];
    float4 bt = ((const float4*)bb)[tid];
    float4 o;
    o.x = dx * rstd * gg.x + bt.x;
    o.y = dy * rstd * gg.y + bt.y;
    o.z = dz * rstd * gg.z + bt.z;
    o.w = dw * rstd * gg.w + bt.w;
    ((float4*)(out + row * H_))[tid] = o;
}

// ---------------- launch -----------------------------------------------------------
extern "C" void kernel_launch(void* const* d_in, const int* in_sizes, int n_in,
                              void* d_out, int out_size)
{
    (void)in_sizes; (void)n_in; (void)out_size;
    const float* x    = (const float*)d_in[0];
    const float* mask = (const float*)d_in[1];
    const float* Wq   = (const float*)d_in[2];
    const float* bq   = (const float*)d_in[3];
    const float* Wk   = (const float*)d_in[4];
    const float* bk   = (const float*)d_in[5];
    const float* Wv   = (const float*)d_in[6];
    const float* bv   = (const float*)d_in[7];
    const float* de   = (const float*)d_in[8];
    const float* Wo   = (const float*)d_in[9];
    const float* bo   = (const float*)d_in[10];
    const float* lng  = (const float*)d_in[11];
    const float* lnb  = (const float*)d_in[12];
    float* out = (float*)d_out;

    float* y;
    cudaGetSymbolAddress((void**)&y, g_y);

    __nv_bfloat16 *xh, *wqh, *wql, *wkh, *wkl, *wvh, *wvl, *woh, *wol;
    __nv_bfloat16 *qh, *ql, *kh, *kl, *vh, *vl, *deh, *del, *ch;
    cudaGetSymbolAddress((void**)&xh, g_xh);
    cudaGetSymbolAddress((void**)&wqh, g_wqh); cudaGetSymbolAddress((void**)&wql, g_wql);
    cudaGetSymbolAddress((void**)&wkh, g_wkh); cudaGetSymbolAddress((void**)&wkl, g_wkl);
    cudaGetSymbolAddress((void**)&wvh, g_wvh); cudaGetSymbolAddress((void**)&wvl, g_wvl);
    cudaGetSymbolAddress((void**)&woh, g_woh); cudaGetSymbolAddress((void**)&wol, g_wol);
    cudaGetSymbolAddress((void**)&qh, g_qh);   cudaGetSymbolAddress((void**)&ql, g_ql);
    cudaGetSymbolAddress((void**)&kh, g_kh);   cudaGetSymbolAddress((void**)&kl, g_kl);
    cudaGetSymbolAddress((void**)&vh, g_vh);   cudaGetSymbolAddress((void**)&vl, g_vl);
    cudaGetSymbolAddress((void**)&deh, g_deh); cudaGetSymbolAddress((void**)&del, g_del);
    cudaGetSymbolAddress((void**)&ch, g_ch);

    cudaFuncSetAttribute(gemm_mma2<1>, cudaFuncAttributeMaxDynamicSharedMemorySize, GSM_TOTAL);
    cudaFuncSetAttribute(gemm_mma2<2>, cudaFuncAttributeMaxDynamicSharedMemorySize, GSM_TOTAL);
    cudaFuncSetAttribute(fused_attn, cudaFuncAttributeMaxDynamicSharedMemorySize, FSM_TOTAL);

    const int NX4 = BS_ * H_ / 4;
    const int NW4 = H_ * H_ / 4;
    conv_hi_kernel<<<NX4 / 256, 256>>>(x, xh, NX4);
    split4_kernel<<<dim3(NW4 / 256, 4), 256>>>(Wq, Wk, Wv, Wo,
                                               wqh, wql, wkh, wkl,
                                               wvh, wvl, woh, wol);
    const int ND4 = 2047 * 64 / 4;
    split_kernel<<<(ND4 + 255) / 256, 256>>>(de, deh, del, ND4);

    gemm_mma2<2><<<dim3(H_ / 128, BS_ / 128, 3), 256, GSM_TOTAL>>>(
        xh, wqh, wql, wkh, wkl, wvh, wvl, bq, bk, bv,
        qh, kh, vh, ql, kl, vl, nullptr);

    fused_attn<<<dim3(S_ / 64, BH_), 256, FSM_TOTAL>>>(
        qh, ql, kh, kl, vh, vl, deh, mask, ch);

    gemm_mma2<1><<<dim3(H_ / 128, BS_ / 128, 1), 256, GSM_TOTAL>>>(
        ch, woh, wol, woh, wol, woh, wol, bo, bo, bo,
        y, y, y, nullptr, nullptr, nullptr, x);

    ln_kernel<<<BS_, 256>>>(y, lng, lnb, out);
}

// round 11
// speedup vs baseline: 1.9069x; 1.1667x over previous
#include <cuda_runtime.h>
#include <cuda_bf16.h>
#include <cstdint>

#define S_   1024
#define H_   1024
#define B_   4
#define NH_  16
#define D_   64
#define BS_  4096
#define BH_  64

// ---------------- scratch (no allocs allowed) ----------------
__device__ float g_y[BS_ * H_];

__device__ __nv_bfloat16 g_xh[BS_ * H_];
__device__ __nv_bfloat16 g_wqh[H_ * H_], g_wql[H_ * H_];
__device__ __nv_bfloat16 g_wkh[H_ * H_], g_wkl[H_ * H_];
__device__ __nv_bfloat16 g_wvh[H_ * H_], g_wvl[H_ * H_];
__device__ __nv_bfloat16 g_woh[H_ * H_], g_wol[H_ * H_];
__device__ __nv_bfloat16 g_qh[BS_ * H_], g_ql[BS_ * H_];
__device__ __nv_bfloat16 g_kh[BS_ * H_], g_kl[BS_ * H_];
__device__ __nv_bfloat16 g_vh[BS_ * H_], g_vl[BS_ * H_];
__device__ __nv_bfloat16 g_deh[2047 * 64], g_del[2047 * 64];
__device__ __nv_bfloat16 g_ch[BS_ * H_];

// ---------------- helpers -------------------------------------------------------
__device__ __forceinline__ uint32_t smem_u32(const void* p)
{
    return (uint32_t)__cvta_generic_to_shared(p);
}
__device__ __forceinline__ void ldm4(uint32_t* r, uint32_t addr)
{
    asm volatile("ldmatrix.sync.aligned.m8n8.x4.shared.b16 {%0,%1,%2,%3}, [%4];"
                 : "=r"(r[0]), "=r"(r[1]), "=r"(r[2]), "=r"(r[3]) : "r"(addr));
}
__device__ __forceinline__ void ldm4t(uint32_t* r, uint32_t addr)
{
    asm volatile("ldmatrix.sync.aligned.m8n8.x4.trans.shared.b16 {%0,%1,%2,%3}, [%4];"
                 : "=r"(r[0]), "=r"(r[1]), "=r"(r[2]), "=r"(r[3]) : "r"(addr));
}
__device__ __forceinline__ void mma16816(float* c, const uint32_t* a, const uint32_t* b)
{
    asm volatile("mma.sync.aligned.m16n8k16.row.col.f32.bf16.bf16.f32 "
                 "{%0,%1,%2,%3}, {%4,%5,%6,%7}, {%8,%9}, {%0,%1,%2,%3};"
                 : "+f"(c[0]), "+f"(c[1]), "+f"(c[2]), "+f"(c[3])
                 : "r"(a[0]), "r"(a[1]), "r"(a[2]), "r"(a[3]), "r"(b[0]), "r"(b[1]));
}
__device__ __forceinline__ void cpa16(uint32_t dst, const void* src)
{
    asm volatile("cp.async.cg.shared.global [%0], [%1], 16;" :: "r"(dst), "l"(src));
}
#define CP_COMMIT() asm volatile("cp.async.commit_group;" ::: "memory")
#define CP_WAIT1()  asm volatile("cp.async.wait_group 1;" ::: "memory")
#define CP_WAIT0()  asm volatile("cp.async.wait_group 0;" ::: "memory")

__device__ __forceinline__ void store_split2(__nv_bfloat16* Hp, __nv_bfloat16* Lp,
                                             size_t off, float f0, float f1)
{
    __nv_bfloat162 hp, lp;
    hp.x = __float2bfloat16(f0); hp.y = __float2bfloat16(f1);
    lp.x = __float2bfloat16(f0 - __bfloat162float(hp.x));
    lp.y = __float2bfloat16(f1 - __bfloat162float(hp.y));
    *(__nv_bfloat162*)(Hp + off) = hp;
    *(__nv_bfloat162*)(Lp + off) = lp;
}

// ---------------- fp32 -> bf16 (hi only) --------------------------------------------
__global__ void __launch_bounds__(256) conv_hi_kernel(const float* __restrict__ in,
                                                      __nv_bfloat16* __restrict__ hi,
                                                      int n4)
{
    int i = blockIdx.x * 256 + threadIdx.x;
    if (i >= n4) return;
    float4 a = ((const float4*)in)[i];
    __nv_bfloat162 h0, h1;
    h0.x = __float2bfloat16(a.x); h0.y = __float2bfloat16(a.y);
    h1.x = __float2bfloat16(a.z); h1.y = __float2bfloat16(a.w);
    ((__nv_bfloat162*)hi)[i * 2 + 0] = h0;
    ((__nv_bfloat162*)hi)[i * 2 + 1] = h1;
}

// ---------------- fp32 -> (hi,lo) bf16 split ---------------------------------------
__global__ void __launch_bounds__(256) split_kernel(const float* __restrict__ in,
                                                    __nv_bfloat16* __restrict__ hi,
                                                    __nv_bfloat16* __restrict__ lo,
                                                    int n4)
{
    int i = blockIdx.x * 256 + threadIdx.x;
    if (i >= n4) return;
    float4 a = ((const float4*)in)[i];
    __nv_bfloat16 h0 = __float2bfloat16(a.x);
    __nv_bfloat16 h1 = __float2bfloat16(a.y);
    __nv_bfloat16 h2 = __float2bfloat16(a.z);
    __nv_bfloat16 h3 = __float2bfloat16(a.w);
    __nv_bfloat162 hh0; hh0.x = h0; hh0.y = h1;
    __nv_bfloat162 hh1; hh1.x = h2; hh1.y = h3;
    ((__nv_bfloat162*)hi)[i * 2 + 0] = hh0;
    ((__nv_bfloat162*)hi)[i * 2 + 1] = hh1;
    __nv_bfloat162 ll0, ll1;
    ll0.x = __float2bfloat16(a.x - __bfloat162float(h0));
    ll0.y = __float2bfloat16(a.y - __bfloat162float(h1));
    ll1.x = __float2bfloat16(a.z - __bfloat162float(h2));
    ll1.y = __float2bfloat16(a.w - __bfloat162float(h3));
    ((__nv_bfloat162*)lo)[i * 2 + 0] = ll0;
    ((__nv_bfloat162*)lo)[i * 2 + 1] = ll1;
}

__global__ void __launch_bounds__(256) split4_kernel(
    const float* __restrict__ w0, const float* __restrict__ w1,
    const float* __restrict__ w2, const float* __restrict__ w3,
    __nv_bfloat16* __restrict__ h0, __nv_bfloat16* __restrict__ l0p,
    __nv_bfloat16* __restrict__ h1, __nv_bfloat16* __restrict__ l1p,
    __nv_bfloat16* __restrict__ h2, __nv_bfloat16* __restrict__ l2p,
    __nv_bfloat16* __restrict__ h3, __nv_bfloat16* __restrict__ l3p)
{
    const int z = blockIdx.y;
    const float* in = (z == 0) ? w0 : (z == 1) ? w1 : (z == 2) ? w2 : w3;
    __nv_bfloat16* hi = (z == 0) ? h0 : (z == 1) ? h1 : (z == 2) ? h2 : h3;
    __nv_bfloat16* lo = (z == 0) ? l0p : (z == 1) ? l1p : (z == 2) ? l2p : l3p;
    int i = blockIdx.x * 256 + threadIdx.x;
    float4 a = ((const float4*)in)[i];
    __nv_bfloat16 a0 = __float2bfloat16(a.x);
    __nv_bfloat16 a1 = __float2bfloat16(a.y);
    __nv_bfloat16 a2 = __float2bfloat16(a.z);
    __nv_bfloat16 a3 = __float2bfloat16(a.w);
    __nv_bfloat162 hh0; hh0.x = a0; hh0.y = a1;
    __nv_bfloat162 hh1; hh1.x = a2; hh1.y = a3;
    ((__nv_bfloat162*)hi)[i * 2 + 0] = hh0;
    ((__nv_bfloat162*)hi)[i * 2 + 1] = hh1;
    __nv_bfloat162 ll0, ll1;
    ll0.x = __float2bfloat16(a.x - __bfloat162float(a0));
    ll0.y = __float2bfloat16(a.y - __bfloat162float(a1));
    ll1.x = __float2bfloat16(a.z - __bfloat162float(a2));
    ll1.y = __float2bfloat16(a.w - __bfloat162float(a3));
    ((__nv_bfloat162*)lo)[i * 2 + 0] = ll0;
    ((__nv_bfloat162*)lo)[i * 2 + 1] = ll1;
}

// ---------------- 2-pass split GEMM NT via HMMA: C = Ah·(Bh+Bl) --------------------
// single __syncthreads per kt: wait1 -> sync -> issue(kt+2) -> compute
#define KT    16
#define LDS_  24
#define MAT_B (128 * LDS_ * 2)
#define STG_B (3 * MAT_B)
#define NSTG  3
#define GSM_TOTAL (NSTG * STG_B)    // 55296 B -> 2 CTAs/SM

template <int EPI>
__global__ void __launch_bounds__(256, 2) gemm_mma2(
    const __nv_bfloat16* __restrict__ Ah,
    const __nv_bfloat16* __restrict__ Bh0, const __nv_bfloat16* __restrict__ Bl0,
    const __nv_bfloat16* __restrict__ Bh1, const __nv_bfloat16* __restrict__ Bl1,
    const __nv_bfloat16* __restrict__ Bh2, const __nv_bfloat16* __restrict__ Bl2,
    const float* __restrict__ bias0, const float* __restrict__ bias1,
    const float* __restrict__ bias2,
    void* O0, void* O1, void* O2,
    void* L0, void* L1, void* L2,
    const float* __restrict__ resid)
{
    extern __shared__ char smem[];
    const uint32_t sb = smem_u32(smem);

    const int z = blockIdx.z;
    const __nv_bfloat16* Bh = (z == 0) ? Bh0 : (z == 1) ? Bh1 : Bh2;
    const __nv_bfloat16* Bl = (z == 0) ? Bl0 : (z == 1) ? Bl1 : Bl2;
    const float* bias = (z == 0) ? bias0 : (z == 1) ? bias1 : bias2;
    void* Ov = (z == 0) ? O0 : (z == 1) ? O1 : O2;
    void* Lv = (z == 0) ? L0 : (z == 1) ? L1 : L2;

    const int tid = threadIdx.x;
    const int lane = tid & 31, wid = tid >> 5;
    const int wm = wid >> 2, wn = wid & 3;
    const int bM = blockIdx.y * 128, bN = blockIdx.x * 128;

    float acc[4][4][4] = {};

    const int vrow = tid >> 1;
    const int vc   = tid & 1;
    const int NK = H_ / KT;   // 64

    const int q8 = lane >> 3, r8 = lane & 7;
    const int arowL = wm * 64 + (q8 & 1) * 8 + r8;
    const int browL = wn * 32 + (q8 >> 1) * 8 + r8;
    const int acolL = (q8 >> 1) * 8;
    const int bcolL = (q8 & 1) * 8;

    auto issue = [&](int kt) {
        const int st = kt % NSTG;
        const uint32_t base = sb + st * STG_B;
        const int k0 = kt * KT;
        const uint32_t d0 = (uint32_t)(vrow * (LDS_ * 2) + vc * 16);
        const size_t gA = (size_t)(bM + vrow) * H_ + k0 + vc * 8;
        const size_t gB = (size_t)(bN + vrow) * H_ + k0 + vc * 8;
        cpa16(base + 0 * MAT_B + d0, Ah + gA);
        cpa16(base + 1 * MAT_B + d0, Bh + gB);
        cpa16(base + 2 * MAT_B + d0, Bl + gB);
    };

    issue(0); CP_COMMIT();
    issue(1); CP_COMMIT();

    for (int kt = 0; kt < NK; kt++) {
        if (kt + 1 < NK) { CP_WAIT1(); } else { CP_WAIT0(); }
        __syncthreads();
        if (kt + 2 < NK) { issue(kt + 2); CP_COMMIT(); }

        const int st = kt % NSTG;
        const uint32_t bAh = sb + st * STG_B + 0 * MAT_B;
        const uint32_t bBh = sb + st * STG_B + 1 * MAT_B;
        const uint32_t bBl = sb + st * STG_B + 2 * MAT_B;

        uint32_t afh[4][4];
#pragma unroll
        for (int mt = 0; mt < 4; mt++) {
            const uint32_t ro = (uint32_t)(((arowL + mt * 16) * LDS_ + acolL) * 2);
            ldm4(afh[mt], bAh + ro);
        }
        uint32_t bfh[2][4], bfl[2][4];
#pragma unroll
        for (int p = 0; p < 2; p++) {
            const uint32_t ro = (uint32_t)(((browL + p * 16) * LDS_ + bcolL) * 2);
            ldm4(bfh[p], bBh + ro);
            ldm4(bfl[p], bBl + ro);
        }
#pragma unroll
        for (int mt = 0; mt < 4; mt++)
#pragma unroll
            for (int nt = 0; nt < 4; nt++) {
                const uint32_t* bhp = &bfh[nt >> 1][(nt & 1) * 2];
                const uint32_t* blp = &bfl[nt >> 1][(nt & 1) * 2];
                mma16816(acc[mt][nt], afh[mt], bhp);
                mma16816(acc[mt][nt], afh[mt], blp);
            }
    }

    const int crow0 = bM + wm * 64 + (lane >> 2);
    const int ccol0 = bN + wn * 32 + (lane & 3) * 2;
#pragma unroll
    for (int mt = 0; mt < 4; mt++) {
        const int r0 = crow0 + mt * 16;
#pragma unroll
        for (int nt = 0; nt < 4; nt++) {
            const int c0 = ccol0 + nt * 8;
            float f0 = acc[mt][nt][0] + bias[c0];
            float f1 = acc[mt][nt][1] + bias[c0 + 1];
            float f2 = acc[mt][nt][2] + bias[c0];
            float f3 = acc[mt][nt][3] + bias[c0 + 1];
            if (EPI == 1) {
                f0 += resid[(size_t)r0 * H_ + c0];
                f1 += resid[(size_t)r0 * H_ + c0 + 1];
                f2 += resid[(size_t)(r0 + 8) * H_ + c0];
                f3 += resid[(size_t)(r0 + 8) * H_ + c0 + 1];
            }
            if (EPI == 2) {
                __nv_bfloat16* OH = (__nv_bfloat16*)Ov;
                __nv_bfloat16* OL = (__nv_bfloat16*)Lv;
                store_split2(OH, OL, (size_t)r0 * H_ + c0, f0, f1);
                store_split2(OH, OL, (size_t)(r0 + 8) * H_ + c0, f2, f3);
            } else {
                float* O = (float*)Ov;
                O[(size_t)r0 * H_ + c0]           = f0;
                O[(size_t)r0 * H_ + c0 + 1]       = f1;
                O[(size_t)(r0 + 8) * H_ + c0]     = f2;
                O[(size_t)(r0 + 8) * H_ + c0 + 1] = f3;
            }
        }
    }
}

// ---------------- fused flash attention: 2-pass S1/PV, Q hi-only, probs hi-only ----
#define FQ    0                    // qh 9216
#define FK    9216                 // kh 9216 + kl 9216
#define FV    27648                // vh 9216 + vl 9216
#define FP    46080                // dist hi, 128x72x2 = 18432
#define FS2B  64512                // bf16 [64][136] = 17408
#define FS3B  81920                // bf16 [64][136] = 17408
#define FPS   64512                // probs hi only (overlap FS2B, post-gather) 9216
#define FRED  99328                // redm [2][64] f32, redsum [2][64] f32
#define FMASK 100352               // 1024 f32
#define FSM_TOTAL 104448

__global__ void __launch_bounds__(256, 2) fused_attn(
    const __nv_bfloat16* __restrict__ qh,
    const __nv_bfloat16* __restrict__ kh, const __nv_bfloat16* __restrict__ kl,
    const __nv_bfloat16* __restrict__ vh, const __nv_bfloat16* __restrict__ vl,
    const __nv_bfloat16* __restrict__ deh,
    const float* __restrict__ mask,
    __nv_bfloat16* __restrict__ ch)
{
    extern __shared__ char smem[];
    const uint32_t sb = smem_u32(smem);
    const int tid = threadIdx.x, lane = tid & 31, wid = tid >> 5;
    const int wr = wid >> 1, wc = wid & 1;
    const int l0 = blockIdx.x * 64;
    const int bh = blockIdx.y;
    const int b = bh >> 4, h = bh & 15;
    const int hcol = h * D_;

    const int q8 = lane >> 3, r8 = lane & 7;
    const int aRow = (q8 & 1) * 8 + r8, aCol = (q8 >> 1) * 8;
    const int bRow = (q8 >> 1) * 8 + r8, bCol = (q8 & 1) * 8;

    auto cp_t64 = [&](uint32_t dstbase, const __nv_bfloat16* srcH,
                      const __nv_bfloat16* srcL, int growbase) {
#pragma unroll
        for (int j = 0; j < 2; j++) {
            int v = tid + 256 * j;
            int row = v >> 3, c = v & 7;
            uint32_t d = dstbase + (uint32_t)(row * 72 + c * 8) * 2;
            cpa16(d, srcH + (size_t)(growbase + row) * H_ + hcol + c * 8);
            cpa16(d + 9216, srcL + (size_t)(growbase + row) * H_ + hcol + c * 8);
        }
    };
    auto cp_P = [&](int it) {
        const int prow0 = l0 - it * 64 + 960;
#pragma unroll
        for (int j = 0; j < 4; j++) {
            int v = tid + 256 * j;
            int row = v >> 3, c = v & 7;
            uint32_t off = (uint32_t)(row * 72 + c * 8) * 2;
            if (row < 127) {
                cpa16(sb + FP + off, deh + (size_t)(prow0 + row) * 64 + c * 8);
            } else {
                uint4 zz = {0, 0, 0, 0};
                *(uint4*)(smem + FP + off) = zz;
            }
        }
    };

    // prologue: group0 = {Qh, K0, P0, mask}, group1 = {V0}
    {
        int v = tid * 2;
        int row = v >> 4;           // 64 rows, 8 vec16 per row... (tid*2: 512 vec)
        // simpler: 2 vec per thread over 512 vec total
#pragma unroll
        for (int j = 0; j < 2; j++) {
            int vv = tid + 256 * j;
            int rr = vv >> 3, cc = vv & 7;
            if (vv < 512)
                cpa16(sb + FQ + (uint32_t)(rr * 72 + cc * 8) * 2,
                      qh + (size_t)(b * S_ + l0 + rr) * H_ + hcol + cc * 8);
        }
        (void)row; (void)v;
    }
    cp_t64(sb + FK, kh, kl, b * S_ + 0);
    cp_P(0);
    cpa16(sb + FMASK + tid * 16, mask + (size_t)b * S_ + tid * 4);
    CP_COMMIT();
    cp_t64(sb + FV, vh, vl, b * S_ + 0);
    CP_COMMIT();

    float O[4][4] = {};
    float mrunA = -1e30f, mrunB = -1e30f;
    float srunA = 0.f, srunB = 0.f;

    const int la = wr * 16 + (lane >> 2);
    __nv_bfloat16* S2b = (__nv_bfloat16*)(smem + FS2B);
    __nv_bfloat16* S3b = (__nv_bfloat16*)(smem + FS3B);
    float* redm = (float*)(smem + FRED);
    float* redsum = (float*)(smem + FRED + 512);
    const float* maskS = (const float*)(smem + FMASK);

    for (int it = 0; it < 16; it++) {
        CP_WAIT1();
        __syncthreads();

        // ---- S1 = Qh @ (Kh+Kl)^T (2-pass) ----
        float accS[4][4] = {};
#pragma unroll
        for (int ks = 0; ks < 4; ks++) {
            uint32_t ah_[4];
            ldm4(ah_, sb + FQ + (uint32_t)(((wr * 16 + aRow) * 72) + ks * 16 + aCol) * 2);
            uint32_t kbh[2][4], kbl[2][4];
#pragma unroll
            for (int p = 0; p < 2; p++) {
                uint32_t ro = (uint32_t)(((wc * 32 + p * 16 + bRow) * 72) + ks * 16 + bCol) * 2;
                ldm4(kbh[p], sb + FK + ro);
                ldm4(kbl[p], sb + FK + 9216 + ro);
            }
#pragma unroll
            for (int nf = 0; nf < 4; nf++) {
                const uint32_t* bhp = &kbh[nf >> 1][(nf & 1) * 2];
                const uint32_t* blp = &kbl[nf >> 1][(nf & 1) * 2];
                mma16816(accS[nf], ah_, bhp);
                mma16816(accS[nf], ah_, blp);
            }
        }

        // ---- S2 = Qh @ Ph^T (single pass) -> bf16 stage ----
        {
            float a2[4][2][4] = {};
#pragma unroll
            for (int ks = 0; ks < 4; ks++) {
                uint32_t pb[4];
                uint32_t ro = (uint32_t)(((wid * 16 + bRow) * 72) + ks * 16 + bCol) * 2;
                ldm4(pb, sb + FP + ro);
#pragma unroll
                for (int mt = 0; mt < 4; mt++) {
                    uint32_t ah_[4];
                    uint32_t ra = (uint32_t)(((mt * 16 + aRow) * 72) + ks * 16 + aCol) * 2;
                    ldm4(ah_, sb + FQ + ra);
#pragma unroll
                    for (int nf = 0; nf < 2; nf++)
                        mma16816(a2[mt][nf], ah_, &pb[nf * 2]);
                }
            }
#pragma unroll
            for (int mt = 0; mt < 4; mt++) {
                const int rr = mt * 16 + (lane >> 2);
#pragma unroll
                for (int nf = 0; nf < 2; nf++) {
                    const int cc = wid * 16 + nf * 8 + (lane & 3) * 2;
                    float2 u0; u0.x = a2[mt][nf][0]; u0.y = a2[mt][nf][1];
                    float2 u1; u1.x = a2[mt][nf][2]; u1.y = a2[mt][nf][3];
                    *(__nv_bfloat162*)&S2b[rr * 136 + cc] = __float22bfloat162_rn(u0);
                    *(__nv_bfloat162*)&S2b[(rr + 8) * 136 + cc] = __float22bfloat162_rn(u1);
                }
            }
        }
        // ---- S3 = Kh @ Ph^T (single pass) -> bf16 stage ----
        {
            float a3[4][2][4] = {};
#pragma unroll
            for (int ks = 0; ks < 4; ks++) {
                uint32_t pb[4];
                uint32_t ro = (uint32_t)(((wid * 16 + bRow) * 72) + ks * 16 + bCol) * 2;
                ldm4(pb, sb + FP + ro);
#pragma unroll
                for (int mt = 0; mt < 4; mt++) {
                    uint32_t ah_[4];
                    uint32_t ra = (uint32_t)(((mt * 16 + aRow) * 72) + ks * 16 + aCol) * 2;
                    ldm4(ah_, sb + FK + ra);
#pragma unroll
                    for (int nf = 0; nf < 2; nf++)
                        mma16816(a3[mt][nf], ah_, &pb[nf * 2]);
                }
            }
#pragma unroll
            for (int mt = 0; mt < 4; mt++) {
                const int rr = mt * 16 + (lane >> 2);
#pragma unroll
                for (int nf = 0; nf < 2; nf++) {
                    const int cc = wid * 16 + nf * 8 + (lane & 3) * 2;
                    float2 u0; u0.x = a3[mt][nf][0]; u0.y = a3[mt][nf][1];
                    float2 u1; u1.x = a3[mt][nf][2]; u1.y = a3[mt][nf][3];
                    *(__nv_bfloat162*)&S3b[rr * 136 + cc] = __float22bfloat162_rn(u0);
                    *(__nv_bfloat162*)&S3b[(rr + 8) * 136 + cc] = __float22bfloat162_rn(u1);
                }
            }
        }
        __syncthreads();

        if (it < 15) {
            cp_t64(sb + FK, kh, kl, b * S_ + (it + 1) * 64);
            cp_P(it + 1);
            CP_COMMIT();
        }

        // ---- gather + mask + scale ----
        float s[4][4];
#pragma unroll
        for (int nf = 0; nf < 4; nf++) {
            const int c0 = wc * 32 + nf * 8 + (lane & 3) * 2;
            const int t0 = la - c0 + 63;
            const float mk0 = maskS[it * 64 + c0];
            const float mk1 = maskS[it * 64 + c0 + 1];
            float s2a = __bfloat162float(S2b[la * 136 + t0]);
            float s2b_ = __bfloat162float(S2b[la * 136 + t0 - 1]);
            float s2c = __bfloat162float(S2b[(la + 8) * 136 + t0 + 8]);
            float s2d = __bfloat162float(S2b[(la + 8) * 136 + t0 + 7]);
            float s3a = __bfloat162float(S3b[c0 * 136 + t0]);
            float s3b_ = __bfloat162float(S3b[(c0 + 1) * 136 + t0 - 1]);
            float s3c = __bfloat162float(S3b[c0 * 136 + t0 + 8]);
            float s3d = __bfloat162float(S3b[(c0 + 1) * 136 + t0 + 7]);
            s[nf][0] = (accS[nf][0] + s2a + s3a) * 0.125f + mk0;
            s[nf][1] = (accS[nf][1] + s2b_ + s3b_) * 0.125f + mk1;
            s[nf][2] = (accS[nf][2] + s2c + s3c) * 0.125f + mk0;
            s[nf][3] = (accS[nf][3] + s2d + s3d) * 0.125f + mk1;
        }

        // ---- online softmax ----
        float mA = -1e30f, mB = -1e30f;
#pragma unroll
        for (int nf = 0; nf < 4; nf++) {
            mA = fmaxf(mA, fmaxf(s[nf][0], s[nf][1]));
            mB = fmaxf(mB, fmaxf(s[nf][2], s[nf][3]));
        }
        mA = fmaxf(mA, __shfl_xor_sync(~0u, mA, 1));
        mA = fmaxf(mA, __shfl_xor_sync(~0u, mA, 2));
        mB = fmaxf(mB, __shfl_xor_sync(~0u, mB, 1));
        mB = fmaxf(mB, __shfl_xor_sync(~0u, mB, 2));
        if ((lane & 3) == 0) {
            redm[wc * 64 + la] = mA;
            redm[wc * 64 + la + 8] = mB;
        }
        __syncthreads();

        mA = fmaxf(mA, redm[(wc ^ 1) * 64 + la]);
        mB = fmaxf(mB, redm[(wc ^ 1) * 64 + la + 8]);
        const float mnA = fmaxf(mrunA, mA), mnB = fmaxf(mrunB, mB);
        const float sclA = __expf(mrunA - mnA), sclB = __expf(mrunB - mnB);
        mrunA = mnA; mrunB = mnB;
#pragma unroll
        for (int nf = 0; nf < 4; nf++) {
            O[nf][0] *= sclA; O[nf][1] *= sclA;
            O[nf][2] *= sclB; O[nf][3] *= sclB;
        }

        __nv_bfloat16* PsH = (__nv_bfloat16*)(smem + FPS);
        float suA = 0.f, suB = 0.f;
#pragma unroll
        for (int nf = 0; nf < 4; nf++) {
            const int c0 = wc * 32 + nf * 8 + (lane & 3) * 2;
            float e0 = __expf(s[nf][0] - mnA), e1 = __expf(s[nf][1] - mnA);
            float e2 = __expf(s[nf][2] - mnB), e3 = __expf(s[nf][3] - mnB);
            suA += e0 + e1; suB += e2 + e3;
            __nv_bfloat162 pA, pB;
            pA.x = __float2bfloat16(e0); pA.y = __float2bfloat16(e1);
            pB.x = __float2bfloat16(e2); pB.y = __float2bfloat16(e3);
            *(__nv_bfloat162*)&PsH[la * 72 + c0] = pA;
            *(__nv_bfloat162*)&PsH[(la + 8) * 72 + c0] = pB;
        }
        suA += __shfl_xor_sync(~0u, suA, 1);
        suA += __shfl_xor_sync(~0u, suA, 2);
        suB += __shfl_xor_sync(~0u, suB, 1);
        suB += __shfl_xor_sync(~0u, suB, 2);
        if ((lane & 3) == 0) {
            redsum[wc * 64 + la] = suA;
            redsum[wc * 64 + la + 8] = suB;
        }
        if (it < 15) { CP_WAIT1(); } else { CP_WAIT0(); }
        __syncthreads();

        suA += redsum[(wc ^ 1) * 64 + la];
        suB += redsum[(wc ^ 1) * 64 + la + 8];
        srunA = srunA * sclA + suA;
        srunB = srunB * sclB + suB;

        // ---- O += Ph @ (Vh+Vl) (2-pass) ----
#pragma unroll
        for (int ks = 0; ks < 4; ks++) {
            uint32_t pah[4];
            uint32_t ra = (uint32_t)(((wr * 16 + aRow) * 72) + ks * 16 + aCol) * 2;
            ldm4(pah, sb + FPS + ra);
            uint32_t vbh[2][4], vbl[2][4];
#pragma unroll
            for (int p = 0; p < 2; p++) {
                uint32_t ro = (uint32_t)(((ks * 16 + aRow) * 72) + wc * 32 + p * 16 + aCol) * 2;
                ldm4t(vbh[p], sb + FV + ro);
                ldm4t(vbl[p], sb + FV + 9216 + ro);
            }
#pragma unroll
            for (int nf = 0; nf < 4; nf++) {
                const uint32_t* bhp = &vbh[nf >> 1][(nf & 1) * 2];
                const uint32_t* blp = &vbl[nf >> 1][(nf & 1) * 2];
                mma16816(O[nf], pah, bhp);
                mma16816(O[nf], pah, blp);
            }
        }
        __syncthreads();

        if (it < 15) {
            cp_t64(sb + FV, vh, vl, b * S_ + (it + 1) * 64);
            CP_COMMIT();
        }
    }

    // ---- epilogue: ctx hi-only ----
    const float iA = 1.f / srunA, iB = 1.f / srunB;
#pragma unroll
    for (int nf = 0; nf < 4; nf++) {
        const int col = hcol + wc * 32 + nf * 8 + (lane & 3) * 2;
        const size_t rowA = (size_t)(b * S_ + l0 + la) * H_ + col;
        const size_t rowB = (size_t)(b * S_ + l0 + la + 8) * H_ + col;
        __nv_bfloat162 cA, cB;
        cA.x = __float2bfloat16(O[nf][0] * iA); cA.y = __float2bfloat16(O[nf][1] * iA);
        cB.x = __float2bfloat16(O[nf][2] * iB); cB.y = __float2bfloat16(O[nf][3] * iB);
        *(__nv_bfloat162*)(ch + rowA) = cA;
        *(__nv_bfloat162*)(ch + rowB) = cB;
    }
}

// ---------------- LayerNorm ----------------------------------------------------------
__global__ void __launch_bounds__(256) ln_kernel(const float* __restrict__ y,
                                                 const float* __restrict__ g,
                                                 const float* __restrict__ bb,
                                                 float* __restrict__ out)
{
    __shared__ float sred[8];
    __shared__ float sbc;
    const size_t row = blockIdx.x;
    const int tid = threadIdx.x;
    const int lane = tid & 31, wid = tid >> 5;

    float4 v = ((const float4*)(y + row * H_))[tid];

    float s = v.x + v.y + v.z + v.w;
#pragma unroll
    for (int o = 16; o > 0; o >>= 1) s += __shfl_xor_sync(~0u, s, o);
    if (lane == 0) sred[wid] = s;
    __syncthreads();
    if (tid == 0) {
        float t = 0.f;
#pragma unroll
        for (int i = 0; i < 8; i++) t += sred[i];
        sbc = t;
    }
    __syncthreads();
    const float mu = sbc * (1.f / H_);

    float dx = v.x - mu, dy = v.y - mu, dz = v.z - mu, dw = v.w - mu;
    float qq = dx * dx + dy * dy + dz * dz + dw * dw;
#pragma unroll
    for (int o = 16; o > 0; o >>= 1) qq += __shfl_xor_sync(~0u, qq, o);
    if (lane == 0) sred[wid] = qq;
    __syncthreads();
    if (tid == 0) {
        float t = 0.f;
#pragma unroll
        for (int i = 0; i < 8; i++) t += sred[i];
        sbc = t;
    }
    __syncthreads();
    const float rstd = rsqrtf(sbc * (1.f / H_) + 1e-12f);

    float4 gg = ((const float4*)g)[tid];
    float4 bt = ((const float4*)bb)[tid];
    float4 o;
    o.x = dx * rstd * gg.x + bt.x;
    o.y = dy * rstd * gg.y + bt.y;
    o.z = dz * rstd * gg.z + bt.z;
    o.w = dw * rstd * gg.w + bt.w;
    ((float4*)(out + row * H_))[tid] = o;
}

// ---------------- launch -----------------------------------------------------------
extern "C" void kernel_launch(void* const* d_in, const int* in_sizes, int n_in,
                              void* d_out, int out_size)
{
    (void)in_sizes; (void)n_in; (void)out_size;
    const float* x    = (const float*)d_in[0];
    const float* mask = (const float*)d_in[1];
    const float* Wq   = (const float*)d_in[2];
    const float* bq   = (const float*)d_in[3];
    const float* Wk   = (const float*)d_in[4];
    const float* bk   = (const float*)d_in[5];
    const float* Wv   = (const float*)d_in[6];
    const float* bv   = (const float*)d_in[7];
    const float* de   = (const float*)d_in[8];
    const float* Wo   = (const float*)d_in[9];
    const float* bo   = (const float*)d_in[10];
    const float* lng  = (const float*)d_in[11];
    const float* lnb  = (const float*)d_in[12];
    float* out = (float*)d_out;

    float* y;
    cudaGetSymbolAddress((void**)&y, g_y);

    __nv_bfloat16 *xh, *wqh, *wql, *wkh, *wkl, *wvh, *wvl, *woh, *wol;
    __nv_bfloat16 *qh, *ql, *kh, *kl, *vh, *vl, *deh, *del, *ch;
    cudaGetSymbolAddress((void**)&xh, g_xh);
    cudaGetSymbolAddress((void**)&wqh, g_wqh); cudaGetSymbolAddress((void**)&wql, g_wql);
    cudaGetSymbolAddress((void**)&wkh, g_wkh); cudaGetSymbolAddress((void**)&wkl, g_wkl);
    cudaGetSymbolAddress((void**)&wvh, g_wvh); cudaGetSymbolAddress((void**)&wvl, g_wvl);
    cudaGetSymbolAddress((void**)&woh, g_woh); cudaGetSymbolAddress((void**)&wol, g_wol);
    cudaGetSymbolAddress((void**)&qh, g_qh);   cudaGetSymbolAddress((void**)&ql, g_ql);
    cudaGetSymbolAddress((void**)&kh, g_kh);   cudaGetSymbolAddress((void**)&kl, g_kl);
    cudaGetSymbolAddress((void**)&vh, g_vh);   cudaGetSymbolAddress((void**)&vl, g_vl);
    cudaGetSymbolAddress((void**)&deh, g_deh); cudaGetSymbolAddress((void**)&del, g_del);
    cudaGetSymbolAddress((void**)&ch, g_ch);

    cudaFuncSetAttribute(gemm_mma2<1>, cudaFuncAttributeMaxDynamicSharedMemorySize, GSM_TOTAL);
    cudaFuncSetAttribute(gemm_mma2<2>, cudaFuncAttributeMaxDynamicSharedMemorySize, GSM_TOTAL);
    cudaFuncSetAttribute(fused_attn, cudaFuncAttributeMaxDynamicSharedMemorySize, FSM_TOTAL);

    const int NX4 = BS_ * H_ / 4;
    const int NW4 = H_ * H_ / 4;
    conv_hi_kernel<<<NX4 / 256, 256>>>(x, xh, NX4);
    split4_kernel<<<dim3(NW4 / 256, 4), 256>>>(Wq, Wk, Wv, Wo,
                                               wqh, wql, wkh, wkl,
                                               wvh, wvl, woh, wol);
    const int ND4 = 2047 * 64 / 4;
    split_kernel<<<(ND4 + 255) / 256, 256>>>(de, deh, del, ND4);

    gemm_mma2<2><<<dim3(H_ / 128, BS_ / 128, 3), 256, GSM_TOTAL>>>(
        xh, wqh, wql, wkh, wkl, wvh, wvl, bq, bk, bv,
        qh, kh, vh, ql, kl, vl, nullptr);

    fused_attn<<<dim3(S_ / 64, BH_), 256, FSM_TOTAL>>>(
        qh, kh, kl, vh, vl, deh, mask, ch);

    gemm_mma2<1><<<dim3(H_ / 128, BS_ / 128, 1), 256, GSM_TOTAL>>>(
        ch, woh, wol, woh, wol, woh, wol, bo, bo, bo,
        y, y, y, nullptr, nullptr, nullptr, x);

    ln_kernel<<<BS_, 256>>>(y, lng, lnb, out);
}

// round 12
// speedup vs baseline: 2.4663x; 1.2933x over previous
#include <cuda_runtime.h>
#include <cuda_fp16.h>
#include <cstdint>

#define S_   1024
#define H_   1024
#define B_   4
#define NH_  16
#define D_   64
#define BS_  4096
#define BH_  64

// ---------------- scratch (no allocs allowed) ----------------
__device__ float g_y[BS_ * H_];

__device__ __half g_xh[BS_ * H_];
__device__ __half g_wq[H_ * H_], g_wk[H_ * H_], g_wv[H_ * H_], g_wo[H_ * H_];
__device__ __half g_qh[BS_ * H_], g_kh[BS_ * H_], g_vh[BS_ * H_];
__device__ __half g_de[2047 * 64];
__device__ __half g_ch[BS_ * H_];

// ---------------- helpers -------------------------------------------------------
__device__ __forceinline__ uint32_t smem_u32(const void* p)
{
    return (uint32_t)__cvta_generic_to_shared(p);
}
__device__ __forceinline__ void ldm4(uint32_t* r, uint32_t addr)
{
    asm volatile("ldmatrix.sync.aligned.m8n8.x4.shared.b16 {%0,%1,%2,%3}, [%4];"
                 : "=r"(r[0]), "=r"(r[1]), "=r"(r[2]), "=r"(r[3]) : "r"(addr));
}
__device__ __forceinline__ void ldm4t(uint32_t* r, uint32_t addr)
{
    asm volatile("ldmatrix.sync.aligned.m8n8.x4.trans.shared.b16 {%0,%1,%2,%3}, [%4];"
                 : "=r"(r[0]), "=r"(r[1]), "=r"(r[2]), "=r"(r[3]) : "r"(addr));
}
__device__ __forceinline__ void mma_f16(float* c, const uint32_t* a, const uint32_t* b)
{
    asm volatile("mma.sync.aligned.m16n8k16.row.col.f32.f16.f16.f32 "
                 "{%0,%1,%2,%3}, {%4,%5,%6,%7}, {%8,%9}, {%0,%1,%2,%3};"
                 : "+f"(c[0]), "+f"(c[1]), "+f"(c[2]), "+f"(c[3])
                 : "r"(a[0]), "r"(a[1]), "r"(a[2]), "r"(a[3]), "r"(b[0]), "r"(b[1]));
}
__device__ __forceinline__ void cpa16(uint32_t dst, const void* src)
{
    asm volatile("cp.async.cg.shared.global [%0], [%1], 16;" :: "r"(dst), "l"(src));
}
#define CP_COMMIT() asm volatile("cp.async.commit_group;" ::: "memory")
#define CP_WAIT1()  asm volatile("cp.async.wait_group 1;" ::: "memory")
#define CP_WAIT0()  asm volatile("cp.async.wait_group 0;" ::: "memory")

// ---------------- fp32 -> fp16 converts ---------------------------------------------
__global__ void __launch_bounds__(256) conv_kernel(const float* __restrict__ in,
                                                   __half* __restrict__ o, int n4)
{
    int i = blockIdx.x * 256 + threadIdx.x;
    if (i >= n4) return;
    float4 a = ((const float4*)in)[i];
    __half2 h0 = __floats2half2_rn(a.x, a.y);
    __half2 h1 = __floats2half2_rn(a.z, a.w);
    ((__half2*)o)[i * 2 + 0] = h0;
    ((__half2*)o)[i * 2 + 1] = h1;
}

__global__ void __launch_bounds__(256) conv4_kernel(
    const float* __restrict__ w0, const float* __restrict__ w1,
    const float* __restrict__ w2, const float* __restrict__ w3,
    __half* __restrict__ o0, __half* __restrict__ o1,
    __half* __restrict__ o2, __half* __restrict__ o3)
{
    const int z = blockIdx.y;
    const float* in = (z == 0) ? w0 : (z == 1) ? w1 : (z == 2) ? w2 : w3;
    __half* o = (z == 0) ? o0 : (z == 1) ? o1 : (z == 2) ? o2 : o3;
    int i = blockIdx.x * 256 + threadIdx.x;
    float4 a = ((const float4*)in)[i];
    ((__half2*)o)[i * 2 + 0] = __floats2half2_rn(a.x, a.y);
    ((__half2*)o)[i * 2 + 1] = __floats2half2_rn(a.z, a.w);
}

// ---------------- single-pass fp16 GEMM NT via HMMA --------------------------------
// C[i,j] = sum_k A[i,k]*B[j,k] + bias[j] (+resid / fp16-out). 3-stage, KT=16,
// single __syncthreads per kt (R11-validated structure).
#define KT    16
#define LDS_  24
#define MAT_B (128 * LDS_ * 2)      // 6144 B
#define STG_B (2 * MAT_B)           // 12288 B (A, B)
#define NSTG  3
#define GSM_TOTAL (NSTG * STG_B)    // 36864 B -> 2 CTAs/SM

template <int EPI>   // 1 = fp32 + bias + resid, 2 = fp16 + bias
__global__ void __launch_bounds__(256, 2) gemm_mma2(
    const __half* __restrict__ Ah,
    const __half* __restrict__ B0, const __half* __restrict__ B1,
    const __half* __restrict__ B2,
    const float* __restrict__ bias0, const float* __restrict__ bias1,
    const float* __restrict__ bias2,
    void* O0, void* O1, void* O2,
    const float* __restrict__ resid)
{
    extern __shared__ char smem[];
    const uint32_t sb = smem_u32(smem);

    const int z = blockIdx.z;
    const __half* Bm = (z == 0) ? B0 : (z == 1) ? B1 : B2;
    const float* bias = (z == 0) ? bias0 : (z == 1) ? bias1 : bias2;
    void* Ov = (z == 0) ? O0 : (z == 1) ? O1 : O2;

    const int tid = threadIdx.x;
    const int lane = tid & 31, wid = tid >> 5;
    const int wm = wid >> 2, wn = wid & 3;
    const int bM = blockIdx.y * 128, bN = blockIdx.x * 128;

    float acc[4][4][4] = {};

    const int vrow = tid >> 1;
    const int vc   = tid & 1;
    const int NK = H_ / KT;   // 64

    const int q8 = lane >> 3, r8 = lane & 7;
    const int arowL = wm * 64 + (q8 & 1) * 8 + r8;
    const int browL = wn * 32 + (q8 >> 1) * 8 + r8;
    const int acolL = (q8 >> 1) * 8;
    const int bcolL = (q8 & 1) * 8;

    auto issue = [&](int kt) {
        const int st = kt % NSTG;
        const uint32_t base = sb + st * STG_B;
        const int k0 = kt * KT;
        const uint32_t d0 = (uint32_t)(vrow * (LDS_ * 2) + vc * 16);
        cpa16(base + 0 * MAT_B + d0, Ah + (size_t)(bM + vrow) * H_ + k0 + vc * 8);
        cpa16(base + 1 * MAT_B + d0, Bm + (size_t)(bN + vrow) * H_ + k0 + vc * 8);
    };

    issue(0); CP_COMMIT();
    issue(1); CP_COMMIT();

    for (int kt = 0; kt < NK; kt++) {
        if (kt + 1 < NK) { CP_WAIT1(); } else { CP_WAIT0(); }
        __syncthreads();
        if (kt + 2 < NK) { issue(kt + 2); CP_COMMIT(); }

        const int st = kt % NSTG;
        const uint32_t bA = sb + st * STG_B + 0 * MAT_B;
        const uint32_t bB = sb + st * STG_B + 1 * MAT_B;

        uint32_t af[4][4];
#pragma unroll
        for (int mt = 0; mt < 4; mt++) {
            const uint32_t ro = (uint32_t)(((arowL + mt * 16) * LDS_ + acolL) * 2);
            ldm4(af[mt], bA + ro);
        }
        uint32_t bf[2][4];
#pragma unroll
        for (int p = 0; p < 2; p++) {
            const uint32_t ro = (uint32_t)(((browL + p * 16) * LDS_ + bcolL) * 2);
            ldm4(bf[p], bB + ro);
        }
#pragma unroll
        for (int mt = 0; mt < 4; mt++)
#pragma unroll
            for (int nt = 0; nt < 4; nt++)
                mma_f16(acc[mt][nt], af[mt], &bf[nt >> 1][(nt & 1) * 2]);
    }

    const int crow0 = bM + wm * 64 + (lane >> 2);
    const int ccol0 = bN + wn * 32 + (lane & 3) * 2;
#pragma unroll
    for (int mt = 0; mt < 4; mt++) {
        const int r0 = crow0 + mt * 16;
#pragma unroll
        for (int nt = 0; nt < 4; nt++) {
            const int c0 = ccol0 + nt * 8;
            float f0 = acc[mt][nt][0] + bias[c0];
            float f1 = acc[mt][nt][1] + bias[c0 + 1];
            float f2 = acc[mt][nt][2] + bias[c0];
            float f3 = acc[mt][nt][3] + bias[c0 + 1];
            if (EPI == 1) {
                f0 += resid[(size_t)r0 * H_ + c0];
                f1 += resid[(size_t)r0 * H_ + c0 + 1];
                f2 += resid[(size_t)(r0 + 8) * H_ + c0];
                f3 += resid[(size_t)(r0 + 8) * H_ + c0 + 1];
                float* O = (float*)Ov;
                O[(size_t)r0 * H_ + c0]           = f0;
                O[(size_t)r0 * H_ + c0 + 1]       = f1;
                O[(size_t)(r0 + 8) * H_ + c0]     = f2;
                O[(size_t)(r0 + 8) * H_ + c0 + 1] = f3;
            } else {
                __half* O = (__half*)Ov;
                *(__half2*)(O + (size_t)r0 * H_ + c0)       = __floats2half2_rn(f0, f1);
                *(__half2*)(O + (size_t)(r0 + 8) * H_ + c0) = __floats2half2_rn(f2, f3);
            }
        }
    }
}

// ---------------- fused flash attention, all fp16 single-pass ----------------------
#define FQ    0                    // 9216
#define FK    9216                 // 9216
#define FV    18432                // 9216
#define FP    27648                // 18432 (128 x 72 fp16)
#define FS2B  46080                // fp16 [64][136] = 17408
#define FS3B  63488                // 17408
#define FPS   46080                // probs fp16 (overlap S2B post-gather) 9216
#define FRED  80896                // 1024
#define FMASK 81920                // 4096
#define FSM_TOTAL 86016

__global__ void __launch_bounds__(256, 2) fused_attn(
    const __half* __restrict__ qh, const __half* __restrict__ kh,
    const __half* __restrict__ vh, const __half* __restrict__ deh,
    const float* __restrict__ mask,
    __half* __restrict__ ch)
{
    extern __shared__ char smem[];
    const uint32_t sb = smem_u32(smem);
    const int tid = threadIdx.x, lane = tid & 31, wid = tid >> 5;
    const int wr = wid >> 1, wc = wid & 1;
    const int l0 = blockIdx.x * 64;
    const int bh = blockIdx.y;
    const int b = bh >> 4, h = bh & 15;
    const int hcol = h * D_;

    const int q8 = lane >> 3, r8 = lane & 7;
    const int aRow = (q8 & 1) * 8 + r8, aCol = (q8 >> 1) * 8;
    const int bRow = (q8 >> 1) * 8 + r8, bCol = (q8 & 1) * 8;

    auto cp_t64 = [&](uint32_t dstbase, const __half* src, int growbase) {
#pragma unroll
        for (int j = 0; j < 2; j++) {
            int v = tid + 256 * j;
            int row = v >> 3, c = v & 7;
            cpa16(dstbase + (uint32_t)(row * 72 + c * 8) * 2,
                  src + (size_t)(growbase + row) * H_ + hcol + c * 8);
        }
    };
    auto cp_P = [&](int it) {
        const int prow0 = l0 - it * 64 + 960;
#pragma unroll
        for (int j = 0; j < 4; j++) {
            int v = tid + 256 * j;
            int row = v >> 3, c = v & 7;
            uint32_t off = (uint32_t)(row * 72 + c * 8) * 2;
            if (row < 127) {
                cpa16(sb + FP + off, deh + (size_t)(prow0 + row) * 64 + c * 8);
            } else {
                uint4 zz = {0, 0, 0, 0};
                *(uint4*)(smem + FP + off) = zz;
            }
        }
    };

    // prologue: group0 = {Q, K0, P0, mask}, group1 = {V0}
    cp_t64(sb + FQ, qh, b * S_ + l0);
    cp_t64(sb + FK, kh, b * S_ + 0);
    cp_P(0);
    cpa16(sb + FMASK + tid * 16, mask + (size_t)b * S_ + tid * 4);
    CP_COMMIT();
    cp_t64(sb + FV, vh, b * S_ + 0);
    CP_COMMIT();

    float O[4][4] = {};
    float mrunA = -1e30f, mrunB = -1e30f;
    float srunA = 0.f, srunB = 0.f;

    const int la = wr * 16 + (lane >> 2);
    __half* S2b = (__half*)(smem + FS2B);
    __half* S3b = (__half*)(smem + FS3B);
    float* redm = (float*)(smem + FRED);
    float* redsum = (float*)(smem + FRED + 512);
    const float* maskS = (const float*)(smem + FMASK);

    for (int it = 0; it < 16; it++) {
        CP_WAIT1();
        __syncthreads();

        // ---- S1 = Q @ K^T (single pass) ----
        float accS[4][4] = {};
#pragma unroll
        for (int ks = 0; ks < 4; ks++) {
            uint32_t af[4];
            ldm4(af, sb + FQ + (uint32_t)(((wr * 16 + aRow) * 72) + ks * 16 + aCol) * 2);
            uint32_t kb[2][4];
#pragma unroll
            for (int p = 0; p < 2; p++) {
                uint32_t ro = (uint32_t)(((wc * 32 + p * 16 + bRow) * 72) + ks * 16 + bCol) * 2;
                ldm4(kb[p], sb + FK + ro);
            }
#pragma unroll
            for (int nf = 0; nf < 4; nf++)
                mma_f16(accS[nf], af, &kb[nf >> 1][(nf & 1) * 2]);
        }

        // ---- S2 = Q @ P^T and S3 = K @ P^T (shared P-fragment) -> fp16 stage ----
        {
            float a2[4][2][4] = {};
            float a3[4][2][4] = {};
#pragma unroll
            for (int ks = 0; ks < 4; ks++) {
                uint32_t pb[4];
                uint32_t ro = (uint32_t)(((wid * 16 + bRow) * 72) + ks * 16 + bCol) * 2;
                ldm4(pb, sb + FP + ro);
#pragma unroll
                for (int mt = 0; mt < 4; mt++) {
                    uint32_t aq[4], ak[4];
                    uint32_t ra = (uint32_t)(((mt * 16 + aRow) * 72) + ks * 16 + aCol) * 2;
                    ldm4(aq, sb + FQ + ra);
                    ldm4(ak, sb + FK + ra);
#pragma unroll
                    for (int nf = 0; nf < 2; nf++) {
                        mma_f16(a2[mt][nf], aq, &pb[nf * 2]);
                        mma_f16(a3[mt][nf], ak, &pb[nf * 2]);
                    }
                }
            }
#pragma unroll
            for (int mt = 0; mt < 4; mt++) {
                const int rr = mt * 16 + (lane >> 2);
#pragma unroll
                for (int nf = 0; nf < 2; nf++) {
                    const int cc = wid * 16 + nf * 8 + (lane & 3) * 2;
                    *(__half2*)&S2b[rr * 136 + cc] = __floats2half2_rn(a2[mt][nf][0], a2[mt][nf][1]);
                    *(__half2*)&S2b[(rr + 8) * 136 + cc] = __floats2half2_rn(a2[mt][nf][2], a2[mt][nf][3]);
                    *(__half2*)&S3b[rr * 136 + cc] = __floats2half2_rn(a3[mt][nf][0], a3[mt][nf][1]);
                    *(__half2*)&S3b[(rr + 8) * 136 + cc] = __floats2half2_rn(a3[mt][nf][2], a3[mt][nf][3]);
                }
            }
        }
        __syncthreads();   // staging visible; K,P reads done

        if (it < 15) {
            cp_t64(sb + FK, kh, b * S_ + (it + 1) * 64);
            cp_P(it + 1);
            CP_COMMIT();
        }

        // ---- gather + mask + scale ----
        float s[4][4];
#pragma unroll
        for (int nf = 0; nf < 4; nf++) {
            const int c0 = wc * 32 + nf * 8 + (lane & 3) * 2;
            const int t0 = la - c0 + 63;
            const float mk0 = maskS[it * 64 + c0];
            const float mk1 = maskS[it * 64 + c0 + 1];
            float s2a = __half2float(S2b[la * 136 + t0]);
            float s2b_ = __half2float(S2b[la * 136 + t0 - 1]);
            float s2c = __half2float(S2b[(la + 8) * 136 + t0 + 8]);
            float s2d = __half2float(S2b[(la + 8) * 136 + t0 + 7]);
            float s3a = __half2float(S3b[c0 * 136 + t0]);
            float s3b_ = __half2float(S3b[(c0 + 1) * 136 + t0 - 1]);
            float s3c = __half2float(S3b[c0 * 136 + t0 + 8]);
            float s3d = __half2float(S3b[(c0 + 1) * 136 + t0 + 7]);
            s[nf][0] = (accS[nf][0] + s2a + s3a) * 0.125f + mk0;
            s[nf][1] = (accS[nf][1] + s2b_ + s3b_) * 0.125f + mk1;
            s[nf][2] = (accS[nf][2] + s2c + s3c) * 0.125f + mk0;
            s[nf][3] = (accS[nf][3] + s2d + s3d) * 0.125f + mk1;
        }

        // ---- online softmax ----
        float mA = -1e30f, mB = -1e30f;
#pragma unroll
        for (int nf = 0; nf < 4; nf++) {
            mA = fmaxf(mA, fmaxf(s[nf][0], s[nf][1]));
            mB = fmaxf(mB, fmaxf(s[nf][2], s[nf][3]));
        }
        mA = fmaxf(mA, __shfl_xor_sync(~0u, mA, 1));
        mA = fmaxf(mA, __shfl_xor_sync(~0u, mA, 2));
        mB = fmaxf(mB, __shfl_xor_sync(~0u, mB, 1));
        mB = fmaxf(mB, __shfl_xor_sync(~0u, mB, 2));
        if ((lane & 3) == 0) {
            redm[wc * 64 + la] = mA;
            redm[wc * 64 + la + 8] = mB;
        }
        __syncthreads();

        mA = fmaxf(mA, redm[(wc ^ 1) * 64 + la]);
        mB = fmaxf(mB, redm[(wc ^ 1) * 64 + la + 8]);
        const float mnA = fmaxf(mrunA, mA), mnB = fmaxf(mrunB, mB);
        const float sclA = __expf(mrunA - mnA), sclB = __expf(mrunB - mnB);
        mrunA = mnA; mrunB = mnB;
#pragma unroll
        for (int nf = 0; nf < 4; nf++) {
            O[nf][0] *= sclA; O[nf][1] *= sclA;
            O[nf][2] *= sclB; O[nf][3] *= sclB;
        }

        __half* PsH = (__half*)(smem + FPS);
        float suA = 0.f, suB = 0.f;
#pragma unroll
        for (int nf = 0; nf < 4; nf++) {
            const int c0 = wc * 32 + nf * 8 + (lane & 3) * 2;
            float e0 = __expf(s[nf][0] - mnA), e1 = __expf(s[nf][1] - mnA);
            float e2 = __expf(s[nf][2] - mnB), e3 = __expf(s[nf][3] - mnB);
            suA += e0 + e1; suB += e2 + e3;
            *(__half2*)&PsH[la * 72 + c0] = __floats2half2_rn(e0, e1);
            *(__half2*)&PsH[(la + 8) * 72 + c0] = __floats2half2_rn(e2, e3);
        }
        suA += __shfl_xor_sync(~0u, suA, 1);
        suA += __shfl_xor_sync(~0u, suA, 2);
        suB += __shfl_xor_sync(~0u, suB, 1);
        suB += __shfl_xor_sync(~0u, suB, 2);
        if ((lane & 3) == 0) {
            redsum[wc * 64 + la] = suA;
            redsum[wc * 64 + la + 8] = suB;
        }
        if (it < 15) { CP_WAIT1(); } else { CP_WAIT0(); }
        __syncthreads();   // probs + redsum + V visible

        suA += redsum[(wc ^ 1) * 64 + la];
        suB += redsum[(wc ^ 1) * 64 + la + 8];
        srunA = srunA * sclA + suA;
        srunB = srunB * sclB + suB;

        // ---- O += P @ V (single pass) ----
#pragma unroll
        for (int ks = 0; ks < 4; ks++) {
            uint32_t pa[4];
            uint32_t ra = (uint32_t)(((wr * 16 + aRow) * 72) + ks * 16 + aCol) * 2;
            ldm4(pa, sb + FPS + ra);
            uint32_t vb[2][4];
#pragma unroll
            for (int p = 0; p < 2; p++) {
                uint32_t ro = (uint32_t)(((ks * 16 + aRow) * 72) + wc * 32 + p * 16 + aCol) * 2;
                ldm4t(vb[p], sb + FV + ro);
            }
#pragma unroll
            for (int nf = 0; nf < 4; nf++)
                mma_f16(O[nf], pa, &vb[nf >> 1][(nf & 1) * 2]);
        }
        __syncthreads();   // PV reads of probs/V done before overwrite

        if (it < 15) {
            cp_t64(sb + FV, vh, b * S_ + (it + 1) * 64);
            CP_COMMIT();
        }
    }

    // ---- epilogue: ctx fp16 ----
    const float iA = 1.f / srunA, iB = 1.f / srunB;
#pragma unroll
    for (int nf = 0; nf < 4; nf++) {
        const int col = hcol + wc * 32 + nf * 8 + (lane & 3) * 2;
        const size_t rowA = (size_t)(b * S_ + l0 + la) * H_ + col;
        const size_t rowB = (size_t)(b * S_ + l0 + la + 8) * H_ + col;
        *(__half2*)(ch + rowA) = __floats2half2_rn(O[nf][0] * iA, O[nf][1] * iA);
        *(__half2*)(ch + rowB) = __floats2half2_rn(O[nf][2] * iB, O[nf][3] * iB);
    }
}

// ---------------- LayerNorm ----------------------------------------------------------
__global__ void __launch_bounds__(256) ln_kernel(const float* __restrict__ y,
                                                 const float* __restrict__ g,
                                                 const float* __restrict__ bb,
                                                 float* __restrict__ out)
{
    __shared__ float sred[8];
    __shared__ float sbc;
    const size_t row = blockIdx.x;
    const int tid = threadIdx.x;
    const int lane = tid & 31, wid = tid >> 5;

    float4 v = ((const float4*)(y + row * H_))[tid];

    float s = v.x + v.y + v.z + v.w;
#pragma unroll
    for (int o = 16; o > 0; o >>= 1) s += __shfl_xor_sync(~0u, s, o);
    if (lane == 0) sred[wid] = s;
    __syncthreads();
    if (tid == 0) {
        float t = 0.f;
#pragma unroll
        for (int i = 0; i < 8; i++) t += sred[i];
        sbc = t;
    }
    __syncthreads();
    const float mu = sbc * (1.f / H_);

    float dx = v.x - mu, dy = v.y - mu, dz = v.z - mu, dw = v.w - mu;
    float qq = dx * dx + dy * dy + dz * dz + dw * dw;
#pragma unroll
    for (int o = 16; o > 0; o >>= 1) qq += __shfl_xor_sync(~0u, qq, o);
    if (lane == 0) sred[wid] = qq;
    __syncthreads();
    if (tid == 0) {
        float t = 0.f;
#pragma unroll
        for (int i = 0; i < 8; i++) t += sred[i];
        sbc = t;
    }
    __syncthreads();
    const float rstd = rsqrtf(sbc * (1.f / H_) + 1e-12f);

    float4 gg = ((const float4*)g)[tid];
    float4 bt = ((const float4*)bb)[tid];
    float4 o;
    o.x = dx * rstd * gg.x + bt.x;
    o.y = dy * rstd * gg.y + bt.y;
    o.z = dz * rstd * gg.z + bt.z;
    o.w = dw * rstd * gg.w + bt.w;
    ((float4*)(out + row * H_))[tid] = o;
}

// ---------------- launch -----------------------------------------------------------
extern "C" void kernel_launch(void* const* d_in, const int* in_sizes, int n_in,
                              void* d_out, int out_size)
{
    (void)in_sizes; (void)n_in; (void)out_size;
    const float* x    = (const float*)d_in[0];
    const float* mask = (const float*)d_in[1];
    const float* Wq   = (const float*)d_in[2];
    const float* bq   = (const float*)d_in[3];
    const float* Wk   = (const float*)d_in[4];
    const float* bk   = (const float*)d_in[5];
    const float* Wv   = (const float*)d_in[6];
    const float* bv   = (const float*)d_in[7];
    const float* de   = (const float*)d_in[8];
    const float* Wo   = (const float*)d_in[9];
    const float* bo   = (const float*)d_in[10];
    const float* lng  = (const float*)d_in[11];
    const float* lnb  = (const float*)d_in[12];
    float* out = (float*)d_out;

    float* y;
    cudaGetSymbolAddress((void**)&y, g_y);

    __half *xh, *wq, *wk, *wv, *wo, *qh, *kh, *vh, *deh, *ch;
    cudaGetSymbolAddress((void**)&xh, g_xh);
    cudaGetSymbolAddress((void**)&wq, g_wq);
    cudaGetSymbolAddress((void**)&wk, g_wk);
    cudaGetSymbolAddress((void**)&wv, g_wv);
    cudaGetSymbolAddress((void**)&wo, g_wo);
    cudaGetSymbolAddress((void**)&qh, g_qh);
    cudaGetSymbolAddress((void**)&kh, g_kh);
    cudaGetSymbolAddress((void**)&vh, g_vh);
    cudaGetSymbolAddress((void**)&deh, g_de);
    cudaGetSymbolAddress((void**)&ch, g_ch);

    cudaFuncSetAttribute(gemm_mma2<1>, cudaFuncAttributeMaxDynamicSharedMemorySize, GSM_TOTAL);
    cudaFuncSetAttribute(gemm_mma2<2>, cudaFuncAttributeMaxDynamicSharedMemorySize, GSM_TOTAL);
    cudaFuncSetAttribute(fused_attn, cudaFuncAttributeMaxDynamicSharedMemorySize, FSM_TOTAL);

    const int NX4 = BS_ * H_ / 4;
    const int NW4 = H_ * H_ / 4;
    conv_kernel<<<NX4 / 256, 256>>>(x, xh, NX4);
    conv4_kernel<<<dim3(NW4 / 256, 4), 256>>>(Wq, Wk, Wv, Wo, wq, wk, wv, wo);
    const int ND4 = 2047 * 64 / 4;
    conv_kernel<<<(ND4 + 255) / 256, 256>>>(de, deh, ND4);

    gemm_mma2<2><<<dim3(H_ / 128, BS_ / 128, 3), 256, GSM_TOTAL>>>(
        xh, wq, wk, wv, bq, bk, bv, qh, kh, vh, nullptr);

    fused_attn<<<dim3(S_ / 64, BH_), 256, FSM_TOTAL>>>(
        qh, kh, vh, deh, mask, ch);

    gemm_mma2<1><<<dim3(H_ / 128, BS_ / 128, 1), 256, GSM_TOTAL>>>(
        ch, wo, wo, wo, bo, bo, bo, y, y, y, x);

    ln_kernel<<<BS_, 256>>>(y, lng, lnb, out);
}

// round 13
// speedup vs baseline: 2.6406x; 1.0707x over previous
#include <cuda_runtime.h>
#include <cuda_fp16.h>
#include <cstdint>

#define S_   1024
#define H_   1024
#define B_   4
#define NH_  16
#define D_   64
#define BS_  4096
#define BH_  64

// ---------------- scratch (no allocs allowed) ----------------
__device__ float g_y[BS_ * H_];

__device__ __half g_xh[BS_ * H_];
__device__ __half g_wq[H_ * H_], g_wk[H_ * H_], g_wv[H_ * H_], g_wo[H_ * H_];
__device__ __half g_qh[BS_ * H_], g_kh[BS_ * H_], g_vh[BS_ * H_];
__device__ __half g_de[2047 * 64];
__device__ __half g_ch[BS_ * H_];

// ---------------- helpers -------------------------------------------------------
__device__ __forceinline__ uint32_t smem_u32(const void* p)
{
    return (uint32_t)__cvta_generic_to_shared(p);
}
__device__ __forceinline__ void ldm4(uint32_t* r, uint32_t addr)
{
    asm volatile("ldmatrix.sync.aligned.m8n8.x4.shared.b16 {%0,%1,%2,%3}, [%4];"
                 : "=r"(r[0]), "=r"(r[1]), "=r"(r[2]), "=r"(r[3]) : "r"(addr));
}
__device__ __forceinline__ void ldm4t(uint32_t* r, uint32_t addr)
{
    asm volatile("ldmatrix.sync.aligned.m8n8.x4.trans.shared.b16 {%0,%1,%2,%3}, [%4];"
                 : "=r"(r[0]), "=r"(r[1]), "=r"(r[2]), "=r"(r[3]) : "r"(addr));
}
__device__ __forceinline__ void mma_f16(float* c, const uint32_t* a, const uint32_t* b)
{
    asm volatile("mma.sync.aligned.m16n8k16.row.col.f32.f16.f16.f32 "
                 "{%0,%1,%2,%3}, {%4,%5,%6,%7}, {%8,%9}, {%0,%1,%2,%3};"
                 : "+f"(c[0]), "+f"(c[1]), "+f"(c[2]), "+f"(c[3])
                 : "r"(a[0]), "r"(a[1]), "r"(a[2]), "r"(a[3]), "r"(b[0]), "r"(b[1]));
}
__device__ __forceinline__ void cpa16(uint32_t dst, const void* src)
{
    asm volatile("cp.async.cg.shared.global [%0], [%1], 16;" :: "r"(dst), "l"(src));
}
#define CP_COMMIT() asm volatile("cp.async.commit_group;" ::: "memory")
#define CP_WAIT1()  asm volatile("cp.async.wait_group 1;" ::: "memory")
#define CP_WAIT0()  asm volatile("cp.async.wait_group 0;" ::: "memory")

// ---------------- fp32 -> fp16 converts ---------------------------------------------
__global__ void __launch_bounds__(256) conv_kernel(const float* __restrict__ in,
                                                   __half* __restrict__ o, int n4)
{
    int i = blockIdx.x * 256 + threadIdx.x;
    if (i >= n4) return;
    float4 a = ((const float4*)in)[i];
    ((__half2*)o)[i * 2 + 0] = __floats2half2_rn(a.x, a.y);
    ((__half2*)o)[i * 2 + 1] = __floats2half2_rn(a.z, a.w);
}

__global__ void __launch_bounds__(256) conv4_kernel(
    const float* __restrict__ w0, const float* __restrict__ w1,
    const float* __restrict__ w2, const float* __restrict__ w3,
    __half* __restrict__ o0, __half* __restrict__ o1,
    __half* __restrict__ o2, __half* __restrict__ o3)
{
    const int z = blockIdx.y;
    const float* in = (z == 0) ? w0 : (z == 1) ? w1 : (z == 2) ? w2 : w3;
    __half* o = (z == 0) ? o0 : (z == 1) ? o1 : (z == 2) ? o2 : o3;
    int i = blockIdx.x * 256 + threadIdx.x;
    float4 a = ((const float4*)in)[i];
    ((__half2*)o)[i * 2 + 0] = __floats2half2_rn(a.x, a.y);
    ((__half2*)o)[i * 2 + 1] = __floats2half2_rn(a.z, a.w);
}

// ---------------- single-pass fp16 GEMM NT, KT=32, 3-stage, 2 CTAs/SM --------------
#define KTG   32
#define LDSG  40                    // 32 + 8 pad halves; 80B stride, conflict-free
#define MAT_B (128 * LDSG * 2)      // 10240 B
#define STG_B (2 * MAT_B)           // 20480 B
#define NSTG  3
#define GSM_TOTAL (NSTG * STG_B)    // 61440 B -> 2 CTAs/SM

template <int EPI>   // 1 = fp32 + bias + resid, 2 = fp16 + bias
__global__ void __launch_bounds__(256, 2) gemm_mma2(
    const __half* __restrict__ Ah,
    const __half* __restrict__ B0, const __half* __restrict__ B1,
    const __half* __restrict__ B2,
    const float* __restrict__ bias0, const float* __restrict__ bias1,
    const float* __restrict__ bias2,
    void* O0, void* O1, void* O2,
    const float* __restrict__ resid)
{
    extern __shared__ char smem[];
    const uint32_t sb = smem_u32(smem);

    const int z = blockIdx.z;
    const __half* Bm = (z == 0) ? B0 : (z == 1) ? B1 : B2;
    const float* bias = (z == 0) ? bias0 : (z == 1) ? bias1 : bias2;
    void* Ov = (z == 0) ? O0 : (z == 1) ? O1 : O2;

    const int tid = threadIdx.x;
    const int lane = tid & 31, wid = tid >> 5;
    const int wm = wid >> 2, wn = wid & 3;
    const int bM = blockIdx.y * 128, bN = blockIdx.x * 128;

    float acc[4][4][4] = {};
    const int NK = H_ / KTG;   // 32

    const int q8 = lane >> 3, r8 = lane & 7;
    const int arowL = wm * 64 + (q8 & 1) * 8 + r8;
    const int browL = wn * 32 + (q8 >> 1) * 8 + r8;
    const int acolL = (q8 >> 1) * 8;
    const int bcolL = (q8 & 1) * 8;

    auto issue = [&](int kt) {
        const int st = kt % NSTG;
        const uint32_t base = sb + st * STG_B;
        const int k0 = kt * KTG;
#pragma unroll
        for (int j = 0; j < 2; j++) {
            int v = tid + 256 * j;
            int row = v >> 2, c = v & 3;
            uint32_t d = base + (uint32_t)(row * (LDSG * 2) + c * 16);
            cpa16(d,         Ah + (size_t)(bM + row) * H_ + k0 + c * 8);
            cpa16(d + MAT_B, Bm + (size_t)(bN + row) * H_ + k0 + c * 8);
        }
    };

    issue(0); CP_COMMIT();
    issue(1); CP_COMMIT();

    for (int kt = 0; kt < NK; kt++) {
        if (kt + 1 < NK) { CP_WAIT1(); } else { CP_WAIT0(); }
        __syncthreads();
        if (kt + 2 < NK) { issue(kt + 2); CP_COMMIT(); }

        const int st = kt % NSTG;
        const uint32_t bA = sb + st * STG_B;
        const uint32_t bB = bA + MAT_B;

#pragma unroll
        for (int ks = 0; ks < KTG; ks += 16) {
            uint32_t af[4][4];
#pragma unroll
            for (int mt = 0; mt < 4; mt++) {
                const uint32_t ro = (uint32_t)(((arowL + mt * 16) * LDSG + acolL + ks) * 2);
                ldm4(af[mt], bA + ro);
            }
            uint32_t bf[2][4];
#pragma unroll
            for (int p = 0; p < 2; p++) {
                const uint32_t ro = (uint32_t)(((browL + p * 16) * LDSG + bcolL + ks) * 2);
                ldm4(bf[p], bB + ro);
            }
#pragma unroll
            for (int mt = 0; mt < 4; mt++)
#pragma unroll
                for (int nt = 0; nt < 4; nt++)
                    mma_f16(acc[mt][nt], af[mt], &bf[nt >> 1][(nt & 1) * 2]);
        }
    }

    const int crow0 = bM + wm * 64 + (lane >> 2);
    const int ccol0 = bN + wn * 32 + (lane & 3) * 2;
#pragma unroll
    for (int mt = 0; mt < 4; mt++) {
        const int r0 = crow0 + mt * 16;
#pragma unroll
        for (int nt = 0; nt < 4; nt++) {
            const int c0 = ccol0 + nt * 8;
            float f0 = acc[mt][nt][0] + bias[c0];
            float f1 = acc[mt][nt][1] + bias[c0 + 1];
            float f2 = acc[mt][nt][2] + bias[c0];
            float f3 = acc[mt][nt][3] + bias[c0 + 1];
            if (EPI == 1) {
                f0 += resid[(size_t)r0 * H_ + c0];
                f1 += resid[(size_t)r0 * H_ + c0 + 1];
                f2 += resid[(size_t)(r0 + 8) * H_ + c0];
                f3 += resid[(size_t)(r0 + 8) * H_ + c0 + 1];
                float* O = (float*)Ov;
                O[(size_t)r0 * H_ + c0]           = f0;
                O[(size_t)r0 * H_ + c0 + 1]       = f1;
                O[(size_t)(r0 + 8) * H_ + c0]     = f2;
                O[(size_t)(r0 + 8) * H_ + c0 + 1] = f3;
            } else {
                __half* O = (__half*)Ov;
                *(__half2*)(O + (size_t)r0 * H_ + c0)       = __floats2half2_rn(f0, f1);
                *(__half2*)(O + (size_t)(r0 + 8) * H_ + c0) = __floats2half2_rn(f2, f3);
            }
        }
    }
}

// ---------------- fused flash attention: incremental S2 ring ------------------------
// S2 ring: q[l]·pe[p] stored at col (p mod 192), pitch 200 halves.
#define FQ    0                    // 9216
#define FK    9216                 // 9216
#define FV    18432                // 9216
#define FP    27648                // 18432 (128 x 72 fp16)
#define FS2R  46080                // fp16 [64][200] = 25600
#define FS3B  71680                // fp16 [64][136] = 17408
#define FPS   89088                // probs fp16 [64][72] = 9216
#define FRED  98304                // 1024
#define FMASK 99328                // 4096
#define FSM_TOTAL 103424

__global__ void __launch_bounds__(256, 2) fused_attn(
    const __half* __restrict__ qh, const __half* __restrict__ kh,
    const __half* __restrict__ vh, const __half* __restrict__ deh,
    const float* __restrict__ mask,
    __half* __restrict__ ch)
{
    extern __shared__ char smem[];
    const uint32_t sb = smem_u32(smem);
    const int tid = threadIdx.x, lane = tid & 31, wid = tid >> 5;
    const int wr = wid >> 1, wc = wid & 1;
    const int l0 = blockIdx.x * 64;
    const int bh = blockIdx.y;
    const int b = bh >> 4, h = bh & 15;
    const int hcol = h * D_;

    const int q8 = lane >> 3, r8 = lane & 7;
    const int aRow = (q8 & 1) * 8 + r8, aCol = (q8 >> 1) * 8;
    const int bRow = (q8 >> 1) * 8 + r8, bCol = (q8 & 1) * 8;

    __half* S2r = (__half*)(smem + FS2R);
    __half* S3b = (__half*)(smem + FS3B);
    float* redm = (float*)(smem + FRED);
    float* redsum = (float*)(smem + FRED + 512);
    const float* maskS = (const float*)(smem + FMASK);

    auto cp_t64 = [&](uint32_t dstbase, const __half* src, int growbase) {
#pragma unroll
        for (int j = 0; j < 2; j++) {
            int v = tid + 256 * j;
            int row = v >> 3, c = v & 7;
            cpa16(dstbase + (uint32_t)(row * 72 + c * 8) * 2,
                  src + (size_t)(growbase + row) * H_ + hcol + c * 8);
        }
    };
    auto cp_P = [&](int it) {
        const int prow0 = l0 - it * 64 + 960;
#pragma unroll
        for (int j = 0; j < 4; j++) {
            int v = tid + 256 * j;
            int row = v >> 3, c = v & 7;
            uint32_t off = (uint32_t)(row * 72 + c * 8) * 2;
            if (row < 127) {
                cpa16(sb + FP + off, deh + (size_t)(prow0 + row) * 64 + c * 8);
            } else {
                uint4 zz = {0, 0, 0, 0};
                *(uint4*)(smem + FP + off) = zz;
            }
        }
    };

    // S2 strip: out = Q[64] @ P[rbase..rbase+63]^T, stored at ring cols [csb, csb+64)
    // warp mapping: wl = wid>>2 (32 l-rows), wt = wid&3 (16 t-cols)
    auto s2_strip = [&](int rbase, int csb) {
        const int wl = wid >> 2, wt = wid & 3;
        float a2[2][2][4] = {};
#pragma unroll
        for (int ks = 0; ks < 4; ks++) {
            uint32_t pb[4];
            uint32_t ro = (uint32_t)(((rbase + wt * 16 + bRow) * 72) + ks * 16 + bCol) * 2;
            ldm4(pb, sb + FP + ro);
#pragma unroll
            for (int mt = 0; mt < 2; mt++) {
                uint32_t aq[4];
                uint32_t ra = (uint32_t)(((wl * 32 + mt * 16 + aRow) * 72) + ks * 16 + aCol) * 2;
                ldm4(aq, sb + FQ + ra);
#pragma unroll
                for (int nf = 0; nf < 2; nf++)
                    mma_f16(a2[mt][nf], aq, &pb[nf * 2]);
            }
        }
#pragma unroll
        for (int mt = 0; mt < 2; mt++) {
            const int rr = wl * 32 + mt * 16 + (lane >> 2);
#pragma unroll
            for (int nf = 0; nf < 2; nf++) {
                const int cc = csb + wt * 16 + nf * 8 + (lane & 3) * 2;
                *(__half2*)&S2r[rr * 200 + cc] = __floats2half2_rn(a2[mt][nf][0], a2[mt][nf][1]);
                *(__half2*)&S2r[(rr + 8) * 200 + cc] = __floats2half2_rn(a2[mt][nf][2], a2[mt][nf][3]);
            }
        }
    };

    // prologue: group0 = {Q, K0, P0, mask}, group1 = {V0}
    cp_t64(sb + FQ, qh, b * S_ + l0);
    cp_t64(sb + FK, kh, b * S_ + 0);
    cp_P(0);
    cpa16(sb + FMASK + tid * 16, mask + (size_t)b * S_ + tid * 4);
    CP_COMMIT();
    cp_t64(sb + FV, vh, b * S_ + 0);
    CP_COMMIT();

    float O[4][4] = {};
    float mrunA = -1e30f, mrunB = -1e30f;
    float srunA = 0.f, srunB = 0.f;
    const int la = wr * 16 + (lane >> 2);

    for (int it = 0; it < 16; it++) {
        CP_WAIT1();
        __syncthreads();

        const int prow0 = l0 - it * 64 + 960;
        const int csb = prow0 % 192;           // 64-aligned in {0,64,128}

        // ---- S1 = Q @ K^T (single pass) ----
        float accS[4][4] = {};
#pragma unroll
        for (int ks = 0; ks < 4; ks++) {
            uint32_t af[4];
            ldm4(af, sb + FQ + (uint32_t)(((wr * 16 + aRow) * 72) + ks * 16 + aCol) * 2);
            uint32_t kb[2][4];
#pragma unroll
            for (int p = 0; p < 2; p++) {
                uint32_t ro = (uint32_t)(((wc * 32 + p * 16 + bRow) * 72) + ks * 16 + bCol) * 2;
                ldm4(kb[p], sb + FK + ro);
            }
#pragma unroll
            for (int nf = 0; nf < 4; nf++)
                mma_f16(accS[nf], af, &kb[nf >> 1][(nf & 1) * 2]);
        }

        // ---- S2 strips (incremental): it=0 computes both halves, else lower only ----
        if (it == 0) s2_strip(64, (csb + 64) % 192);
        s2_strip(0, csb);

        // ---- S3 = K @ P^T (full 128 t) -> fp16 stage ----
        {
            float a3[4][2][4] = {};
#pragma unroll
            for (int ks = 0; ks < 4; ks++) {
                uint32_t pb[4];
                uint32_t ro = (uint32_t)(((wid * 16 + bRow) * 72) + ks * 16 + bCol) * 2;
                ldm4(pb, sb + FP + ro);
#pragma unroll
                for (int mt = 0; mt < 4; mt++) {
                    uint32_t ak[4];
                    uint32_t ra = (uint32_t)(((mt * 16 + aRow) * 72) + ks * 16 + aCol) * 2;
                    ldm4(ak, sb + FK + ra);
#pragma unroll
                    for (int nf = 0; nf < 2; nf++)
                        mma_f16(a3[mt][nf], ak, &pb[nf * 2]);
                }
            }
#pragma unroll
            for (int mt = 0; mt < 4; mt++) {
                const int rr = mt * 16 + (lane >> 2);
#pragma unroll
                for (int nf = 0; nf < 2; nf++) {
                    const int cc = wid * 16 + nf * 8 + (lane & 3) * 2;
                    *(__half2*)&S3b[rr * 136 + cc] = __floats2half2_rn(a3[mt][nf][0], a3[mt][nf][1]);
                    *(__half2*)&S3b[(rr + 8) * 136 + cc] = __floats2half2_rn(a3[mt][nf][2], a3[mt][nf][3]);
                }
            }
        }
        __syncthreads();   // S2 strip + S3 visible; K,P reads done

        if (it < 15) {
            cp_t64(sb + FK, kh, b * S_ + (it + 1) * 64);
            cp_P(it + 1);
            CP_COMMIT();
        }

        // ---- gather + mask + scale (S2 via ring mod-192) ----
        float s[4][4];
#pragma unroll
        for (int nf = 0; nf < 4; nf++) {
            const int c0 = wc * 32 + nf * 8 + (lane & 3) * 2;
            const int t0 = la - c0 + 63;
            int ca = csb + t0;        if (ca >= 192) ca -= 192;
            int cb = csb + t0 - 1;    if (cb < 0) cb += 192; else if (cb >= 192) cb -= 192;
            int cc = csb + t0 + 8;    if (cc >= 192) cc -= 192;
            int cd = csb + t0 + 7;    if (cd >= 192) cd -= 192;
            const float mk0 = maskS[it * 64 + c0];
            const float mk1 = maskS[it * 64 + c0 + 1];
            float s2a = __half2float(S2r[la * 200 + ca]);
            float s2b_ = __half2float(S2r[la * 200 + cb]);
            float s2c = __half2float(S2r[(la + 8) * 200 + cc]);
            float s2d = __half2float(S2r[(la + 8) * 200 + cd]);
            float s3a = __half2float(S3b[c0 * 136 + t0]);
            float s3b_ = __half2float(S3b[(c0 + 1) * 136 + t0 - 1]);
            float s3c = __half2float(S3b[c0 * 136 + t0 + 8]);
            float s3d = __half2float(S3b[(c0 + 1) * 136 + t0 + 7]);
            s[nf][0] = (accS[nf][0] + s2a + s3a) * 0.125f + mk0;
            s[nf][1] = (accS[nf][1] + s2b_ + s3b_) * 0.125f + mk1;
            s[nf][2] = (accS[nf][2] + s2c + s3c) * 0.125f + mk0;
            s[nf][3] = (accS[nf][3] + s2d + s3d) * 0.125f + mk1;
        }

        // ---- online softmax ----
        float mA = -1e30f, mB = -1e30f;
#pragma unroll
        for (int nf = 0; nf < 4; nf++) {
            mA = fmaxf(mA, fmaxf(s[nf][0], s[nf][1]));
            mB = fmaxf(mB, fmaxf(s[nf][2], s[nf][3]));
        }
        mA = fmaxf(mA, __shfl_xor_sync(~0u, mA, 1));
        mA = fmaxf(mA, __shfl_xor_sync(~0u, mA, 2));
        mB = fmaxf(mB, __shfl_xor_sync(~0u, mB, 1));
        mB = fmaxf(mB, __shfl_xor_sync(~0u, mB, 2));
        if ((lane & 3) == 0) {
            redm[wc * 64 + la] = mA;
            redm[wc * 64 + la + 8] = mB;
        }
        __syncthreads();

        mA = fmaxf(mA, redm[(wc ^ 1) * 64 + la]);
        mB = fmaxf(mB, redm[(wc ^ 1) * 64 + la + 8]);
        const float mnA = fmaxf(mrunA, mA), mnB = fmaxf(mrunB, mB);
        const float sclA = __expf(mrunA - mnA), sclB = __expf(mrunB - mnB);
        mrunA = mnA; mrunB = mnB;
#pragma unroll
        for (int nf = 0; nf < 4; nf++) {
            O[nf][0] *= sclA; O[nf][1] *= sclA;
            O[nf][2] *= sclB; O[nf][3] *= sclB;
        }

        __half* PsH = (__half*)(smem + FPS);
        float suA = 0.f, suB = 0.f;
#pragma unroll
        for (int nf = 0; nf < 4; nf++) {
            const int c0 = wc * 32 + nf * 8 + (lane & 3) * 2;
            float e0 = __expf(s[nf][0] - mnA), e1 = __expf(s[nf][1] - mnA);
            float e2 = __expf(s[nf][2] - mnB), e3 = __expf(s[nf][3] - mnB);
            suA += e0 + e1; suB += e2 + e3;
            *(__half2*)&PsH[la * 72 + c0] = __floats2half2_rn(e0, e1);
            *(__half2*)&PsH[(la + 8) * 72 + c0] = __floats2half2_rn(e2, e3);
        }
        suA += __shfl_xor_sync(~0u, suA, 1);
        suA += __shfl_xor_sync(~0u, suA, 2);
        suB += __shfl_xor_sync(~0u, suB, 1);
        suB += __shfl_xor_sync(~0u, suB, 2);
        if ((lane & 3) == 0) {
            redsum[wc * 64 + la] = suA;
            redsum[wc * 64 + la + 8] = suB;
        }
        if (it < 15) { CP_WAIT1(); } else { CP_WAIT0(); }
        __syncthreads();   // probs + redsum + V visible

        suA += redsum[(wc ^ 1) * 64 + la];
        suB += redsum[(wc ^ 1) * 64 + la + 8];
        srunA = srunA * sclA + suA;
        srunB = srunB * sclB + suB;

        // ---- O += P @ V (single pass) ----
#pragma unroll
        for (int ks = 0; ks < 4; ks++) {
            uint32_t pa[4];
            uint32_t ra = (uint32_t)(((wr * 16 + aRow) * 72) + ks * 16 + aCol) * 2;
            ldm4(pa, sb + FPS + ra);
            uint32_t vb[2][4];
#pragma unroll
            for (int p = 0; p < 2; p++) {
                uint32_t ro = (uint32_t)(((ks * 16 + aRow) * 72) + wc * 32 + p * 16 + aCol) * 2;
                ldm4t(vb[p], sb + FV + ro);
            }
#pragma unroll
            for (int nf = 0; nf < 4; nf++)
                mma_f16(O[nf], pa, &vb[nf >> 1][(nf & 1) * 2]);
        }
        __syncthreads();   // PV reads done before V/probs overwrite

        if (it < 15) {
            cp_t64(sb + FV, vh, b * S_ + (it + 1) * 64);
            CP_COMMIT();
        }
    }

    // ---- epilogue: ctx fp16 ----
    const float iA = 1.f / srunA, iB = 1.f / srunB;
#pragma unroll
    for (int nf = 0; nf < 4; nf++) {
        const int col = hcol + wc * 32 + nf * 8 + (lane & 3) * 2;
        const size_t rowA = (size_t)(b * S_ + l0 + la) * H_ + col;
        const size_t rowB = (size_t)(b * S_ + l0 + la + 8) * H_ + col;
        *(__half2*)(ch + rowA) = __floats2half2_rn(O[nf][0] * iA, O[nf][1] * iA);
        *(__half2*)(ch + rowB) = __floats2half2_rn(O[nf][2] * iB, O[nf][3] * iB);
    }
}

// ---------------- LayerNorm ----------------------------------------------------------
__global__ void __launch_bounds__(256) ln_kernel(const float* __restrict__ y,
                                                 const float* __restrict__ g,
                                                 const float* __restrict__ bb,
                                                 float* __restrict__ out)
{
    __shared__ float sred[8];
    __shared__ float sbc;
    const size_t row = blockIdx.x;
    const int tid = threadIdx.x;
    const int lane = tid & 31, wid = tid >> 5;

    float4 v = ((const float4*)(y + row * H_))[tid];

    float s = v.x + v.y + v.z + v.w;
#pragma unroll
    for (int o = 16; o > 0; o >>= 1) s += __shfl_xor_sync(~0u, s, o);
    if (lane == 0) sred[wid] = s;
    __syncthreads();
    if (tid == 0) {
        float t = 0.f;
#pragma unroll
        for (int i = 0; i < 8; i++) t += sred[i];
        sbc = t;
    }
    __syncthreads();
    const float mu = sbc * (1.f / H_);

    float dx = v.x - mu, dy = v.y - mu, dz = v.z - mu, dw = v.w - mu;
    float qq = dx * dx + dy * dy + dz * dz + dw * dw;
#pragma unroll
    for (int o = 16; o > 0; o >>= 1) qq += __shfl_xor_sync(~0u, qq, o);
    if (lane == 0) sred[wid] = qq;
    __syncthreads();
    if (tid == 0) {
        float t = 0.f;
#pragma unroll
        for (int i = 0; i < 8; i++) t += sred[i];
        sbc = t;
    }
    __syncthreads();
    const float rstd = rsqrtf(sbc * (1.f / H_) + 1e-12f);

    float4 gg = ((const float4*)g)[tid];
    float4 bt = ((const float4*)bb)[tid];
    float4 o;
    o.x = dx * rstd * gg.x + bt.x;
    o.y = dy * rstd * gg.y + bt.y;
    o.z = dz * rstd * gg.z + bt.z;
    o.w = dw * rstd * gg.w + bt.w;
    ((float4*)(out + row * H_))[tid] = o;
}

// ---------------- launch -----------------------------------------------------------
extern "C" void kernel_launch(void* const* d_in, const int* in_sizes, int n_in,
                              void* d_out, int out_size)
{
    (void)in_sizes; (void)n_in; (void)out_size;
    const float* x    = (const float*)d_in[0];
    const float* mask = (const float*)d_in[1];
    const float* Wq   = (const float*)d_in[2];
    const float* bq   = (const float*)d_in[3];
    const float* Wk   = (const float*)d_in[4];
    const float* bk   = (const float*)d_in[5];
    const float* Wv   = (const float*)d_in[6];
    const float* bv   = (const float*)d_in[7];
    const float* de   = (const float*)d_in[8];
    const float* Wo   = (const float*)d_in[9];
    const float* bo   = (const float*)d_in[10];
    const float* lng  = (const float*)d_in[11];
    const float* lnb  = (const float*)d_in[12];
    float* out = (float*)d_out;

    float* y;
    cudaGetSymbolAddress((void**)&y, g_y);

    __half *xh, *wq, *wk, *wv, *wo, *qh, *kh, *vh, *deh, *ch;
    cudaGetSymbolAddress((void**)&xh, g_xh);
    cudaGetSymbolAddress((void**)&wq, g_wq);
    cudaGetSymbolAddress((void**)&wk, g_wk);
    cudaGetSymbolAddress((void**)&wv, g_wv);
    cudaGetSymbolAddress((void**)&wo, g_wo);
    cudaGetSymbolAddress((void**)&qh, g_qh);
    cudaGetSymbolAddress((void**)&kh, g_kh);
    cudaGetSymbolAddress((void**)&vh, g_vh);
    cudaGetSymbolAddress((void**)&deh, g_de);
    cudaGetSymbolAddress((void**)&ch, g_ch);

    cudaFuncSetAttribute(gemm_mma2<1>, cudaFuncAttributeMaxDynamicSharedMemorySize, GSM_TOTAL);
    cudaFuncSetAttribute(gemm_mma2<2>, cudaFuncAttributeMaxDynamicSharedMemorySize, GSM_TOTAL);
    cudaFuncSetAttribute(fused_attn, cudaFuncAttributeMaxDynamicSharedMemorySize, FSM_TOTAL);

    const int NX4 = BS_ * H_ / 4;
    const int NW4 = H_ * H_ / 4;
    conv_kernel<<<NX4 / 256, 256>>>(x, xh, NX4);
    conv4_kernel<<<dim3(NW4 / 256, 4), 256>>>(Wq, Wk, Wv, Wo, wq, wk, wv, wo);
    const int ND4 = 2047 * 64 / 4;
    conv_kernel<<<(ND4 + 255) / 256, 256>>>(de, deh, ND4);

    gemm_mma2<2><<<dim3(H_ / 128, BS_ / 128, 3), 256, GSM_TOTAL>>>(
        xh, wq, wk, wv, bq, bk, bv, qh, kh, vh, nullptr);

    fused_attn<<<dim3(S_ / 64, BH_), 256, FSM_TOTAL>>>(
        qh, kh, vh, deh, mask, ch);

    gemm_mma2<1><<<dim3(H_ / 128, BS_ / 128, 1), 256, GSM_TOTAL>>>(
        ch, wo, wo, wo, bo, bo, bo, y, y, y, x);

    ln_kernel<<<BS_, 256>>>(y, lng, lnb, out);
}

// round 14
// speedup vs baseline: 2.7389x; 1.0372x over previous
#include <cuda_runtime.h>
#include <cuda_fp16.h>
#include <cstdint>

#define S_   1024
#define H_   1024
#define B_   4
#define NH_  16
#define D_   64
#define BS_  4096
#define BH_  64

// ---------------- scratch (no allocs allowed) ----------------
__device__ float g_y[BS_ * H_];

__device__ __half g_xh[BS_ * H_];
__device__ __half g_wq[H_ * H_], g_wk[H_ * H_], g_wv[H_ * H_], g_wo[H_ * H_];
__device__ __half g_qh[BS_ * H_], g_kh[BS_ * H_], g_vh[BS_ * H_];
__device__ __half g_de[2047 * 64];
__device__ __half g_ch[BS_ * H_];

// ---------------- helpers -------------------------------------------------------
__device__ __forceinline__ uint32_t smem_u32(const void* p)
{
    return (uint32_t)__cvta_generic_to_shared(p);
}
__device__ __forceinline__ void ldm4(uint32_t* r, uint32_t addr)
{
    asm volatile("ldmatrix.sync.aligned.m8n8.x4.shared.b16 {%0,%1,%2,%3}, [%4];"
                 : "=r"(r[0]), "=r"(r[1]), "=r"(r[2]), "=r"(r[3]) : "r"(addr));
}
__device__ __forceinline__ void ldm4t(uint32_t* r, uint32_t addr)
{
    asm volatile("ldmatrix.sync.aligned.m8n8.x4.trans.shared.b16 {%0,%1,%2,%3}, [%4];"
                 : "=r"(r[0]), "=r"(r[1]), "=r"(r[2]), "=r"(r[3]) : "r"(addr));
}
__device__ __forceinline__ void mma_f16(float* c, const uint32_t* a, const uint32_t* b)
{
    asm volatile("mma.sync.aligned.m16n8k16.row.col.f32.f16.f16.f32 "
                 "{%0,%1,%2,%3}, {%4,%5,%6,%7}, {%8,%9}, {%0,%1,%2,%3};"
                 : "+f"(c[0]), "+f"(c[1]), "+f"(c[2]), "+f"(c[3])
                 : "r"(a[0]), "r"(a[1]), "r"(a[2]), "r"(a[3]), "r"(b[0]), "r"(b[1]));
}
__device__ __forceinline__ void cpa16(uint32_t dst, const void* src)
{
    asm volatile("cp.async.cg.shared.global [%0], [%1], 16;" :: "r"(dst), "l"(src));
}
#define CP_COMMIT() asm volatile("cp.async.commit_group;" ::: "memory")
#define CP_WAIT1()  asm volatile("cp.async.wait_group 1;" ::: "memory")
#define CP_WAIT0()  asm volatile("cp.async.wait_group 0;" ::: "memory")

// ---------------- fp32 -> fp16 converts ---------------------------------------------
__global__ void __launch_bounds__(256) conv_kernel(const float* __restrict__ in,
                                                   __half* __restrict__ o, int n4)
{
    int i = blockIdx.x * 256 + threadIdx.x;
    if (i >= n4) return;
    float4 a = ((const float4*)in)[i];
    ((__half2*)o)[i * 2 + 0] = __floats2half2_rn(a.x, a.y);
    ((__half2*)o)[i * 2 + 1] = __floats2half2_rn(a.z, a.w);
}

__global__ void __launch_bounds__(256) conv4_kernel(
    const float* __restrict__ w0, const float* __restrict__ w1,
    const float* __restrict__ w2, const float* __restrict__ w3,
    __half* __restrict__ o0, __half* __restrict__ o1,
    __half* __restrict__ o2, __half* __restrict__ o3)
{
    const int z = blockIdx.y;
    const float* in = (z == 0) ? w0 : (z == 1) ? w1 : (z == 2) ? w2 : w3;
    __half* o = (z == 0) ? o0 : (z == 1) ? o1 : (z == 2) ? o2 : o3;
    int i = blockIdx.x * 256 + threadIdx.x;
    float4 a = ((const float4*)in)[i];
    ((__half2*)o)[i * 2 + 0] = __floats2half2_rn(a.x, a.y);
    ((__half2*)o)[i * 2 + 1] = __floats2half2_rn(a.z, a.w);
}

// ---------------- fp16 GEMM NT, 128 threads, warp tile 64x64, KT=32 ----------------
#define KTG   32
#define LDSG  40
#define MAT_B (128 * LDSG * 2)      // 10240 B
#define STG_B (2 * MAT_B)           // 20480 B
#define NSTG  3
#define GSM_TOTAL (NSTG * STG_B)    // 61440 B -> 2 CTAs/SM

template <int EPI>   // 1 = fp32 + bias + resid, 2 = fp16 + bias
__global__ void __launch_bounds__(128, 2) gemm_mma2(
    const __half* __restrict__ Ah,
    const __half* __restrict__ B0, const __half* __restrict__ B1,
    const __half* __restrict__ B2,
    const float* __restrict__ bias0, const float* __restrict__ bias1,
    const float* __restrict__ bias2,
    void* O0, void* O1, void* O2,
    const float* __restrict__ resid)
{
    extern __shared__ char smem[];
    const uint32_t sb = smem_u32(smem);

    const int z = blockIdx.z;
    const __half* Bm = (z == 0) ? B0 : (z == 1) ? B1 : B2;
    const float* bias = (z == 0) ? bias0 : (z == 1) ? bias1 : bias2;
    void* Ov = (z == 0) ? O0 : (z == 1) ? O1 : O2;

    const int tid = threadIdx.x;
    const int lane = tid & 31, wid = tid >> 5;   // 4 warps
    const int wm = wid >> 1, wn = wid & 1;       // 2x2
    const int bM = blockIdx.y * 128, bN = blockIdx.x * 128;

    float acc[4][8][4] = {};
    const int NK = H_ / KTG;   // 32

    const int q8 = lane >> 3, r8 = lane & 7;
    const int arowL = wm * 64 + (q8 & 1) * 8 + r8;
    const int browL = wn * 64 + (q8 >> 1) * 8 + r8;
    const int acolL = (q8 >> 1) * 8;
    const int bcolL = (q8 & 1) * 8;

    auto issue = [&](int kt) {
        const int st = kt % NSTG;
        const uint32_t base = sb + st * STG_B;
        const int k0 = kt * KTG;
#pragma unroll
        for (int j = 0; j < 4; j++) {
            int v = tid + 128 * j;
            int row = v >> 2, c = v & 3;
            uint32_t d = base + (uint32_t)(row * (LDSG * 2) + c * 16);
            cpa16(d,         Ah + (size_t)(bM + row) * H_ + k0 + c * 8);
            cpa16(d + MAT_B, Bm + (size_t)(bN + row) * H_ + k0 + c * 8);
        }
    };

    issue(0); CP_COMMIT();
    issue(1); CP_COMMIT();

    for (int kt = 0; kt < NK; kt++) {
        if (kt + 1 < NK) { CP_WAIT1(); } else { CP_WAIT0(); }
        __syncthreads();
        if (kt + 2 < NK) { issue(kt + 2); CP_COMMIT(); }

        const int st = kt % NSTG;
        const uint32_t bA = sb + st * STG_B;
        const uint32_t bB = bA + MAT_B;

#pragma unroll
        for (int ks = 0; ks < KTG; ks += 16) {
            uint32_t af[4][4];
#pragma unroll
            for (int mt = 0; mt < 4; mt++) {
                const uint32_t ro = (uint32_t)(((arowL + mt * 16) * LDSG + acolL + ks) * 2);
                ldm4(af[mt], bA + ro);
            }
            uint32_t bf[4][4];
#pragma unroll
            for (int p = 0; p < 4; p++) {
                const uint32_t ro = (uint32_t)(((browL + p * 16) * LDSG + bcolL + ks) * 2);
                ldm4(bf[p], bB + ro);
            }
#pragma unroll
            for (int mt = 0; mt < 4; mt++)
#pragma unroll
                for (int nt = 0; nt < 8; nt++)
                    mma_f16(acc[mt][nt], af[mt], &bf[nt >> 1][(nt & 1) * 2]);
        }
    }

    const int crow0 = bM + wm * 64 + (lane >> 2);
    const int ccol0 = bN + wn * 64 + (lane & 3) * 2;
#pragma unroll
    for (int mt = 0; mt < 4; mt++) {
        const int r0 = crow0 + mt * 16;
#pragma unroll
        for (int nt = 0; nt < 8; nt++) {
            const int c0 = ccol0 + nt * 8;
            float f0 = acc[mt][nt][0] + bias[c0];
            float f1 = acc[mt][nt][1] + bias[c0 + 1];
            float f2 = acc[mt][nt][2] + bias[c0];
            float f3 = acc[mt][nt][3] + bias[c0 + 1];
            if (EPI == 1) {
                f0 += resid[(size_t)r0 * H_ + c0];
                f1 += resid[(size_t)r0 * H_ + c0 + 1];
                f2 += resid[(size_t)(r0 + 8) * H_ + c0];
                f3 += resid[(size_t)(r0 + 8) * H_ + c0 + 1];
                float* O = (float*)Ov;
                O[(size_t)r0 * H_ + c0]           = f0;
                O[(size_t)r0 * H_ + c0 + 1]       = f1;
                O[(size_t)(r0 + 8) * H_ + c0]     = f2;
                O[(size_t)(r0 + 8) * H_ + c0 + 1] = f3;
            } else {
                __half* O = (__half*)Ov;
                *(__half2*)(O + (size_t)r0 * H_ + c0)       = __floats2half2_rn(f0, f1);
                *(__half2*)(O + (size_t)(r0 + 8) * H_ + c0) = __floats2half2_rn(f2, f3);
            }
        }
    }
}

// ---------------- fused flash attention: incremental S2 ring (R13, unchanged) ------
#define FQ    0
#define FK    9216
#define FV    18432
#define FP    27648
#define FS2R  46080                // fp16 [64][200] = 25600
#define FS3B  71680                // fp16 [64][136] = 17408
#define FPS   89088                // probs fp16 [64][72] = 9216
#define FRED  98304
#define FMASK 99328
#define FSM_TOTAL 103424

__global__ void __launch_bounds__(256, 2) fused_attn(
    const __half* __restrict__ qh, const __half* __restrict__ kh,
    const __half* __restrict__ vh, const __half* __restrict__ deh,
    const float* __restrict__ mask,
    __half* __restrict__ ch)
{
    extern __shared__ char smem[];
    const uint32_t sb = smem_u32(smem);
    const int tid = threadIdx.x, lane = tid & 31, wid = tid >> 5;
    const int wr = wid >> 1, wc = wid & 1;
    const int l0 = blockIdx.x * 64;
    const int bh = blockIdx.y;
    const int b = bh >> 4, h = bh & 15;
    const int hcol = h * D_;

    const int q8 = lane >> 3, r8 = lane & 7;
    const int aRow = (q8 & 1) * 8 + r8, aCol = (q8 >> 1) * 8;
    const int bRow = (q8 >> 1) * 8 + r8, bCol = (q8 & 1) * 8;

    __half* S2r = (__half*)(smem + FS2R);
    __half* S3b = (__half*)(smem + FS3B);
    float* redm = (float*)(smem + FRED);
    float* redsum = (float*)(smem + FRED + 512);
    const float* maskS = (const float*)(smem + FMASK);

    auto cp_t64 = [&](uint32_t dstbase, const __half* src, int growbase) {
#pragma unroll
        for (int j = 0; j < 2; j++) {
            int v = tid + 256 * j;
            int row = v >> 3, c = v & 7;
            cpa16(dstbase + (uint32_t)(row * 72 + c * 8) * 2,
                  src + (size_t)(growbase + row) * H_ + hcol + c * 8);
        }
    };
    auto cp_P = [&](int it) {
        const int prow0 = l0 - it * 64 + 960;
#pragma unroll
        for (int j = 0; j < 4; j++) {
            int v = tid + 256 * j;
            int row = v >> 3, c = v & 7;
            uint32_t off = (uint32_t)(row * 72 + c * 8) * 2;
            if (row < 127) {
                cpa16(sb + FP + off, deh + (size_t)(prow0 + row) * 64 + c * 8);
            } else {
                uint4 zz = {0, 0, 0, 0};
                *(uint4*)(smem + FP + off) = zz;
            }
        }
    };

    auto s2_strip = [&](int rbase, int csb) {
        const int wl = wid >> 2, wt = wid & 3;
        float a2[2][2][4] = {};
#pragma unroll
        for (int ks = 0; ks < 4; ks++) {
            uint32_t pb[4];
            uint32_t ro = (uint32_t)(((rbase + wt * 16 + bRow) * 72) + ks * 16 + bCol) * 2;
            ldm4(pb, sb + FP + ro);
#pragma unroll
            for (int mt = 0; mt < 2; mt++) {
                uint32_t aq[4];
                uint32_t ra = (uint32_t)(((wl * 32 + mt * 16 + aRow) * 72) + ks * 16 + aCol) * 2;
                ldm4(aq, sb + FQ + ra);
#pragma unroll
                for (int nf = 0; nf < 2; nf++)
                    mma_f16(a2[mt][nf], aq, &pb[nf * 2]);
            }
        }
#pragma unroll
        for (int mt = 0; mt < 2; mt++) {
            const int rr = wl * 32 + mt * 16 + (lane >> 2);
#pragma unroll
            for (int nf = 0; nf < 2; nf++) {
                const int cc = csb + wt * 16 + nf * 8 + (lane & 3) * 2;
                *(__half2*)&S2r[rr * 200 + cc] = __floats2half2_rn(a2[mt][nf][0], a2[mt][nf][1]);
                *(__half2*)&S2r[(rr + 8) * 200 + cc] = __floats2half2_rn(a2[mt][nf][2], a2[mt][nf][3]);
            }
        }
    };

    cp_t64(sb + FQ, qh, b * S_ + l0);
    cp_t64(sb + FK, kh, b * S_ + 0);
    cp_P(0);
    cpa16(sb + FMASK + tid * 16, mask + (size_t)b * S_ + tid * 4);
    CP_COMMIT();
    cp_t64(sb + FV, vh, b * S_ + 0);
    CP_COMMIT();

    float O[4][4] = {};
    float mrunA = -1e30f, mrunB = -1e30f;
    float srunA = 0.f, srunB = 0.f;
    const int la = wr * 16 + (lane >> 2);

    for (int it = 0; it < 16; it++) {
        CP_WAIT1();
        __syncthreads();

        const int prow0 = l0 - it * 64 + 960;
        const int csb = prow0 % 192;

        // ---- S1 = Q @ K^T ----
        float accS[4][4] = {};
#pragma unroll
        for (int ks = 0; ks < 4; ks++) {
            uint32_t af[4];
            ldm4(af, sb + FQ + (uint32_t)(((wr * 16 + aRow) * 72) + ks * 16 + aCol) * 2);
            uint32_t kb[2][4];
#pragma unroll
            for (int p = 0; p < 2; p++) {
                uint32_t ro = (uint32_t)(((wc * 32 + p * 16 + bRow) * 72) + ks * 16 + bCol) * 2;
                ldm4(kb[p], sb + FK + ro);
            }
#pragma unroll
            for (int nf = 0; nf < 4; nf++)
                mma_f16(accS[nf], af, &kb[nf >> 1][(nf & 1) * 2]);
        }

        if (it == 0) s2_strip(64, (csb + 64) % 192);
        s2_strip(0, csb);

        // ---- S3 = K @ P^T ----
        {
            float a3[4][2][4] = {};
#pragma unroll
            for (int ks = 0; ks < 4; ks++) {
                uint32_t pb[4];
                uint32_t ro = (uint32_t)(((wid * 16 + bRow) * 72) + ks * 16 + bCol) * 2;
                ldm4(pb, sb + FP + ro);
#pragma unroll
                for (int mt = 0; mt < 4; mt++) {
                    uint32_t ak[4];
                    uint32_t ra = (uint32_t)(((mt * 16 + aRow) * 72) + ks * 16 + aCol) * 2;
                    ldm4(ak, sb + FK + ra);
#pragma unroll
                    for (int nf = 0; nf < 2; nf++)
                        mma_f16(a3[mt][nf], ak, &pb[nf * 2]);
                }
            }
#pragma unroll
            for (int mt = 0; mt < 4; mt++) {
                const int rr = mt * 16 + (lane >> 2);
#pragma unroll
                for (int nf = 0; nf < 2; nf++) {
                    const int cc = wid * 16 + nf * 8 + (lane & 3) * 2;
                    *(__half2*)&S3b[rr * 136 + cc] = __floats2half2_rn(a3[mt][nf][0], a3[mt][nf][1]);
                    *(__half2*)&S3b[(rr + 8) * 136 + cc] = __floats2half2_rn(a3[mt][nf][2], a3[mt][nf][3]);
                }
            }
        }
        __syncthreads();

        if (it < 15) {
            cp_t64(sb + FK, kh, b * S_ + (it + 1) * 64);
            cp_P(it + 1);
            CP_COMMIT();
        }

        // ---- gather + mask + scale ----
        float s[4][4];
#pragma unroll
        for (int nf = 0; nf < 4; nf++) {
            const int c0 = wc * 32 + nf * 8 + (lane & 3) * 2;
            const int t0 = la - c0 + 63;
            int ca = csb + t0;        if (ca >= 192) ca -= 192;
            int cb = csb + t0 - 1;    if (cb < 0) cb += 192; else if (cb >= 192) cb -= 192;
            int cc = csb + t0 + 8;    if (cc >= 192) cc -= 192;
            int cd = csb + t0 + 7;    if (cd >= 192) cd -= 192;
            const float mk0 = maskS[it * 64 + c0];
            const float mk1 = maskS[it * 64 + c0 + 1];
            float s2a = __half2float(S2r[la * 200 + ca]);
            float s2b_ = __half2float(S2r[la * 200 + cb]);
            float s2c = __half2float(S2r[(la + 8) * 200 + cc]);
            float s2d = __half2float(S2r[(la + 8) * 200 + cd]);
            float s3a = __half2float(S3b[c0 * 136 + t0]);
            float s3b_ = __half2float(S3b[(c0 + 1) * 136 + t0 - 1]);
            float s3c = __half2float(S3b[c0 * 136 + t0 + 8]);
            float s3d = __half2float(S3b[(c0 + 1) * 136 + t0 + 7]);
            s[nf][0] = (accS[nf][0] + s2a + s3a) * 0.125f + mk0;
            s[nf][1] = (accS[nf][1] + s2b_ + s3b_) * 0.125f + mk1;
            s[nf][2] = (accS[nf][2] + s2c + s3c) * 0.125f + mk0;
            s[nf][3] = (accS[nf][3] + s2d + s3d) * 0.125f + mk1;
        }

        // ---- online softmax ----
        float mA = -1e30f, mB = -1e30f;
#pragma unroll
        for (int nf = 0; nf < 4; nf++) {
            mA = fmaxf(mA, fmaxf(s[nf][0], s[nf][1]));
            mB = fmaxf(mB, fmaxf(s[nf][2], s[nf][3]));
        }
        mA = fmaxf(mA, __shfl_xor_sync(~0u, mA, 1));
        mA = fmaxf(mA, __shfl_xor_sync(~0u, mA, 2));
        mB = fmaxf(mB, __shfl_xor_sync(~0u, mB, 1));
        mB = fmaxf(mB, __shfl_xor_sync(~0u, mB, 2));
        if ((lane & 3) == 0) {
            redm[wc * 64 + la] = mA;
            redm[wc * 64 + la + 8] = mB;
        }
        __syncthreads();

        mA = fmaxf(mA, redm[(wc ^ 1) * 64 + la]);
        mB = fmaxf(mB, redm[(wc ^ 1) * 64 + la + 8]);
        const float mnA = fmaxf(mrunA, mA), mnB = fmaxf(mrunB, mB);
        const float sclA = __expf(mrunA - mnA), sclB = __expf(mrunB - mnB);
        mrunA = mnA; mrunB = mnB;
#pragma unroll
        for (int nf = 0; nf < 4; nf++) {
            O[nf][0] *= sclA; O[nf][1] *= sclA;
            O[nf][2] *= sclB; O[nf][3] *= sclB;
        }

        __half* PsH = (__half*)(smem + FPS);
        float suA = 0.f, suB = 0.f;
#pragma unroll
        for (int nf = 0; nf < 4; nf++) {
            const int c0 = wc * 32 + nf * 8 + (lane & 3) * 2;
            float e0 = __expf(s[nf][0] - mnA), e1 = __expf(s[nf][1] - mnA);
            float e2 = __expf(s[nf][2] - mnB), e3 = __expf(s[nf][3] - mnB);
            suA += e0 + e1; suB += e2 + e3;
            *(__half2*)&PsH[la * 72 + c0] = __floats2half2_rn(e0, e1);
            *(__half2*)&PsH[(la + 8) * 72 + c0] = __floats2half2_rn(e2, e3);
        }
        suA += __shfl_xor_sync(~0u, suA, 1);
        suA += __shfl_xor_sync(~0u, suA, 2);
        suB += __shfl_xor_sync(~0u, suB, 1);
        suB += __shfl_xor_sync(~0u, suB, 2);
        if ((lane & 3) == 0) {
            redsum[wc * 64 + la] = suA;
            redsum[wc * 64 + la + 8] = suB;
        }
        if (it < 15) { CP_WAIT1(); } else { CP_WAIT0(); }
        __syncthreads();

        suA += redsum[(wc ^ 1) * 64 + la];
        suB += redsum[(wc ^ 1) * 64 + la + 8];
        srunA = srunA * sclA + suA;
        srunB = srunB * sclB + suB;

        // ---- O += P @ V ----
#pragma unroll
        for (int ks = 0; ks < 4; ks++) {
            uint32_t pa[4];
            uint32_t ra = (uint32_t)(((wr * 16 + aRow) * 72) + ks * 16 + aCol) * 2;
            ldm4(pa, sb + FPS + ra);
            uint32_t vb[2][4];
#pragma unroll
            for (int p = 0; p < 2; p++) {
                uint32_t ro = (uint32_t)(((ks * 16 + aRow) * 72) + wc * 32 + p * 16 + aCol) * 2;
                ldm4t(vb[p], sb + FV + ro);
            }
#pragma unroll
            for (int nf = 0; nf < 4; nf++)
                mma_f16(O[nf], pa, &vb[nf >> 1][(nf & 1) * 2]);
        }
        __syncthreads();

        if (it < 15) {
            cp_t64(sb + FV, vh, b * S_ + (it + 1) * 64);
            CP_COMMIT();
        }
    }

    const float iA = 1.f / srunA, iB = 1.f / srunB;
#pragma unroll
    for (int nf = 0; nf < 4; nf++) {
        const int col = hcol + wc * 32 + nf * 8 + (lane & 3) * 2;
        const size_t rowA = (size_t)(b * S_ + l0 + la) * H_ + col;
        const size_t rowB = (size_t)(b * S_ + l0 + la + 8) * H_ + col;
        *(__half2*)(ch + rowA) = __floats2half2_rn(O[nf][0] * iA, O[nf][1] * iA);
        *(__half2*)(ch + rowB) = __floats2half2_rn(O[nf][2] * iB, O[nf][3] * iB);
    }
}

// ---------------- LayerNorm ----------------------------------------------------------
__global__ void __launch_bounds__(256) ln_kernel(const float* __restrict__ y,
                                                 const float* __restrict__ g,
                                                 const float* __restrict__ bb,
                                                 float* __restrict__ out)
{
    __shared__ float sred[8];
    __shared__ float sbc;
    const size_t row = blockIdx.x;
    const int tid = threadIdx.x;
    const int lane = tid & 31, wid = tid >> 5;

    float4 v = ((const float4*)(y + row * H_))[tid];

    float s = v.x + v.y + v.z + v.w;
#pragma unroll
    for (int o = 16; o > 0; o >>= 1) s += __shfl_xor_sync(~0u, s, o);
    if (lane == 0) sred[wid] = s;
    __syncthreads();
    if (tid == 0) {
        float t = 0.f;
#pragma unroll
        for (int i = 0; i < 8; i++) t += sred[i];
        sbc = t;
    }
    __syncthreads();
    const float mu = sbc * (1.f / H_);

    float dx = v.x - mu, dy = v.y - mu, dz = v.z - mu, dw = v.w - mu;
    float qq = dx * dx + dy * dy + dz * dz + dw * dw;
#pragma unroll
    for (int o = 16; o > 0; o >>= 1) qq += __shfl_xor_sync(~0u, qq, o);
    if (lane == 0) sred[wid] = qq;
    __syncthreads();
    if (tid == 0) {
        float t = 0.f;
#pragma unroll
        for (int i = 0; i < 8; i++) t += sred[i];
        sbc = t;
    }
    __syncthreads();
    const float rstd = rsqrtf(sbc * (1.f / H_) + 1e-12f);

    float4 gg = ((const float4*)g)[tid];
    float4 bt = ((const float4*)bb)[tid];
    float4 o;
    o.x = dx * rstd * gg.x + bt.x;
    o.y = dy * rstd * gg.y + bt.y;
    o.z = dz * rstd * gg.z + bt.z;
    o.w = dw * rstd * gg.w + bt.w;
    ((float4*)(out + row * H_))[tid] = o;
}

// ---------------- launch -----------------------------------------------------------
extern "C" void kernel_launch(void* const* d_in, const int* in_sizes, int n_in,
                              void* d_out, int out_size)
{
    (void)in_sizes; (void)n_in; (void)out_size;
    const float* x    = (const float*)d_in[0];
    const float* mask = (const float*)d_in[1];
    const float* Wq   = (const float*)d_in[2];
    const float* bq   = (const float*)d_in[3];
    const float* Wk   = (const float*)d_in[4];
    const float* bk   = (const float*)d_in[5];
    const float* Wv   = (const float*)d_in[6];
    const float* bv   = (const float*)d_in[7];
    const float* de   = (const float*)d_in[8];
    const float* Wo   = (const float*)d_in[9];
    const float* bo   = (const float*)d_in[10];
    const float* lng  = (const float*)d_in[11];
    const float* lnb  = (const float*)d_in[12];
    float* out = (float*)d_out;

    float* y;
    cudaGetSymbolAddress((void**)&y, g_y);

    __half *xh, *wq, *wk, *wv, *wo, *qh, *kh, *vh, *deh, *ch;
    cudaGetSymbolAddress((void**)&xh, g_xh);
    cudaGetSymbolAddress((void**)&wq, g_wq);
    cudaGetSymbolAddress((void**)&wk, g_wk);
    cudaGetSymbolAddress((void**)&wv, g_wv);
    cudaGetSymbolAddress((void**)&wo, g_wo);
    cudaGetSymbolAddress((void**)&qh, g_qh);
    cudaGetSymbolAddress((void**)&kh, g_kh);
    cudaGetSymbolAddress((void**)&vh, g_vh);
    cudaGetSymbolAddress((void**)&deh, g_de);
    cudaGetSymbolAddress((void**)&ch, g_ch);

    cudaFuncSetAttribute(gemm_mma2<1>, cudaFuncAttributeMaxDynamicSharedMemorySize, GSM_TOTAL);
    cudaFuncSetAttribute(gemm_mma2<2>, cudaFuncAttributeMaxDynamicSharedMemorySize, GSM_TOTAL);
    cudaFuncSetAttribute(fused_attn, cudaFuncAttributeMaxDynamicSharedMemorySize, FSM_TOTAL);

    const int NX4 = BS_ * H_ / 4;
    const int NW4 = H_ * H_ / 4;
    conv_kernel<<<NX4 / 256, 256>>>(x, xh, NX4);
    conv4_kernel<<<dim3(NW4 / 256, 4), 256>>>(Wq, Wk, Wv, Wo, wq, wk, wv, wo);
    const int ND4 = 2047 * 64 / 4;
    conv_kernel<<<(ND4 + 255) / 256, 256>>>(de, deh, ND4);

    gemm_mma2<2><<<dim3(H_ / 128, BS_ / 128, 3), 128, GSM_TOTAL>>>(
        xh, wq, wk, wv, bq, bk, bv, qh, kh, vh, nullptr);

    fused_attn<<<dim3(S_ / 64, BH_), 256, FSM_TOTAL>>>(
        qh, kh, vh, deh, mask, ch);

    gemm_mma2<1><<<dim3(H_ / 128, BS_ / 128, 1), 128, GSM_TOTAL>>>(
        ch, wo, wo, wo, bo, bo, bo, y, y, y, x);

    ln_kernel<<<BS_, 256>>>(y, lng, lnb, out);
}

// round 15
// speedup vs baseline: 2.9218x; 1.0668x over previous
#include <cuda_runtime.h>
#include <cuda_fp16.h>
#include <cstdint>

#define S_   1024
#define H_   1024
#define B_   4
#define NH_  16
#define D_   64
#define BS_  4096
#define BH_  64

// ---------------- scratch (no allocs allowed) ----------------
__device__ float g_y[BS_ * H_];

__device__ __half g_xh[BS_ * H_];
__device__ __half g_wq[H_ * H_], g_wk[H_ * H_], g_wv[H_ * H_], g_wo[H_ * H_];
__device__ __half g_qh[BS_ * H_], g_kh[BS_ * H_], g_vh[BS_ * H_];
__device__ __half g_de[2047 * 64];
__device__ __half g_ch[BS_ * H_];

// ---------------- helpers -------------------------------------------------------
__device__ __forceinline__ uint32_t smem_u32(const void* p)
{
    return (uint32_t)__cvta_generic_to_shared(p);
}
__device__ __forceinline__ void ldm4(uint32_t* r, uint32_t addr)
{
    asm volatile("ldmatrix.sync.aligned.m8n8.x4.shared.b16 {%0,%1,%2,%3}, [%4];"
                 : "=r"(r[0]), "=r"(r[1]), "=r"(r[2]), "=r"(r[3]) : "r"(addr));
}
__device__ __forceinline__ void ldm4t(uint32_t* r, uint32_t addr)
{
    asm volatile("ldmatrix.sync.aligned.m8n8.x4.trans.shared.b16 {%0,%1,%2,%3}, [%4];"
                 : "=r"(r[0]), "=r"(r[1]), "=r"(r[2]), "=r"(r[3]) : "r"(addr));
}
__device__ __forceinline__ void mma_f16(float* c, const uint32_t* a, const uint32_t* b)
{
    asm volatile("mma.sync.aligned.m16n8k16.row.col.f32.f16.f16.f32 "
                 "{%0,%1,%2,%3}, {%4,%5,%6,%7}, {%8,%9}, {%0,%1,%2,%3};"
                 : "+f"(c[0]), "+f"(c[1]), "+f"(c[2]), "+f"(c[3])
                 : "r"(a[0]), "r"(a[1]), "r"(a[2]), "r"(a[3]), "r"(b[0]), "r"(b[1]));
}
__device__ __forceinline__ void cpa16(uint32_t dst, const void* src)
{
    asm volatile("cp.async.cg.shared.global [%0], [%1], 16;" :: "r"(dst), "l"(src));
}
#define CP_COMMIT() asm volatile("cp.async.commit_group;" ::: "memory")
#define CP_WAIT1()  asm volatile("cp.async.wait_group 1;" ::: "memory")
#define CP_WAIT0()  asm volatile("cp.async.wait_group 0;" ::: "memory")

__device__ __forceinline__ uint32_t pack_h2(float a, float b)
{
    __half2 h = __floats2half2_rn(a, b);
    return *(uint32_t*)&h;
}

// ---------------- fp32 -> fp16 converts ---------------------------------------------
__global__ void __launch_bounds__(256) conv_kernel(const float* __restrict__ in,
                                                   __half* __restrict__ o, int n4)
{
    int i = blockIdx.x * 256 + threadIdx.x;
    if (i >= n4) return;
    float4 a = ((const float4*)in)[i];
    ((__half2*)o)[i * 2 + 0] = __floats2half2_rn(a.x, a.y);
    ((__half2*)o)[i * 2 + 1] = __floats2half2_rn(a.z, a.w);
}

__global__ void __launch_bounds__(256) conv4_kernel(
    const float* __restrict__ w0, const float* __restrict__ w1,
    const float* __restrict__ w2, const float* __restrict__ w3,
    __half* __restrict__ o0, __half* __restrict__ o1,
    __half* __restrict__ o2, __half* __restrict__ o3)
{
    const int z = blockIdx.y;
    const float* in = (z == 0) ? w0 : (z == 1) ? w1 : (z == 2) ? w2 : w3;
    __half* o = (z == 0) ? o0 : (z == 1) ? o1 : (z == 2) ? o2 : o3;
    int i = blockIdx.x * 256 + threadIdx.x;
    float4 a = ((const float4*)in)[i];
    ((__half2*)o)[i * 2 + 0] = __floats2half2_rn(a.x, a.y);
    ((__half2*)o)[i * 2 + 1] = __floats2half2_rn(a.z, a.w);
}

// ---------------- fp16 GEMM NT, 128 threads, warp tile 64x64, KT=32 (R14) ----------
#define KTG   32
#define LDSG  40
#define MAT_B (128 * LDSG * 2)
#define STG_B (2 * MAT_B)
#define NSTG  3
#define GSM_TOTAL (NSTG * STG_B)    // 61440 B -> 2 CTAs/SM

template <int EPI>
__global__ void __launch_bounds__(128, 2) gemm_mma2(
    const __half* __restrict__ Ah,
    const __half* __restrict__ B0, const __half* __restrict__ B1,
    const __half* __restrict__ B2,
    const float* __restrict__ bias0, const float* __restrict__ bias1,
    const float* __restrict__ bias2,
    void* O0, void* O1, void* O2,
    const float* __restrict__ resid)
{
    extern __shared__ char smem[];
    const uint32_t sb = smem_u32(smem);

    const int z = blockIdx.z;
    const __half* Bm = (z == 0) ? B0 : (z == 1) ? B1 : B2;
    const float* bias = (z == 0) ? bias0 : (z == 1) ? bias1 : bias2;
    void* Ov = (z == 0) ? O0 : (z == 1) ? O1 : O2;

    const int tid = threadIdx.x;
    const int lane = tid & 31, wid = tid >> 5;
    const int wm = wid >> 1, wn = wid & 1;
    const int bM = blockIdx.y * 128, bN = blockIdx.x * 128;

    float acc[4][8][4] = {};
    const int NK = H_ / KTG;

    const int q8 = lane >> 3, r8 = lane & 7;
    const int arowL = wm * 64 + (q8 & 1) * 8 + r8;
    const int browL = wn * 64 + (q8 >> 1) * 8 + r8;
    const int acolL = (q8 >> 1) * 8;
    const int bcolL = (q8 & 1) * 8;

    auto issue = [&](int kt) {
        const int st = kt % NSTG;
        const uint32_t base = sb + st * STG_B;
        const int k0 = kt * KTG;
#pragma unroll
        for (int j = 0; j < 4; j++) {
            int v = tid + 128 * j;
            int row = v >> 2, c = v & 3;
            uint32_t d = base + (uint32_t)(row * (LDSG * 2) + c * 16);
            cpa16(d,         Ah + (size_t)(bM + row) * H_ + k0 + c * 8);
            cpa16(d + MAT_B, Bm + (size_t)(bN + row) * H_ + k0 + c * 8);
        }
    };

    issue(0); CP_COMMIT();
    issue(1); CP_COMMIT();

    for (int kt = 0; kt < NK; kt++) {
        if (kt + 1 < NK) { CP_WAIT1(); } else { CP_WAIT0(); }
        __syncthreads();
        if (kt + 2 < NK) { issue(kt + 2); CP_COMMIT(); }

        const int st = kt % NSTG;
        const uint32_t bA = sb + st * STG_B;
        const uint32_t bB = bA + MAT_B;

#pragma unroll
        for (int ks = 0; ks < KTG; ks += 16) {
            uint32_t af[4][4];
#pragma unroll
            for (int mt = 0; mt < 4; mt++) {
                const uint32_t ro = (uint32_t)(((arowL + mt * 16) * LDSG + acolL + ks) * 2);
                ldm4(af[mt], bA + ro);
            }
            uint32_t bf[4][4];
#pragma unroll
            for (int p = 0; p < 4; p++) {
                const uint32_t ro = (uint32_t)(((browL + p * 16) * LDSG + bcolL + ks) * 2);
                ldm4(bf[p], bB + ro);
            }
#pragma unroll
            for (int mt = 0; mt < 4; mt++)
#pragma unroll
                for (int nt = 0; nt < 8; nt++)
                    mma_f16(acc[mt][nt], af[mt], &bf[nt >> 1][(nt & 1) * 2]);
        }
    }

    const int crow0 = bM + wm * 64 + (lane >> 2);
    const int ccol0 = bN + wn * 64 + (lane & 3) * 2;
#pragma unroll
    for (int mt = 0; mt < 4; mt++) {
        const int r0 = crow0 + mt * 16;
#pragma unroll
        for (int nt = 0; nt < 8; nt++) {
            const int c0 = ccol0 + nt * 8;
            float f0 = acc[mt][nt][0] + bias[c0];
            float f1 = acc[mt][nt][1] + bias[c0 + 1];
            float f2 = acc[mt][nt][2] + bias[c0];
            float f3 = acc[mt][nt][3] + bias[c0 + 1];
            if (EPI == 1) {
                f0 += resid[(size_t)r0 * H_ + c0];
                f1 += resid[(size_t)r0 * H_ + c0 + 1];
                f2 += resid[(size_t)(r0 + 8) * H_ + c0];
                f3 += resid[(size_t)(r0 + 8) * H_ + c0 + 1];
                float* O = (float*)Ov;
                O[(size_t)r0 * H_ + c0]           = f0;
                O[(size_t)r0 * H_ + c0 + 1]       = f1;
                O[(size_t)(r0 + 8) * H_ + c0]     = f2;
                O[(size_t)(r0 + 8) * H_ + c0 + 1] = f3;
            } else {
                __half* O = (__half*)Ov;
                *(__half2*)(O + (size_t)r0 * H_ + c0)       = __floats2half2_rn(f0, f1);
                *(__half2*)(O + (size_t)(r0 + 8) * H_ + c0) = __floats2half2_rn(f2, f3);
            }
        }
    }
}

// ---------------- fused flash attention: 4 warps, row-private softmax, reg probs ----
#define FQ    0                    // 9216
#define FK    9216                 // 9216
#define FV    18432                // 2 x 9216 double buffer
#define FP    36864                // 18432 (128 x 72 fp16)
#define FS2R  55296                // fp16 [64][200] = 25600
#define FS3B  80896                // fp16 [64][136] = 17408
#define FMASK 98304                // 1024 f32 = 4096
#define FSM_TOTAL 102400

__global__ void __launch_bounds__(128, 2) fused_attn(
    const __half* __restrict__ qh, const __half* __restrict__ kh,
    const __half* __restrict__ vh, const __half* __restrict__ deh,
    const float* __restrict__ mask,
    __half* __restrict__ ch)
{
    extern __shared__ char smem[];
    const uint32_t sb = smem_u32(smem);
    const int tid = threadIdx.x, lane = tid & 31, wid = tid >> 5;  // 4 warps
    const int l0 = blockIdx.x * 64;
    const int bh = blockIdx.y;
    const int b = bh >> 4, h = bh & 15;
    const int hcol = h * D_;

    const int q8 = lane >> 3, r8 = lane & 7;
    const int aRow = (q8 & 1) * 8 + r8, aCol = (q8 >> 1) * 8;
    const int bRow = (q8 >> 1) * 8 + r8, bCol = (q8 & 1) * 8;

    __half* S2r = (__half*)(smem + FS2R);
    __half* S3b = (__half*)(smem + FS3B);
    const float* maskS = (const float*)(smem + FMASK);

    auto cp_t64 = [&](uint32_t dstbase, const __half* src, int growbase) {
#pragma unroll
        for (int j = 0; j < 4; j++) {
            int v = tid + 128 * j;
            int row = v >> 3, c = v & 7;
            cpa16(dstbase + (uint32_t)(row * 72 + c * 8) * 2,
                  src + (size_t)(growbase + row) * H_ + hcol + c * 8);
        }
    };
    auto cp_P = [&](int it) {
        const int prow0 = l0 - it * 64 + 960;
#pragma unroll
        for (int j = 0; j < 8; j++) {
            int v = tid + 128 * j;
            int row = v >> 3, c = v & 7;
            uint32_t off = (uint32_t)(row * 72 + c * 8) * 2;
            if (row < 127) {
                cpa16(sb + FP + off, deh + (size_t)(prow0 + row) * 64 + c * 8);
            } else {
                uint4 zz = {0, 0, 0, 0};
                *(uint4*)(smem + FP + off) = zz;
            }
        }
    };

    // S2 strip: Q[64l] @ P[rbase..rbase+63]^T -> ring cols [csb, csb+64)
    auto s2_strip = [&](int rbase, int csb) {
        float a2[8][4] = {};
#pragma unroll
        for (int ks = 0; ks < 4; ks++) {
            uint32_t aq[4];
            ldm4(aq, sb + FQ + (uint32_t)(((wid * 16 + aRow) * 72) + ks * 16 + aCol) * 2);
            uint32_t pb[4][4];
#pragma unroll
            for (int j = 0; j < 4; j++) {
                uint32_t ro = (uint32_t)(((rbase + j * 16 + bRow) * 72) + ks * 16 + bCol) * 2;
                ldm4(pb[j], sb + FP + ro);
            }
#pragma unroll
            for (int nf = 0; nf < 8; nf++)
                mma_f16(a2[nf], aq, &pb[nf >> 1][(nf & 1) * 2]);
        }
        const int rr = wid * 16 + (lane >> 2);
#pragma unroll
        for (int nf = 0; nf < 8; nf++) {
            const int cc = csb + nf * 8 + (lane & 3) * 2;
            *(__half2*)&S2r[rr * 200 + cc] = __floats2half2_rn(a2[nf][0], a2[nf][1]);
            *(__half2*)&S2r[(rr + 8) * 200 + cc] = __floats2half2_rn(a2[nf][2], a2[nf][3]);
        }
    };

    // prologue: group0 = {Q, K0, P0, mask}, group1 = {V0 -> buf0}
    cp_t64(sb + FQ, qh, b * S_ + l0);
    cp_t64(sb + FK, kh, b * S_ + 0);
    cp_P(0);
#pragma unroll
    for (int j = 0; j < 2; j++) {
        int v = tid + 128 * j;
        cpa16(sb + FMASK + v * 16, mask + (size_t)b * S_ + v * 4);
    }
    CP_COMMIT();
    cp_t64(sb + FV, vh, b * S_ + 0);
    CP_COMMIT();

    float O[8][4] = {};
    float mrunA = -1e30f, mrunB = -1e30f;
    float srunA = 0.f, srunB = 0.f;
    const int la = lane >> 2;                  // row within warp tile
    const int lrow = wid * 16 + la;            // l-row (0..63)

    for (int it = 0; it < 16; it++) {
        CP_WAIT1();
        __syncthreads();                       // KP(it) ready

        const int prow0 = l0 - it * 64 + 960;
        const int csb = prow0 % 192;

        // ---- S1 = Q(own 16 rows) @ K^T (64 cols) ----
        float accS[8][4] = {};
#pragma unroll
        for (int ks = 0; ks < 4; ks++) {
            uint32_t aq[4];
            ldm4(aq, sb + FQ + (uint32_t)(((wid * 16 + aRow) * 72) + ks * 16 + aCol) * 2);
            uint32_t kb[4][4];
#pragma unroll
            for (int j = 0; j < 4; j++) {
                uint32_t ro = (uint32_t)(((j * 16 + bRow) * 72) + ks * 16 + bCol) * 2;
                ldm4(kb[j], sb + FK + ro);
            }
#pragma unroll
            for (int nf = 0; nf < 8; nf++)
                mma_f16(accS[nf], aq, &kb[nf >> 1][(nf & 1) * 2]);
        }

        // ---- S2 strips (incremental ring) ----
        if (it == 0) s2_strip(64, (csb + 64) % 192);
        s2_strip(0, csb);

        // ---- S3 = K(own 16 r-rows) @ P^T (128 t), two t-halves ----
#pragma unroll
        for (int th = 0; th < 2; th++) {
            float a3[8][4] = {};
#pragma unroll
            for (int ks = 0; ks < 4; ks++) {
                uint32_t ak[4];
                ldm4(ak, sb + FK + (uint32_t)(((wid * 16 + aRow) * 72) + ks * 16 + aCol) * 2);
                uint32_t pb[4][4];
#pragma unroll
                for (int j = 0; j < 4; j++) {
                    uint32_t ro = (uint32_t)(((th * 64 + j * 16 + bRow) * 72) + ks * 16 + bCol) * 2;
                    ldm4(pb[j], sb + FP + ro);
                }
#pragma unroll
                for (int nf = 0; nf < 8; nf++)
                    mma_f16(a3[nf], ak, &pb[nf >> 1][(nf & 1) * 2]);
            }
            const int rr = wid * 16 + la;
#pragma unroll
            for (int nf = 0; nf < 8; nf++) {
                const int cc = th * 64 + nf * 8 + (lane & 3) * 2;
                *(__half2*)&S3b[rr * 136 + cc] = __floats2half2_rn(a3[nf][0], a3[nf][1]);
                *(__half2*)&S3b[(rr + 8) * 136 + cc] = __floats2half2_rn(a3[nf][2], a3[nf][3]);
            }
        }
        __syncthreads();                       // staging visible; K,P consumed

        if (it < 15) {
            cp_t64(sb + FK, kh, b * S_ + (it + 1) * 64);
            cp_P(it + 1);
            CP_COMMIT();
        }

        // ---- gather + mask + scale (into accS in place) ----
#pragma unroll
        for (int nf = 0; nf < 8; nf++) {
            const int c0 = nf * 8 + (lane & 3) * 2;
            const int t0 = lrow - c0 + 63;
            int ca = csb + t0;        if (ca >= 192) ca -= 192;
            int cb = csb + t0 - 1;    if (cb < 0) cb += 192; else if (cb >= 192) cb -= 192;
            int cc = csb + t0 + 8;    if (cc >= 192) cc -= 192;
            int cd = csb + t0 + 7;    if (cd >= 192) cd -= 192;
            const float mk0 = maskS[it * 64 + c0];
            const float mk1 = maskS[it * 64 + c0 + 1];
            float s2a = __half2float(S2r[lrow * 200 + ca]);
            float s2b_ = __half2float(S2r[lrow * 200 + cb]);
            float s2c = __half2float(S2r[(lrow + 8) * 200 + cc]);
            float s2d = __half2float(S2r[(lrow + 8) * 200 + cd]);
            float s3a = __half2float(S3b[c0 * 136 + t0]);
            float s3b_ = __half2float(S3b[(c0 + 1) * 136 + t0 - 1]);
            float s3c = __half2float(S3b[c0 * 136 + t0 + 8]);
            float s3d = __half2float(S3b[(c0 + 1) * 136 + t0 + 7]);
            accS[nf][0] = (accS[nf][0] + s2a + s3a) * 0.125f + mk0;
            accS[nf][1] = (accS[nf][1] + s2b_ + s3b_) * 0.125f + mk1;
            accS[nf][2] = (accS[nf][2] + s2c + s3c) * 0.125f + mk0;
            accS[nf][3] = (accS[nf][3] + s2d + s3d) * 0.125f + mk1;
        }

        // ---- warp-private online softmax (rows owned by this warp) ----
        float mA = -1e30f, mB = -1e30f;
#pragma unroll
        for (int nf = 0; nf < 8; nf++) {
            mA = fmaxf(mA, fmaxf(accS[nf][0], accS[nf][1]));
            mB = fmaxf(mB, fmaxf(accS[nf][2], accS[nf][3]));
        }
        mA = fmaxf(mA, __shfl_xor_sync(~0u, mA, 1));
        mA = fmaxf(mA, __shfl_xor_sync(~0u, mA, 2));
        mB = fmaxf(mB, __shfl_xor_sync(~0u, mB, 1));
        mB = fmaxf(mB, __shfl_xor_sync(~0u, mB, 2));

        const float mnA = fmaxf(mrunA, mA), mnB = fmaxf(mrunB, mB);
        const float sclA = __expf(mrunA - mnA), sclB = __expf(mrunB - mnB);
        mrunA = mnA; mrunB = mnB;
#pragma unroll
        for (int nf = 0; nf < 8; nf++) {
            O[nf][0] *= sclA; O[nf][1] *= sclA;
            O[nf][2] *= sclB; O[nf][3] *= sclB;
        }

        float suA = 0.f, suB = 0.f;
#pragma unroll
        for (int nf = 0; nf < 8; nf++) {
            accS[nf][0] = __expf(accS[nf][0] - mnA);
            accS[nf][1] = __expf(accS[nf][1] - mnA);
            accS[nf][2] = __expf(accS[nf][2] - mnB);
            accS[nf][3] = __expf(accS[nf][3] - mnB);
            suA += accS[nf][0] + accS[nf][1];
            suB += accS[nf][2] + accS[nf][3];
        }
        suA += __shfl_xor_sync(~0u, suA, 1);
        suA += __shfl_xor_sync(~0u, suA, 2);
        suB += __shfl_xor_sync(~0u, suB, 1);
        suB += __shfl_xor_sync(~0u, suB, 2);
        srunA = srunA * sclA + suA;
        srunB = srunB * sclB + suB;

        // ---- pack probs: C-frag -> A-frag (register only) ----
        uint32_t pa[4][4];
#pragma unroll
        for (int kg = 0; kg < 4; kg++) {
            pa[kg][0] = pack_h2(accS[2 * kg][0],     accS[2 * kg][1]);
            pa[kg][1] = pack_h2(accS[2 * kg][2],     accS[2 * kg][3]);
            pa[kg][2] = pack_h2(accS[2 * kg + 1][0], accS[2 * kg + 1][1]);
            pa[kg][3] = pack_h2(accS[2 * kg + 1][2], accS[2 * kg + 1][3]);
        }

        // ---- V(it) ready ----
        if (it < 15) { CP_WAIT1(); } else { CP_WAIT0(); }
        __syncthreads();

        const uint32_t Vb = sb + FV + (uint32_t)(it & 1) * 9216;
        // ---- O += P @ V ----
#pragma unroll
        for (int kg = 0; kg < 4; kg++) {
            uint32_t vb[4][4];
#pragma unroll
            for (int j = 0; j < 4; j++) {
                uint32_t ro = (uint32_t)(((kg * 16 + aRow) * 72) + j * 16 + aCol) * 2;
                ldm4t(vb[j], Vb + ro);
            }
#pragma unroll
            for (int nf = 0; nf < 8; nf++)
                mma_f16(O[nf], pa[kg], &vb[nf >> 1][(nf & 1) * 2]);
        }

        if (it < 15) {
            cp_t64(sb + FV + (uint32_t)((it + 1) & 1) * 9216, vh, b * S_ + (it + 1) * 64);
            CP_COMMIT();
        }
    }

    // ---- epilogue: ctx fp16 ----
    const float iA = 1.f / srunA, iB = 1.f / srunB;
#pragma unroll
    for (int nf = 0; nf < 8; nf++) {
        const int col = hcol + nf * 8 + (lane & 3) * 2;
        const size_t rowA = (size_t)(b * S_ + l0 + lrow) * H_ + col;
        const size_t rowB = (size_t)(b * S_ + l0 + lrow + 8) * H_ + col;
        *(__half2*)(ch + rowA) = __floats2half2_rn(O[nf][0] * iA, O[nf][1] * iA);
        *(__half2*)(ch + rowB) = __floats2half2_rn(O[nf][2] * iB, O[nf][3] * iB);
    }
}

// ---------------- LayerNorm ----------------------------------------------------------
__global__ void __launch_bounds__(256) ln_kernel(const float* __restrict__ y,
                                                 const float* __restrict__ g,
                                                 const float* __restrict__ bb,
                                                 float* __restrict__ out)
{
    __shared__ float sred[8];
    __shared__ float sbc;
    const size_t row = blockIdx.x;
    const int tid = threadIdx.x;
    const int lane = tid & 31, wid = tid >> 5;

    float4 v = ((const float4*)(y + row * H_))[tid];

    float s = v.x + v.y + v.z + v.w;
#pragma unroll
    for (int o = 16; o > 0; o >>= 1) s += __shfl_xor_sync(~0u, s, o);
    if (lane == 0) sred[wid] = s;
    __syncthreads();
    if (tid == 0) {
        float t = 0.f;
#pragma unroll
        for (int i = 0; i < 8; i++) t += sred[i];
        sbc = t;
    }
    __syncthreads();
    const float mu = sbc * (1.f / H_);

    float dx = v.x - mu, dy = v.y - mu, dz = v.z - mu, dw = v.w - mu;
    float qq = dx * dx + dy * dy + dz * dz + dw * dw;
#pragma unroll
    for (int o = 16; o > 0; o >>= 1) qq += __shfl_xor_sync(~0u, qq, o);
    if (lane == 0) sred[wid] = qq;
    __syncthreads();
    if (tid == 0) {
        float t = 0.f;
#pragma unroll
        for (int i = 0; i < 8; i++) t += sred[i];
        sbc = t;
    }
    __syncthreads();
    const float rstd = rsqrtf(sbc * (1.f / H_) + 1e-12f);

    float4 gg = ((const float4*)g)[tid];
    float4 bt = ((const float4*)bb)[tid];
    float4 o;
    o.x = dx * rstd * gg.x + bt.x;
    o.y = dy * rstd * gg.y + bt.y;
    o.z = dz * rstd * gg.z + bt.z;
    o.w = dw * rstd * gg.w + bt.w;
    ((float4*)(out + row * H_))[tid] = o;
}

// ---------------- launch -----------------------------------------------------------
extern "C" void kernel_launch(void* const* d_in, const int* in_sizes, int n_in,
                              void* d_out, int out_size)
{
    (void)in_sizes; (void)n_in; (void)out_size;
    const float* x    = (const float*)d_in[0];
    const float* mask = (const float*)d_in[1];
    const float* Wq   = (const float*)d_in[2];
    const float* bq   = (const float*)d_in[3];
    const float* Wk   = (const float*)d_in[4];
    const float* bk   = (const float*)d_in[5];
    const float* Wv   = (const float*)d_in[6];
    const float* bv   = (const float*)d_in[7];
    const float* de   = (const float*)d_in[8];
    const float* Wo   = (const float*)d_in[9];
    const float* bo   = (const float*)d_in[10];
    const float* lng  = (const float*)d_in[11];
    const float* lnb  = (const float*)d_in[12];
    float* out = (float*)d_out;

    float* y;
    cudaGetSymbolAddress((void**)&y, g_y);

    __half *xh, *wq, *wk, *wv, *wo, *qh, *kh, *vh, *deh, *ch;
    cudaGetSymbolAddress((void**)&xh, g_xh);
    cudaGetSymbolAddress((void**)&wq, g_wq);
    cudaGetSymbolAddress((void**)&wk, g_wk);
    cudaGetSymbolAddress((void**)&wv, g_wv);
    cudaGetSymbolAddress((void**)&wo, g_wo);
    cudaGetSymbolAddress((void**)&qh, g_qh);
    cudaGetSymbolAddress((void**)&kh, g_kh);
    cudaGetSymbolAddress((void**)&vh, g_vh);
    cudaGetSymbolAddress((void**)&deh, g_de);
    cudaGetSymbolAddress((void**)&ch, g_ch);

    cudaFuncSetAttribute(gemm_mma2<1>, cudaFuncAttributeMaxDynamicSharedMemorySize, GSM_TOTAL);
    cudaFuncSetAttribute(gemm_mma2<2>, cudaFuncAttributeMaxDynamicSharedMemorySize, GSM_TOTAL);
    cudaFuncSetAttribute(fused_attn, cudaFuncAttributeMaxDynamicSharedMemorySize, FSM_TOTAL);

    const int NX4 = BS_ * H_ / 4;
    const int NW4 = H_ * H_ / 4;
    conv_kernel<<<NX4 / 256, 256>>>(x, xh, NX4);
    conv4_kernel<<<dim3(NW4 / 256, 4), 256>>>(Wq, Wk, Wv, Wo, wq, wk, wv, wo);
    const int ND4 = 2047 * 64 / 4;
    conv_kernel<<<(ND4 + 255) / 256, 256>>>(de, deh, ND4);

    gemm_mma2<2><<<dim3(H_ / 128, BS_ / 128, 3), 128, GSM_TOTAL>>>(
        xh, wq, wk, wv, bq, bk, bv, qh, kh, vh, nullptr);

    fused_attn<<<dim3(S_ / 64, BH_), 128, FSM_TOTAL>>>(
        qh, kh, vh, deh, mask, ch);

    gemm_mma2<1><<<dim3(H_ / 128, BS_ / 128, 1), 128, GSM_TOTAL>>>(
        ch, wo, wo, wo, bo, bo, bo, y, y, y, x);

    ln_kernel<<<BS_, 256>>>(y, lng, lnb, out);
}

// round 16
// speedup vs baseline: 2.9369x; 1.0052x over previous
#include <cuda_runtime.h>
#include <cuda_fp16.h>
#include <cstdint>

#define S_   1024
#define H_   1024
#define B_   4
#define NH_  16
#define D_   64
#define BS_  4096
#define BH_  64

// ---------------- scratch (no allocs allowed) ----------------
__device__ float g_y[BS_ * H_];

__device__ __half g_xh[BS_ * H_];
__device__ __half g_wq[H_ * H_], g_wk[H_ * H_], g_wv[H_ * H_], g_wo[H_ * H_];
__device__ __half g_qh[BS_ * H_], g_kh[BS_ * H_], g_vh[BS_ * H_];
__device__ __half g_de[2047 * 64];
__device__ __half g_ch[BS_ * H_];

// ---------------- helpers -------------------------------------------------------
__device__ __forceinline__ uint32_t smem_u32(const void* p)
{
    return (uint32_t)__cvta_generic_to_shared(p);
}
__device__ __forceinline__ void ldm4(uint32_t* r, uint32_t addr)
{
    asm volatile("ldmatrix.sync.aligned.m8n8.x4.shared.b16 {%0,%1,%2,%3}, [%4];"
                 : "=r"(r[0]), "=r"(r[1]), "=r"(r[2]), "=r"(r[3]) : "r"(addr));
}
__device__ __forceinline__ void ldm4t(uint32_t* r, uint32_t addr)
{
    asm volatile("ldmatrix.sync.aligned.m8n8.x4.trans.shared.b16 {%0,%1,%2,%3}, [%4];"
                 : "=r"(r[0]), "=r"(r[1]), "=r"(r[2]), "=r"(r[3]) : "r"(addr));
}
__device__ __forceinline__ void mma_f16(float* c, const uint32_t* a, const uint32_t* b)
{
    asm volatile("mma.sync.aligned.m16n8k16.row.col.f32.f16.f16.f32 "
                 "{%0,%1,%2,%3}, {%4,%5,%6,%7}, {%8,%9}, {%0,%1,%2,%3};"
                 : "+f"(c[0]), "+f"(c[1]), "+f"(c[2]), "+f"(c[3])
                 : "r"(a[0]), "r"(a[1]), "r"(a[2]), "r"(a[3]), "r"(b[0]), "r"(b[1]));
}
__device__ __forceinline__ void cpa16(uint32_t dst, const void* src)
{
    asm volatile("cp.async.cg.shared.global [%0], [%1], 16;" :: "r"(dst), "l"(src));
}
#define CP_COMMIT() asm volatile("cp.async.commit_group;" ::: "memory")
#define CP_WAIT2()  asm volatile("cp.async.wait_group 2;" ::: "memory")
#define CP_WAIT1()  asm volatile("cp.async.wait_group 1;" ::: "memory")
#define CP_WAIT0()  asm volatile("cp.async.wait_group 0;" ::: "memory")

__device__ __forceinline__ uint32_t pack_h2(float a, float b)
{
    __half2 h = __floats2half2_rn(a, b);
    return *(uint32_t*)&h;
}

// ---------------- fp32 -> fp16 converts ---------------------------------------------
__global__ void __launch_bounds__(256) conv_kernel(const float* __restrict__ in,
                                                   __half* __restrict__ o, int n4)
{
    int i = blockIdx.x * 256 + threadIdx.x;
    if (i >= n4) return;
    float4 a = ((const float4*)in)[i];
    ((__half2*)o)[i * 2 + 0] = __floats2half2_rn(a.x, a.y);
    ((__half2*)o)[i * 2 + 1] = __floats2half2_rn(a.z, a.w);
}

__global__ void __launch_bounds__(256) conv4_kernel(
    const float* __restrict__ w0, const float* __restrict__ w1,
    const float* __restrict__ w2, const float* __restrict__ w3,
    __half* __restrict__ o0, __half* __restrict__ o1,
    __half* __restrict__ o2, __half* __restrict__ o3)
{
    const int z = blockIdx.y;
    const float* in = (z == 0) ? w0 : (z == 1) ? w1 : (z == 2) ? w2 : w3;
    __half* o = (z == 0) ? o0 : (z == 1) ? o1 : (z == 2) ? o2 : o3;
    int i = blockIdx.x * 256 + threadIdx.x;
    float4 a = ((const float4*)in)[i];
    ((__half2*)o)[i * 2 + 0] = __floats2half2_rn(a.x, a.y);
    ((__half2*)o)[i * 2 + 1] = __floats2half2_rn(a.z, a.w);
}

// ---------------- fp16 GEMM NT, 128 threads, warp tile 64x64, KT=32, 4 stages ------
#define KTG   32
#define LDSG  40
#define MAT_B (128 * LDSG * 2)
#define STG_B (2 * MAT_B)
#define NSTG  4
#define GSM_TOTAL (NSTG * STG_B)    // 81920 B -> 2 CTAs/SM

template <int EPI>
__global__ void __launch_bounds__(128, 2) gemm_mma2(
    const __half* __restrict__ Ah,
    const __half* __restrict__ B0, const __half* __restrict__ B1,
    const __half* __restrict__ B2,
    const float* __restrict__ bias0, const float* __restrict__ bias1,
    const float* __restrict__ bias2,
    void* O0, void* O1, void* O2,
    const float* __restrict__ resid)
{
    extern __shared__ char smem[];
    const uint32_t sb = smem_u32(smem);

    const int z = blockIdx.z;
    const __half* Bm = (z == 0) ? B0 : (z == 1) ? B1 : B2;
    const float* bias = (z == 0) ? bias0 : (z == 1) ? bias1 : bias2;
    void* Ov = (z == 0) ? O0 : (z == 1) ? O1 : O2;

    const int tid = threadIdx.x;
    const int lane = tid & 31, wid = tid >> 5;
    const int wm = wid >> 1, wn = wid & 1;
    const int bM = blockIdx.y * 128, bN = blockIdx.x * 128;

    float acc[4][8][4] = {};
    const int NK = H_ / KTG;

    const int q8 = lane >> 3, r8 = lane & 7;
    const int arowL = wm * 64 + (q8 & 1) * 8 + r8;
    const int browL = wn * 64 + (q8 >> 1) * 8 + r8;
    const int acolL = (q8 >> 1) * 8;
    const int bcolL = (q8 & 1) * 8;

    auto issue = [&](int kt) {
        const int st = kt % NSTG;
        const uint32_t base = sb + st * STG_B;
        const int k0 = kt * KTG;
#pragma unroll
        for (int j = 0; j < 4; j++) {
            int v = tid + 128 * j;
            int row = v >> 2, c = v & 3;
            uint32_t d = base + (uint32_t)(row * (LDSG * 2) + c * 16);
            cpa16(d,         Ah + (size_t)(bM + row) * H_ + k0 + c * 8);
            cpa16(d + MAT_B, Bm + (size_t)(bN + row) * H_ + k0 + c * 8);
        }
    };

    issue(0); CP_COMMIT();
    issue(1); CP_COMMIT();
    issue(2); CP_COMMIT();

    for (int kt = 0; kt < NK; kt++) {
        if (kt + 2 < NK) { CP_WAIT2(); }
        else if (kt + 1 < NK) { CP_WAIT1(); }
        else { CP_WAIT0(); }
        __syncthreads();
        if (kt + 3 < NK) { issue(kt + 3); CP_COMMIT(); }

        const int st = kt % NSTG;
        const uint32_t bA = sb + st * STG_B;
        const uint32_t bB = bA + MAT_B;

#pragma unroll
        for (int ks = 0; ks < KTG; ks += 16) {
            uint32_t af[4][4];
#pragma unroll
            for (int mt = 0; mt < 4; mt++) {
                const uint32_t ro = (uint32_t)(((arowL + mt * 16) * LDSG + acolL + ks) * 2);
                ldm4(af[mt], bA + ro);
            }
            uint32_t bf[4][4];
#pragma unroll
            for (int p = 0; p < 4; p++) {
                const uint32_t ro = (uint32_t)(((browL + p * 16) * LDSG + bcolL + ks) * 2);
                ldm4(bf[p], bB + ro);
            }
#pragma unroll
            for (int mt = 0; mt < 4; mt++)
#pragma unroll
                for (int nt = 0; nt < 8; nt++)
                    mma_f16(acc[mt][nt], af[mt], &bf[nt >> 1][(nt & 1) * 2]);
        }
    }

    const int crow0 = bM + wm * 64 + (lane >> 2);
    const int ccol0 = bN + wn * 64 + (lane & 3) * 2;
#pragma unroll
    for (int mt = 0; mt < 4; mt++) {
        const int r0 = crow0 + mt * 16;
#pragma unroll
        for (int nt = 0; nt < 8; nt++) {
            const int c0 = ccol0 + nt * 8;
            float f0 = acc[mt][nt][0] + bias[c0];
            float f1 = acc[mt][nt][1] + bias[c0 + 1];
            float f2 = acc[mt][nt][2] + bias[c0];
            float f3 = acc[mt][nt][3] + bias[c0 + 1];
            if (EPI == 1) {
                f0 += resid[(size_t)r0 * H_ + c0];
                f1 += resid[(size_t)r0 * H_ + c0 + 1];
                f2 += resid[(size_t)(r0 + 8) * H_ + c0];
                f3 += resid[(size_t)(r0 + 8) * H_ + c0 + 1];
                float* O = (float*)Ov;
                O[(size_t)r0 * H_ + c0]           = f0;
                O[(size_t)r0 * H_ + c0 + 1]       = f1;
                O[(size_t)(r0 + 8) * H_ + c0]     = f2;
                O[(size_t)(r0 + 8) * H_ + c0 + 1] = f3;
            } else {
                __half* O = (__half*)Ov;
                *(__half2*)(O + (size_t)r0 * H_ + c0)       = __floats2half2_rn(f0, f1);
                *(__half2*)(O + (size_t)(r0 + 8) * H_ + c0) = __floats2half2_rn(f2, f3);
            }
        }
    }
}

// ---------------- fused flash attention (R15, unchanged) ---------------------------
#define FQ    0
#define FK    9216
#define FV    18432                // 2 x 9216 double buffer
#define FP    36864
#define FS2R  55296                // fp16 [64][200] = 25600
#define FS3B  80896                // fp16 [64][136] = 17408
#define FMASK 98304
#define FSM_TOTAL 102400

__global__ void __launch_bounds__(128, 2) fused_attn(
    const __half* __restrict__ qh, const __half* __restrict__ kh,
    const __half* __restrict__ vh, const __half* __restrict__ deh,
    const float* __restrict__ mask,
    __half* __restrict__ ch)
{
    extern __shared__ char smem[];
    const uint32_t sb = smem_u32(smem);
    const int tid = threadIdx.x, lane = tid & 31, wid = tid >> 5;
    const int l0 = blockIdx.x * 64;
    const int bh = blockIdx.y;
    const int b = bh >> 4, h = bh & 15;
    const int hcol = h * D_;

    const int q8 = lane >> 3, r8 = lane & 7;
    const int aRow = (q8 & 1) * 8 + r8, aCol = (q8 >> 1) * 8;
    const int bRow = (q8 >> 1) * 8 + r8, bCol = (q8 & 1) * 8;

    __half* S2r = (__half*)(smem + FS2R);
    __half* S3b = (__half*)(smem + FS3B);
    const float* maskS = (const float*)(smem + FMASK);

    auto cp_t64 = [&](uint32_t dstbase, const __half* src, int growbase) {
#pragma unroll
        for (int j = 0; j < 4; j++) {
            int v = tid + 128 * j;
            int row = v >> 3, c = v & 7;
            cpa16(dstbase + (uint32_t)(row * 72 + c * 8) * 2,
                  src + (size_t)(growbase + row) * H_ + hcol + c * 8);
        }
    };
    auto cp_P = [&](int it) {
        const int prow0 = l0 - it * 64 + 960;
#pragma unroll
        for (int j = 0; j < 8; j++) {
            int v = tid + 128 * j;
            int row = v >> 3, c = v & 7;
            uint32_t off = (uint32_t)(row * 72 + c * 8) * 2;
            if (row < 127) {
                cpa16(sb + FP + off, deh + (size_t)(prow0 + row) * 64 + c * 8);
            } else {
                uint4 zz = {0, 0, 0, 0};
                *(uint4*)(smem + FP + off) = zz;
            }
        }
    };

    auto s2_strip = [&](int rbase, int csb) {
        float a2[8][4] = {};
#pragma unroll
        for (int ks = 0; ks < 4; ks++) {
            uint32_t aq[4];
            ldm4(aq, sb + FQ + (uint32_t)(((wid * 16 + aRow) * 72) + ks * 16 + aCol) * 2);
            uint32_t pb[4][4];
#pragma unroll
            for (int j = 0; j < 4; j++) {
                uint32_t ro = (uint32_t)(((rbase + j * 16 + bRow) * 72) + ks * 16 + bCol) * 2;
                ldm4(pb[j], sb + FP + ro);
            }
#pragma unroll
            for (int nf = 0; nf < 8; nf++)
                mma_f16(a2[nf], aq, &pb[nf >> 1][(nf & 1) * 2]);
        }
        const int rr = wid * 16 + (lane >> 2);
#pragma unroll
        for (int nf = 0; nf < 8; nf++) {
            const int cc = csb + nf * 8 + (lane & 3) * 2;
            *(__half2*)&S2r[rr * 200 + cc] = __floats2half2_rn(a2[nf][0], a2[nf][1]);
            *(__half2*)&S2r[(rr + 8) * 200 + cc] = __floats2half2_rn(a2[nf][2], a2[nf][3]);
        }
    };

    cp_t64(sb + FQ, qh, b * S_ + l0);
    cp_t64(sb + FK, kh, b * S_ + 0);
    cp_P(0);
#pragma unroll
    for (int j = 0; j < 2; j++) {
        int v = tid + 128 * j;
        cpa16(sb + FMASK + v * 16, mask + (size_t)b * S_ + v * 4);
    }
    CP_COMMIT();
    cp_t64(sb + FV, vh, b * S_ + 0);
    CP_COMMIT();

    float O[8][4] = {};
    float mrunA = -1e30f, mrunB = -1e30f;
    float srunA = 0.f, srunB = 0.f;
    const int la = lane >> 2;
    const int lrow = wid * 16 + la;

    for (int it = 0; it < 16; it++) {
        CP_WAIT1();
        __syncthreads();

        const int prow0 = l0 - it * 64 + 960;
        const int csb = prow0 % 192;

        float accS[8][4] = {};
#pragma unroll
        for (int ks = 0; ks < 4; ks++) {
            uint32_t aq[4];
            ldm4(aq, sb + FQ + (uint32_t)(((wid * 16 + aRow) * 72) + ks * 16 + aCol) * 2);
            uint32_t kb[4][4];
#pragma unroll
            for (int j = 0; j < 4; j++) {
                uint32_t ro = (uint32_t)(((j * 16 + bRow) * 72) + ks * 16 + bCol) * 2;
                ldm4(kb[j], sb + FK + ro);
            }
#pragma unroll
            for (int nf = 0; nf < 8; nf++)
                mma_f16(accS[nf], aq, &kb[nf >> 1][(nf & 1) * 2]);
        }

        if (it == 0) s2_strip(64, (csb + 64) % 192);
        s2_strip(0, csb);

#pragma unroll
        for (int th = 0; th < 2; th++) {
            float a3[8][4] = {};
#pragma unroll
            for (int ks = 0; ks < 4; ks++) {
                uint32_t ak[4];
                ldm4(ak, sb + FK + (uint32_t)(((wid * 16 + aRow) * 72) + ks * 16 + aCol) * 2);
                uint32_t pb[4][4];
#pragma unroll
                for (int j = 0; j < 4; j++) {
                    uint32_t ro = (uint32_t)(((th * 64 + j * 16 + bRow) * 72) + ks * 16 + bCol) * 2;
                    ldm4(pb[j], sb + FP + ro);
                }
#pragma unroll
                for (int nf = 0; nf < 8; nf++)
                    mma_f16(a3[nf], ak, &pb[nf >> 1][(nf & 1) * 2]);
            }
            const int rr = wid * 16 + la;
#pragma unroll
            for (int nf = 0; nf < 8; nf++) {
                const int cc = th * 64 + nf * 8 + (lane & 3) * 2;
                *(__half2*)&S3b[rr * 136 + cc] = __floats2half2_rn(a3[nf][0], a3[nf][1]);
                *(__half2*)&S3b[(rr + 8) * 136 + cc] = __floats2half2_rn(a3[nf][2], a3[nf][3]);
            }
        }
        __syncthreads();

        if (it < 15) {
            cp_t64(sb + FK, kh, b * S_ + (it + 1) * 64);
            cp_P(it + 1);
            CP_COMMIT();
        }

#pragma unroll
        for (int nf = 0; nf < 8; nf++) {
            const int c0 = nf * 8 + (lane & 3) * 2;
            const int t0 = lrow - c0 + 63;
            int ca = csb + t0;        if (ca >= 192) ca -= 192;
            int cb = csb + t0 - 1;    if (cb < 0) cb += 192; else if (cb >= 192) cb -= 192;
            int cc = csb + t0 + 8;    if (cc >= 192) cc -= 192;
            int cd = csb + t0 + 7;    if (cd >= 192) cd -= 192;
            const float mk0 = maskS[it * 64 + c0];
            const float mk1 = maskS[it * 64 + c0 + 1];
            float s2a = __half2float(S2r[lrow * 200 + ca]);
            float s2b_ = __half2float(S2r[lrow * 200 + cb]);
            float s2c = __half2float(S2r[(lrow + 8) * 200 + cc]);
            float s2d = __half2float(S2r[(lrow + 8) * 200 + cd]);
            float s3a = __half2float(S3b[c0 * 136 + t0]);
            float s3b_ = __half2float(S3b[(c0 + 1) * 136 + t0 - 1]);
            float s3c = __half2float(S3b[c0 * 136 + t0 + 8]);
            float s3d = __half2float(S3b[(c0 + 1) * 136 + t0 + 7]);
            accS[nf][0] = (accS[nf][0] + s2a + s3a) * 0.125f + mk0;
            accS[nf][1] = (accS[nf][1] + s2b_ + s3b_) * 0.125f + mk1;
            accS[nf][2] = (accS[nf][2] + s2c + s3c) * 0.125f + mk0;
            accS[nf][3] = (accS[nf][3] + s2d + s3d) * 0.125f + mk1;
        }

        float mA = -1e30f, mB = -1e30f;
#pragma unroll
        for (int nf = 0; nf < 8; nf++) {
            mA = fmaxf(mA, fmaxf(accS[nf][0], accS[nf][1]));
            mB = fmaxf(mB, fmaxf(accS[nf][2], accS[nf][3]));
        }
        mA = fmaxf(mA, __shfl_xor_sync(~0u, mA, 1));
        mA = fmaxf(mA, __shfl_xor_sync(~0u, mA, 2));
        mB = fmaxf(mB, __shfl_xor_sync(~0u, mB, 1));
        mB = fmaxf(mB, __shfl_xor_sync(~0u, mB, 2));

        const float mnA = fmaxf(mrunA, mA), mnB = fmaxf(mrunB, mB);
        const float sclA = __expf(mrunA - mnA), sclB = __expf(mrunB - mnB);
        mrunA = mnA; mrunB = mnB;
#pragma unroll
        for (int nf = 0; nf < 8; nf++) {
            O[nf][0] *= sclA; O[nf][1] *= sclA;
            O[nf][2] *= sclB; O[nf][3] *= sclB;
        }

        float suA = 0.f, suB = 0.f;
#pragma unroll
        for (int nf = 0; nf < 8; nf++) {
            accS[nf][0] = __expf(accS[nf][0] - mnA);
            accS[nf][1] = __expf(accS[nf][1] - mnA);
            accS[nf][2] = __expf(accS[nf][2] - mnB);
            accS[nf][3] = __expf(accS[nf][3] - mnB);
            suA += accS[nf][0] + accS[nf][1];
            suB += accS[nf][2] + accS[nf][3];
        }
        suA += __shfl_xor_sync(~0u, suA, 1);
        suA += __shfl_xor_sync(~0u, suA, 2);
        suB += __shfl_xor_sync(~0u, suB, 1);
        suB += __shfl_xor_sync(~0u, suB, 2);
        srunA = srunA * sclA + suA;
        srunB = srunB * sclB + suB;

        uint32_t pa[4][4];
#pragma unroll
        for (int kg = 0; kg < 4; kg++) {
            pa[kg][0] = pack_h2(accS[2 * kg][0],     accS[2 * kg][1]);
            pa[kg][1] = pack_h2(accS[2 * kg][2],     accS[2 * kg][3]);
            pa[kg][2] = pack_h2(accS[2 * kg + 1][0], accS[2 * kg + 1][1]);
            pa[kg][3] = pack_h2(accS[2 * kg + 1][2], accS[2 * kg + 1][3]);
        }

        if (it < 15) { CP_WAIT1(); } else { CP_WAIT0(); }
        __syncthreads();

        const uint32_t Vb = sb + FV + (uint32_t)(it & 1) * 9216;
#pragma unroll
        for (int kg = 0; kg < 4; kg++) {
            uint32_t vb[4][4];
#pragma unroll
            for (int j = 0; j < 4; j++) {
                uint32_t ro = (uint32_t)(((kg * 16 + aRow) * 72) + j * 16 + aCol) * 2;
                ldm4t(vb[j], Vb + ro);
            }
#pragma unroll
            for (int nf = 0; nf < 8; nf++)
                mma_f16(O[nf], pa[kg], &vb[nf >> 1][(nf & 1) * 2]);
        }

        if (it < 15) {
            cp_t64(sb + FV + (uint32_t)((it + 1) & 1) * 9216, vh, b * S_ + (it + 1) * 64);
            CP_COMMIT();
        }
    }

    const float iA = 1.f / srunA, iB = 1.f / srunB;
#pragma unroll
    for (int nf = 0; nf < 8; nf++) {
        const int col = hcol + nf * 8 + (lane & 3) * 2;
        const size_t rowA = (size_t)(b * S_ + l0 + lrow) * H_ + col;
        const size_t rowB = (size_t)(b * S_ + l0 + lrow + 8) * H_ + col;
        *(__half2*)(ch + rowA) = __floats2half2_rn(O[nf][0] * iA, O[nf][1] * iA);
        *(__half2*)(ch + rowB) = __floats2half2_rn(O[nf][2] * iB, O[nf][3] * iB);
    }
}

// ---------------- LayerNorm: one warp per row, shuffle-only ------------------------
__global__ void __launch_bounds__(256) ln_kernel(const float* __restrict__ y,
                                                 const float* __restrict__ g,
                                                 const float* __restrict__ bb,
                                                 float* __restrict__ out)
{
    const int lane = threadIdx.x & 31;
    const int wrow = threadIdx.x >> 5;              // 8 warps = 8 rows
    const size_t row = (size_t)blockIdx.x * 8 + wrow;

    const float* yp = y + row * H_;
    float4 v[8];
    float s = 0.f;
#pragma unroll
    for (int p = 0; p < 8; p++) {
        v[p] = ((const float4*)yp)[lane + p * 32];
        s += v[p].x + v[p].y + v[p].z + v[p].w;
    }
#pragma unroll
    for (int o = 16; o > 0; o >>= 1) s += __shfl_xor_sync(~0u, s, o);
    const float mu = s * (1.f / H_);

    float q = 0.f;
#pragma unroll
    for (int p = 0; p < 8; p++) {
        v[p].x -= mu; v[p].y -= mu; v[p].z -= mu; v[p].w -= mu;
        q += v[p].x * v[p].x + v[p].y * v[p].y + v[p].z * v[p].z + v[p].w * v[p].w;
    }
#pragma unroll
    for (int o = 16; o > 0; o >>= 1) q += __shfl_xor_sync(~0u, q, o);
    const float rstd = rsqrtf(q * (1.f / H_) + 1e-12f);

    float* op = out + row * H_;
#pragma unroll
    for (int p = 0; p < 8; p++) {
        float4 gg = ((const float4*)g)[lane + p * 32];
        float4 bt = ((const float4*)bb)[lane + p * 32];
        float4 o;
        o.x = v[p].x * rstd * gg.x + bt.x;
        o.y = v[p].y * rstd * gg.y + bt.y;
        o.z = v[p].z * rstd * gg.z + bt.z;
        o.w = v[p].w * rstd * gg.w + bt.w;
        ((float4*)op)[lane + p * 32] = o;
    }
}

// ---------------- launch -----------------------------------------------------------
extern "C" void kernel_launch(void* const* d_in, const int* in_sizes, int n_in,
                              void* d_out, int out_size)
{
    (void)in_sizes; (void)n_in; (void)out_size;
    const float* x    = (const float*)d_in[0];
    const float* mask = (const float*)d_in[1];
    const float* Wq   = (const float*)d_in[2];
    const float* bq   = (const float*)d_in[3];
    const float* Wk   = (const float*)d_in[4];
    const float* bk   = (const float*)d_in[5];
    const float* Wv   = (const float*)d_in[6];
    const float* bv   = (const float*)d_in[7];
    const float* de   = (const float*)d_in[8];
    const float* Wo   = (const float*)d_in[9];
    const float* bo   = (const float*)d_in[10];
    const float* lng  = (const float*)d_in[11];
    const float* lnb  = (const float*)d_in[12];
    float* out = (float*)d_out;

    float* y;
    cudaGetSymbolAddress((void**)&y, g_y);

    __half *xh, *wq, *wk, *wv, *wo, *qh, *kh, *vh, *deh, *ch;
    cudaGetSymbolAddress((void**)&xh, g_xh);
    cudaGetSymbolAddress((void**)&wq, g_wq);
    cudaGetSymbolAddress((void**)&wk, g_wk);
    cudaGetSymbolAddress((void**)&wv, g_wv);
    cudaGetSymbolAddress((void**)&wo, g_wo);
    cudaGetSymbolAddress((void**)&qh, g_qh);
    cudaGetSymbolAddress((void**)&kh, g_kh);
    cudaGetSymbolAddress((void**)&vh, g_vh);
    cudaGetSymbolAddress((void**)&deh, g_de);
    cudaGetSymbolAddress((void**)&ch, g_ch);

    cudaFuncSetAttribute(gemm_mma2<1>, cudaFuncAttributeMaxDynamicSharedMemorySize, GSM_TOTAL);
    cudaFuncSetAttribute(gemm_mma2<2>, cudaFuncAttributeMaxDynamicSharedMemorySize, GSM_TOTAL);
    cudaFuncSetAttribute(fused_attn, cudaFuncAttributeMaxDynamicSharedMemorySize, FSM_TOTAL);

    const int NX4 = BS_ * H_ / 4;
    const int NW4 = H_ * H_ / 4;
    conv_kernel<<<NX4 / 256, 256>>>(x, xh, NX4);
    conv4_kernel<<<dim3(NW4 / 256, 4), 256>>>(Wq, Wk, Wv, Wo, wq, wk, wv, wo);
    const int ND4 = 2047 * 64 / 4;
    conv_kernel<<<(ND4 + 255) / 256, 256>>>(de, deh, ND4);

    gemm_mma2<2><<<dim3(H_ / 128, BS_ / 128, 3), 128, GSM_TOTAL>>>(
        xh, wq, wk, wv, bq, bk, bv, qh, kh, vh, nullptr);

    fused_attn<<<dim3(S_ / 64, BH_), 128, FSM_TOTAL>>>(
        qh, kh, vh, deh, mask, ch);

    gemm_mma2<1><<<dim3(H_ / 128, BS_ / 128, 1), 128, GSM_TOTAL>>>(
        ch, wo, wo, wo, bo, bo, bo, y, y, y, x);

    ln_kernel<<<BS_ / 8, 256>>>(y, lng, lnb, out);
}

// round 17
// speedup vs baseline: 3.0901x; 1.0522x over previous
#include <cuda_runtime.h>
#include <cuda_fp16.h>
#include <cstdint>

#define S_   1024
#define H_   1024
#define B_   4
#define NH_  16
#define D_   64
#define BS_  4096
#define BH_  64

// ---------------- scratch (no allocs allowed) ----------------
__device__ float g_y[BS_ * H_];

__device__ __half g_xh[BS_ * H_];
__device__ __half g_wq[H_ * H_], g_wk[H_ * H_], g_wv[H_ * H_], g_wo[H_ * H_];
__device__ __half g_qh[BS_ * H_], g_kh[BS_ * H_], g_vh[BS_ * H_];
__device__ __half g_de[2047 * 64];
__device__ __half g_ch[BS_ * H_];

// ---------------- helpers -------------------------------------------------------
__device__ __forceinline__ uint32_t smem_u32(const void* p)
{
    return (uint32_t)__cvta_generic_to_shared(p);
}
__device__ __forceinline__ void ldm4(uint32_t* r, uint32_t addr)
{
    asm volatile("ldmatrix.sync.aligned.m8n8.x4.shared.b16 {%0,%1,%2,%3}, [%4];"
                 : "=r"(r[0]), "=r"(r[1]), "=r"(r[2]), "=r"(r[3]) : "r"(addr));
}
__device__ __forceinline__ void ldm4t(uint32_t* r, uint32_t addr)
{
    asm volatile("ldmatrix.sync.aligned.m8n8.x4.trans.shared.b16 {%0,%1,%2,%3}, [%4];"
                 : "=r"(r[0]), "=r"(r[1]), "=r"(r[2]), "=r"(r[3]) : "r"(addr));
}
__device__ __forceinline__ void mma_f16(float* c, const uint32_t* a, const uint32_t* b)
{
    asm volatile("mma.sync.aligned.m16n8k16.row.col.f32.f16.f16.f32 "
                 "{%0,%1,%2,%3}, {%4,%5,%6,%7}, {%8,%9}, {%0,%1,%2,%3};"
                 : "+f"(c[0]), "+f"(c[1]), "+f"(c[2]), "+f"(c[3])
                 : "r"(a[0]), "r"(a[1]), "r"(a[2]), "r"(a[3]), "r"(b[0]), "r"(b[1]));
}
__device__ __forceinline__ void cpa16(uint32_t dst, const void* src)
{
    asm volatile("cp.async.cg.shared.global [%0], [%1], 16;" :: "r"(dst), "l"(src));
}
#define CP_COMMIT() asm volatile("cp.async.commit_group;" ::: "memory")
#define CP_WAIT1()  asm volatile("cp.async.wait_group 1;" ::: "memory")
#define CP_WAIT0()  asm volatile("cp.async.wait_group 0;" ::: "memory")

__device__ __forceinline__ uint32_t pack_h2(float a, float b)
{
    __half2 h = __floats2half2_rn(a, b);
    return *(uint32_t*)&h;
}

// ---------------- fp32 -> fp16 converts ---------------------------------------------
__global__ void __launch_bounds__(256) conv_kernel(const float* __restrict__ in,
                                                   __half* __restrict__ o, int n4)
{
    int i = blockIdx.x * 256 + threadIdx.x;
    if (i >= n4) return;
    float4 a = ((const float4*)in)[i];
    ((__half2*)o)[i * 2 + 0] = __floats2half2_rn(a.x, a.y);
    ((__half2*)o)[i * 2 + 1] = __floats2half2_rn(a.z, a.w);
}

__global__ void __launch_bounds__(256) conv4_kernel(
    const float* __restrict__ w0, const float* __restrict__ w1,
    const float* __restrict__ w2, const float* __restrict__ w3,
    __half* __restrict__ o0, __half* __restrict__ o1,
    __half* __restrict__ o2, __half* __restrict__ o3)
{
    const int z = blockIdx.y;
    const float* in = (z == 0) ? w0 : (z == 1) ? w1 : (z == 2) ? w2 : w3;
    __half* o = (z == 0) ? o0 : (z == 1) ? o1 : (z == 2) ? o2 : o3;
    int i = blockIdx.x * 256 + threadIdx.x;
    float4 a = ((const float4*)in)[i];
    ((__half2*)o)[i * 2 + 0] = __floats2half2_rn(a.x, a.y);
    ((__half2*)o)[i * 2 + 1] = __floats2half2_rn(a.z, a.w);
}

// ---------------- fp16 GEMM NT, 128 threads, warp tile 64x64, KT=32, 3 stages ------
#define KTG   32
#define LDSG  40
#define MAT_B (128 * LDSG * 2)
#define STG_B (2 * MAT_B)
#define NSTG  3
#define GSM_TOTAL (NSTG * STG_B)    // 61440 B -> 2 CTAs/SM

template <int EPI>
__global__ void __launch_bounds__(128, 2) gemm_mma2(
    const __half* __restrict__ Ah,
    const __half* __restrict__ B0, const __half* __restrict__ B1,
    const __half* __restrict__ B2,
    const float* __restrict__ bias0, const float* __restrict__ bias1,
    const float* __restrict__ bias2,
    void* O0, void* O1, void* O2,
    const float* __restrict__ resid)
{
    extern __shared__ char smem[];
    const uint32_t sb = smem_u32(smem);

    const int z = blockIdx.z;
    const __half* Bm = (z == 0) ? B0 : (z == 1) ? B1 : B2;
    const float* bias = (z == 0) ? bias0 : (z == 1) ? bias1 : bias2;
    void* Ov = (z == 0) ? O0 : (z == 1) ? O1 : O2;

    const int tid = threadIdx.x;
    const int lane = tid & 31, wid = tid >> 5;
    const int wm = wid >> 1, wn = wid & 1;
    const int bM = blockIdx.y * 128, bN = blockIdx.x * 128;

    float acc[4][8][4] = {};
    const int NK = H_ / KTG;

    const int q8 = lane >> 3, r8 = lane & 7;
    const int arowL = wm * 64 + (q8 & 1) * 8 + r8;
    const int browL = wn * 64 + (q8 >> 1) * 8 + r8;
    const int acolL = (q8 >> 1) * 8;
    const int bcolL = (q8 & 1) * 8;

    auto issue = [&](int kt) {
        const int st = kt % NSTG;
        const uint32_t base = sb + st * STG_B;
        const int k0 = kt * KTG;
#pragma unroll
        for (int j = 0; j < 4; j++) {
            int v = tid + 128 * j;
            int row = v >> 2, c = v & 3;
            uint32_t d = base + (uint32_t)(row * (LDSG * 2) + c * 16);
            cpa16(d,         Ah + (size_t)(bM + row) * H_ + k0 + c * 8);
            cpa16(d + MAT_B, Bm + (size_t)(bN + row) * H_ + k0 + c * 8);
        }
    };

    issue(0); CP_COMMIT();
    issue(1); CP_COMMIT();

    for (int kt = 0; kt < NK; kt++) {
        if (kt + 1 < NK) { CP_WAIT1(); } else { CP_WAIT0(); }
        __syncthreads();
        if (kt + 2 < NK) { issue(kt + 2); CP_COMMIT(); }

        const int st = kt % NSTG;
        const uint32_t bA = sb + st * STG_B;
        const uint32_t bB = bA + MAT_B;

#pragma unroll
        for (int ks = 0; ks < KTG; ks += 16) {
            uint32_t af[4][4];
#pragma unroll
            for (int mt = 0; mt < 4; mt++) {
                const uint32_t ro = (uint32_t)(((arowL + mt * 16) * LDSG + acolL + ks) * 2);
                ldm4(af[mt], bA + ro);
            }
            uint32_t bf[4][4];
#pragma unroll
            for (int p = 0; p < 4; p++) {
                const uint32_t ro = (uint32_t)(((browL + p * 16) * LDSG + bcolL + ks) * 2);
                ldm4(bf[p], bB + ro);
            }
#pragma unroll
            for (int mt = 0; mt < 4; mt++)
#pragma unroll
                for (int nt = 0; nt < 8; nt++)
                    mma_f16(acc[mt][nt], af[mt], &bf[nt >> 1][(nt & 1) * 2]);
        }
    }

    const int crow0 = bM + wm * 64 + (lane >> 2);
    const int ccol0 = bN + wn * 64 + (lane & 3) * 2;
#pragma unroll
    for (int mt = 0; mt < 4; mt++) {
        const int r0 = crow0 + mt * 16;
#pragma unroll
        for (int nt = 0; nt < 8; nt++) {
            const int c0 = ccol0 + nt * 8;
            float f0 = acc[mt][nt][0] + bias[c0];
            float f1 = acc[mt][nt][1] + bias[c0 + 1];
            float f2 = acc[mt][nt][2] + bias[c0];
            float f3 = acc[mt][nt][3] + bias[c0 + 1];
            if (EPI == 1) {
                f0 += resid[(size_t)r0 * H_ + c0];
                f1 += resid[(size_t)r0 * H_ + c0 + 1];
                f2 += resid[(size_t)(r0 + 8) * H_ + c0];
                f3 += resid[(size_t)(r0 + 8) * H_ + c0 + 1];
                float* O = (float*)Ov;
                O[(size_t)r0 * H_ + c0]           = f0;
                O[(size_t)r0 * H_ + c0 + 1]       = f1;
                O[(size_t)(r0 + 8) * H_ + c0]     = f2;
                O[(size_t)(r0 + 8) * H_ + c0 + 1] = f3;
            } else {
                __half* O = (__half*)Ov;
                *(__half2*)(O + (size_t)r0 * H_ + c0)       = __floats2half2_rn(f0, f1);
                *(__half2*)(O + (size_t)(r0 + 8) * H_ + c0) = __floats2half2_rn(f2, f3);
            }
        }
    }
}

// ---------------- fused flash attention: banded S3 (5 tiles/warp) ------------------
#define FQ    0
#define FK    9216
#define FV    18432                // 2 x 9216 double buffer
#define FP    36864
#define FS2R  55296                // fp16 [64][200] = 25600
#define FS3B  80896                // fp16 [64][136] = 17408
#define FMASK 98304
#define FSM_TOTAL 102400

__global__ void __launch_bounds__(128, 2) fused_attn(
    const __half* __restrict__ qh, const __half* __restrict__ kh,
    const __half* __restrict__ vh, const __half* __restrict__ deh,
    const float* __restrict__ mask,
    __half* __restrict__ ch)
{
    extern __shared__ char smem[];
    const uint32_t sb = smem_u32(smem);
    const int tid = threadIdx.x, lane = tid & 31, wid = tid >> 5;
    const int l0 = blockIdx.x * 64;
    const int bh = blockIdx.y;
    const int b = bh >> 4, h = bh & 15;
    const int hcol = h * D_;

    const int q8 = lane >> 3, r8 = lane & 7;
    const int aRow = (q8 & 1) * 8 + r8, aCol = (q8 >> 1) * 8;
    const int bRow = (q8 >> 1) * 8 + r8, bCol = (q8 & 1) * 8;

    __half* S2r = (__half*)(smem + FS2R);
    __half* S3b = (__half*)(smem + FS3B);
    const float* maskS = (const float*)(smem + FMASK);

    auto cp_t64 = [&](uint32_t dstbase, const __half* src, int growbase) {
#pragma unroll
        for (int j = 0; j < 4; j++) {
            int v = tid + 128 * j;
            int row = v >> 3, c = v & 7;
            cpa16(dstbase + (uint32_t)(row * 72 + c * 8) * 2,
                  src + (size_t)(growbase + row) * H_ + hcol + c * 8);
        }
    };
    auto cp_P = [&](int it) {
        const int prow0 = l0 - it * 64 + 960;
#pragma unroll
        for (int j = 0; j < 8; j++) {
            int v = tid + 128 * j;
            int row = v >> 3, c = v & 7;
            uint32_t off = (uint32_t)(row * 72 + c * 8) * 2;
            if (row < 127) {
                cpa16(sb + FP + off, deh + (size_t)(prow0 + row) * 64 + c * 8);
            } else {
                uint4 zz = {0, 0, 0, 0};
                *(uint4*)(smem + FP + off) = zz;
            }
        }
    };

    auto s2_strip = [&](int rbase, int csb) {
        float a2[8][4] = {};
#pragma unroll
        for (int ks = 0; ks < 4; ks++) {
            uint32_t aq[4];
            ldm4(aq, sb + FQ + (uint32_t)(((wid * 16 + aRow) * 72) + ks * 16 + aCol) * 2);
            uint32_t pb[4][4];
#pragma unroll
            for (int j = 0; j < 4; j++) {
                uint32_t ro = (uint32_t)(((rbase + j * 16 + bRow) * 72) + ks * 16 + bCol) * 2;
                ldm4(pb[j], sb + FP + ro);
            }
#pragma unroll
            for (int nf = 0; nf < 8; nf++)
                mma_f16(a2[nf], aq, &pb[nf >> 1][(nf & 1) * 2]);
        }
        const int rr = wid * 16 + (lane >> 2);
#pragma unroll
        for (int nf = 0; nf < 8; nf++) {
            const int cc = csb + nf * 8 + (lane & 3) * 2;
            *(__half2*)&S2r[rr * 200 + cc] = __floats2half2_rn(a2[nf][0], a2[nf][1]);
            *(__half2*)&S2r[(rr + 8) * 200 + cc] = __floats2half2_rn(a2[nf][2], a2[nf][3]);
        }
    };

    cp_t64(sb + FQ, qh, b * S_ + l0);
    cp_t64(sb + FK, kh, b * S_ + 0);
    cp_P(0);
#pragma unroll
    for (int j = 0; j < 2; j++) {
        int v = tid + 128 * j;
        cpa16(sb + FMASK + v * 16, mask + (size_t)b * S_ + v * 4);
    }
    CP_COMMIT();
    cp_t64(sb + FV, vh, b * S_ + 0);
    CP_COMMIT();

    float O[8][4] = {};
    float mrunA = -1e30f, mrunB = -1e30f;
    float srunA = 0.f, srunB = 0.f;
    const int la = lane >> 2;
    const int lrow = wid * 16 + la;
    const int tb0 = 48 - 16 * wid;   // banded S3 t-base for this warp's rows

    for (int it = 0; it < 16; it++) {
        CP_WAIT1();
        __syncthreads();

        const int prow0 = l0 - it * 64 + 960;
        const int csb = prow0 % 192;

        // ---- S1 = Q(own 16 rows) @ K^T ----
        float accS[8][4] = {};
#pragma unroll
        for (int ks = 0; ks < 4; ks++) {
            uint32_t aq[4];
            ldm4(aq, sb + FQ + (uint32_t)(((wid * 16 + aRow) * 72) + ks * 16 + aCol) * 2);
            uint32_t kb[4][4];
#pragma unroll
            for (int j = 0; j < 4; j++) {
                uint32_t ro = (uint32_t)(((j * 16 + bRow) * 72) + ks * 16 + bCol) * 2;
                ldm4(kb[j], sb + FK + ro);
            }
#pragma unroll
            for (int nf = 0; nf < 8; nf++)
                mma_f16(accS[nf], aq, &kb[nf >> 1][(nf & 1) * 2]);
        }

        // ---- S2 strips (incremental ring) ----
        if (it == 0) s2_strip(64, (csb + 64) % 192);
        s2_strip(0, csb);

        // ---- S3 = K(own 16 r-rows) @ P^T, banded: 5 t-tiles at tb0 ----
        {
            float a3[10][4] = {};
#pragma unroll
            for (int ks = 0; ks < 4; ks++) {
                uint32_t ak[4];
                ldm4(ak, sb + FK + (uint32_t)(((wid * 16 + aRow) * 72) + ks * 16 + aCol) * 2);
                uint32_t pb[5][4];
#pragma unroll
                for (int j = 0; j < 5; j++) {
                    uint32_t ro = (uint32_t)(((tb0 + j * 16 + bRow) * 72) + ks * 16 + bCol) * 2;
                    ldm4(pb[j], sb + FP + ro);
                }
#pragma unroll
                for (int j = 0; j < 5; j++)
#pragma unroll
                    for (int nf = 0; nf < 2; nf++)
                        mma_f16(a3[j * 2 + nf], ak, &pb[j][nf * 2]);
            }
            const int rr = wid * 16 + la;
#pragma unroll
            for (int j = 0; j < 5; j++)
#pragma unroll
                for (int nf = 0; nf < 2; nf++) {
                    const int cc = tb0 + j * 16 + nf * 8 + (lane & 3) * 2;
                    *(__half2*)&S3b[rr * 136 + cc] =
                        __floats2half2_rn(a3[j * 2 + nf][0], a3[j * 2 + nf][1]);
                    *(__half2*)&S3b[(rr + 8) * 136 + cc] =
                        __floats2half2_rn(a3[j * 2 + nf][2], a3[j * 2 + nf][3]);
                }
        }
        __syncthreads();

        if (it < 15) {
            cp_t64(sb + FK, kh, b * S_ + (it + 1) * 64);
            cp_P(it + 1);
            CP_COMMIT();
        }

        // ---- gather + mask + scale ----
#pragma unroll
        for (int nf = 0; nf < 8; nf++) {
            const int c0 = nf * 8 + (lane & 3) * 2;
            const int t0 = lrow - c0 + 63;
            int ca = csb + t0;        if (ca >= 192) ca -= 192;
            int cb = csb + t0 - 1;    if (cb < 0) cb += 192; else if (cb >= 192) cb -= 192;
            int cc = csb + t0 + 8;    if (cc >= 192) cc -= 192;
            int cd = csb + t0 + 7;    if (cd >= 192) cd -= 192;
            const float mk0 = maskS[it * 64 + c0];
            const float mk1 = maskS[it * 64 + c0 + 1];
            float s2a = __half2float(S2r[lrow * 200 + ca]);
            float s2b_ = __half2float(S2r[lrow * 200 + cb]);
            float s2c = __half2float(S2r[(lrow + 8) * 200 + cc]);
            float s2d = __half2float(S2r[(lrow + 8) * 200 + cd]);
            float s3a = __half2float(S3b[c0 * 136 + t0]);
            float s3b_ = __half2float(S3b[(c0 + 1) * 136 + t0 - 1]);
            float s3c = __half2float(S3b[c0 * 136 + t0 + 8]);
            float s3d = __half2float(S3b[(c0 + 1) * 136 + t0 + 7]);
            accS[nf][0] = (accS[nf][0] + s2a + s3a) * 0.125f + mk0;
            accS[nf][1] = (accS[nf][1] + s2b_ + s3b_) * 0.125f + mk1;
            accS[nf][2] = (accS[nf][2] + s2c + s3c) * 0.125f + mk0;
            accS[nf][3] = (accS[nf][3] + s2d + s3d) * 0.125f + mk1;
        }

        // ---- warp-private online softmax ----
        float mA = -1e30f, mB = -1e30f;
#pragma unroll
        for (int nf = 0; nf < 8; nf++) {
            mA = fmaxf(mA, fmaxf(accS[nf][0], accS[nf][1]));
            mB = fmaxf(mB, fmaxf(accS[nf][2], accS[nf][3]));
        }
        mA = fmaxf(mA, __shfl_xor_sync(~0u, mA, 1));
        mA = fmaxf(mA, __shfl_xor_sync(~0u, mA, 2));
        mB = fmaxf(mB, __shfl_xor_sync(~0u, mB, 1));
        mB = fmaxf(mB, __shfl_xor_sync(~0u, mB, 2));

        const float mnA = fmaxf(mrunA, mA), mnB = fmaxf(mrunB, mB);
        const float sclA = __expf(mrunA - mnA), sclB = __expf(mrunB - mnB);
        mrunA = mnA; mrunB = mnB;
#pragma unroll
        for (int nf = 0; nf < 8; nf++) {
            O[nf][0] *= sclA; O[nf][1] *= sclA;
            O[nf][2] *= sclB; O[nf][3] *= sclB;
        }

        float suA = 0.f, suB = 0.f;
#pragma unroll
        for (int nf = 0; nf < 8; nf++) {
            accS[nf][0] = __expf(accS[nf][0] - mnA);
            accS[nf][1] = __expf(accS[nf][1] - mnA);
            accS[nf][2] = __expf(accS[nf][2] - mnB);
            accS[nf][3] = __expf(accS[nf][3] - mnB);
            suA += accS[nf][0] + accS[nf][1];
            suB += accS[nf][2] + accS[nf][3];
        }
        suA += __shfl_xor_sync(~0u, suA, 1);
        suA += __shfl_xor_sync(~0u, suA, 2);
        suB += __shfl_xor_sync(~0u, suB, 1);
        suB += __shfl_xor_sync(~0u, suB, 2);
        srunA = srunA * sclA + suA;
        srunB = srunB * sclB + suB;

        uint32_t pa[4][4];
#pragma unroll
        for (int kg = 0; kg < 4; kg++) {
            pa[kg][0] = pack_h2(accS[2 * kg][0],     accS[2 * kg][1]);
            pa[kg][1] = pack_h2(accS[2 * kg][2],     accS[2 * kg][3]);
            pa[kg][2] = pack_h2(accS[2 * kg + 1][0], accS[2 * kg + 1][1]);
            pa[kg][3] = pack_h2(accS[2 * kg + 1][2], accS[2 * kg + 1][3]);
        }

        if (it < 15) { CP_WAIT1(); } else { CP_WAIT0(); }
        __syncthreads();

        const uint32_t Vb = sb + FV + (uint32_t)(it & 1) * 9216;
#pragma unroll
        for (int kg = 0; kg < 4; kg++) {
            uint32_t vb[4][4];
#pragma unroll
            for (int j = 0; j < 4; j++) {
                uint32_t ro = (uint32_t)(((kg * 16 + aRow) * 72) + j * 16 + aCol) * 2;
                ldm4t(vb[j], Vb + ro);
            }
#pragma unroll
            for (int nf = 0; nf < 8; nf++)
                mma_f16(O[nf], pa[kg], &vb[nf >> 1][(nf & 1) * 2]);
        }

        if (it < 15) {
            cp_t64(sb + FV + (uint32_t)((it + 1) & 1) * 9216, vh, b * S_ + (it + 1) * 64);
            CP_COMMIT();
        }
    }

    const float iA = 1.f / srunA, iB = 1.f / srunB;
#pragma unroll
    for (int nf = 0; nf < 8; nf++) {
        const int col = hcol + nf * 8 + (lane & 3) * 2;
        const size_t rowA = (size_t)(b * S_ + l0 + lrow) * H_ + col;
        const size_t rowB = (size_t)(b * S_ + l0 + lrow + 8) * H_ + col;
        *(__half2*)(ch + rowA) = __floats2half2_rn(O[nf][0] * iA, O[nf][1] * iA);
        *(__half2*)(ch + rowB) = __floats2half2_rn(O[nf][2] * iB, O[nf][3] * iB);
    }
}

// ---------------- LayerNorm: one warp per row, shuffle-only ------------------------
__global__ void __launch_bounds__(256) ln_kernel(const float* __restrict__ y,
                                                 const float* __restrict__ g,
                                                 const float* __restrict__ bb,
                                                 float* __restrict__ out)
{
    const int lane = threadIdx.x & 31;
    const int wrow = threadIdx.x >> 5;
    const size_t row = (size_t)blockIdx.x * 8 + wrow;

    const float* yp = y + row * H_;
    float4 v[8];
    float s = 0.f;
#pragma unroll
    for (int p = 0; p < 8; p++) {
        v[p] = ((const float4*)yp)[lane + p * 32];
        s += v[p].x + v[p].y + v[p].z + v[p].w;
    }
#pragma unroll
    for (int o = 16; o > 0; o >>= 1) s += __shfl_xor_sync(~0u, s, o);
    const float mu = s * (1.f / H_);

    float q = 0.f;
#pragma unroll
    for (int p = 0; p < 8; p++) {
        v[p].x -= mu; v[p].y -= mu; v[p].z -= mu; v[p].w -= mu;
        q += v[p].x * v[p].x + v[p].y * v[p].y + v[p].z * v[p].z + v[p].w * v[p].w;
    }
#pragma unroll
    for (int o = 16; o > 0; o >>= 1) q += __shfl_xor_sync(~0u, q, o);
    const float rstd = rsqrtf(q * (1.f / H_) + 1e-12f);

    float* op = out + row * H_;
#pragma unroll
    for (int p = 0; p < 8; p++) {
        float4 gg = ((const float4*)g)[lane + p * 32];
        float4 bt = ((const float4*)bb)[lane + p * 32];
        float4 o;
        o.x = v[p].x * rstd * gg.x + bt.x;
        o.y = v[p].y * rstd * gg.y + bt.y;
        o.z = v[p].z * rstd * gg.z + bt.z;
        o.w = v[p].w * rstd * gg.w + bt.w;
        ((float4*)op)[lane + p * 32] = o;
    }
}

// ---------------- launch -----------------------------------------------------------
extern "C" void kernel_launch(void* const* d_in, const int* in_sizes, int n_in,
                              void* d_out, int out_size)
{
    (void)in_sizes; (void)n_in; (void)out_size;
    const float* x    = (const float*)d_in[0];
    const float* mask = (const float*)d_in[1];
    const float* Wq   = (const float*)d_in[2];
    const float* bq   = (const float*)d_in[3];
    const float* Wk   = (const float*)d_in[4];
    const float* bk   = (const float*)d_in[5];
    const float* Wv   = (const float*)d_in[6];
    const float* bv   = (const float*)d_in[7];
    const float* de   = (const float*)d_in[8];
    const float* Wo   = (const float*)d_in[9];
    const float* bo   = (const float*)d_in[10];
    const float* lng  = (const float*)d_in[11];
    const float* lnb  = (const float*)d_in[12];
    float* out = (float*)d_out;

    float* y;
    cudaGetSymbolAddress((void**)&y, g_y);

    __half *xh, *wq, *wk, *wv, *wo, *qh, *kh, *vh, *deh, *ch;
    cudaGetSymbolAddress((void**)&xh, g_xh);
    cudaGetSymbolAddress((void**)&wq, g_wq);
    cudaGetSymbolAddress((void**)&wk, g_wk);
    cudaGetSymbolAddress((void**)&wv, g_wv);
    cudaGetSymbolAddress((void**)&wo, g_wo);
    cudaGetSymbolAddress((void**)&qh, g_qh);
    cudaGetSymbolAddress((void**)&kh, g_kh);
    cudaGetSymbolAddress((void**)&vh, g_vh);
    cudaGetSymbolAddress((void**)&deh, g_de);
    cudaGetSymbolAddress((void**)&ch, g_ch);

    cudaFuncSetAttribute(gemm_mma2<1>, cudaFuncAttributeMaxDynamicSharedMemorySize, GSM_TOTAL);
    cudaFuncSetAttribute(gemm_mma2<2>, cudaFuncAttributeMaxDynamicSharedMemorySize, GSM_TOTAL);
    cudaFuncSetAttribute(fused_attn, cudaFuncAttributeMaxDynamicSharedMemorySize, FSM_TOTAL);

    const int NX4 = BS_ * H_ / 4;
    const int NW4 = H_ * H_ / 4;
    conv_kernel<<<NX4 / 256, 256>>>(x, xh, NX4);
    conv4_kernel<<<dim3(NW4 / 256, 4), 256>>>(Wq, Wk, Wv, Wo, wq, wk, wv, wo);
    const int ND4 = 2047 * 64 / 4;
    conv_kernel<<<(ND4 + 255) / 256, 256>>>(de, deh, ND4);

    gemm_mma2<2><<<dim3(H_ / 128, BS_ / 128, 3), 128, GSM_TOTAL>>>(
        xh, wq, wk, wv, bq, bk, bv, qh, kh, vh, nullptr);

    fused_attn<<<dim3(S_ / 64, BH_), 128, FSM_TOTAL>>>(
        qh, kh, vh, deh, mask, ch);

    gemm_mma2<1><<<dim3(H_ / 128, BS_ / 128, 1), 128, GSM_TOTAL>>>(
        ch, wo, wo, wo, bo, bo, bo, y, y, y, x);

    ln_kernel<<<BS_ / 8, 256>>>(y, lng, lnb, out);
}